// round 13
// baseline (speedup 1.0000x reference)
#include <cuda_runtime.h>
#include <cuda_bf16.h>
#include <math.h>
#include <stdint.h>

// ---------------- problem constants ----------------
#define BB 4
#define SS 2048
#define DIMC 128
#define HH 8
#define DHD 128
#define DEPTH 2
#define NCLS 10
#define MF 128
#define CHUNK 128
#define NC 16
#define INNER 1024
#define FFD 512
#define BSR 8192
#define BHS 65536
#define NBH 32

#define NORMC 0.29730177875068026f
#define RATIOC 0.08838834764831845f

// ---------------- device scratch (fp32) ----------------
__device__ float g_h  [BSR*DIMC];
__device__ float g_kp [(size_t)NBH*SS*MF];
__device__ float g_diagk[BHS];
__device__ float g_bmax[NBH*16];
__device__ float g_o  [BSR*INNER];
__device__ float g_den[BHS];
__device__ float g_kvc[(size_t)NBH*NC*MF*DHD];
__device__ float g_ksc[NBH*NC*MF];
__device__ float g_ksp[NBH*NC*MF];
__device__ float g_pp [BB*16*DIMC];

// ---------------- device scratch (bf16 hi/lo) ----------------
__device__ __align__(256) __nv_bfloat16 g_yh [BSR*DIMC];
__device__ __align__(256) __nv_bfloat16 g_yl [BSR*DIMC];
__device__ __align__(256) __nv_bfloat16 g_wth[2*672000];
__device__ __align__(256) __nv_bfloat16 g_wtl[2*672000];
__device__ __align__(256) __nv_bfloat16 g_qnh[(size_t)BHS*DHD];
__device__ __align__(256) __nv_bfloat16 g_qnl[(size_t)BHS*DHD];
__device__ __align__(256) __nv_bfloat16 g_knh[(size_t)BHS*DHD];
__device__ __align__(256) __nv_bfloat16 g_knl[(size_t)BHS*DHD];
__device__ __align__(256) __nv_bfloat16 g_vh [(size_t)BSR*INNER];
__device__ __align__(256) __nv_bfloat16 g_vl [(size_t)BSR*INNER];
__device__ __align__(256) __nv_bfloat16 g_qph[(size_t)NBH*SS*MF];
__device__ __align__(256) __nv_bfloat16 g_qpl[(size_t)NBH*SS*MF];
__device__ __align__(256) __nv_bfloat16 g_kvph[(size_t)NBH*NC*MF*DHD];
__device__ __align__(256) __nv_bfloat16 g_kvpl[(size_t)NBH*NC*MF*DHD];
__device__ __align__(256) __nv_bfloat16 g_oh [(size_t)BSR*INNER];
__device__ __align__(256) __nv_bfloat16 g_ol [(size_t)BSR*INNER];
__device__ __align__(256) __nv_bfloat16 g_fh [(size_t)BSR*FFD];
__device__ __align__(256) __nv_bfloat16 g_fl [(size_t)BSR*FFD];

#define WT_Q  0
#define WT_K  131072
#define WT_V  262144
#define WT_O  393216
#define WT_F1 524288
#define WT_F2 589824
#define WT_PJ 655360
#define WT_LAYER 672000

// ---------------- warp MMA helpers ----------------
__device__ __forceinline__ uint32_t s2u(const void* p){
    uint32_t a;
    asm("{ .reg .u64 t; cvta.to.shared.u64 t, %1; cvt.u32.u64 %0, t; }" : "=r"(a) : "l"(p));
    return a;
}
__device__ __forceinline__ void ldsm4(uint32_t* r, uint32_t addr){
    asm volatile("ldmatrix.sync.aligned.m8n8.x4.shared.b16 {%0,%1,%2,%3}, [%4];"
                 : "=r"(r[0]),"=r"(r[1]),"=r"(r[2]),"=r"(r[3]) : "r"(addr));
}
__device__ __forceinline__ void ldsm4t(uint32_t* r, uint32_t addr){
    asm volatile("ldmatrix.sync.aligned.m8n8.x4.trans.shared.b16 {%0,%1,%2,%3}, [%4];"
                 : "=r"(r[0]),"=r"(r[1]),"=r"(r[2]),"=r"(r[3]) : "r"(addr));
}
__device__ __forceinline__ void mma_bf16(float* c, const uint32_t* a, const uint32_t* b){
    asm volatile("mma.sync.aligned.m16n8k16.row.col.f32.bf16.bf16.f32 "
                 "{%0,%1,%2,%3}, {%4,%5,%6,%7}, {%8,%9}, {%0,%1,%2,%3};"
                 : "+f"(c[0]),"+f"(c[1]),"+f"(c[2]),"+f"(c[3])
                 : "r"(a[0]),"r"(a[1]),"r"(a[2]),"r"(a[3]), "r"(b[0]),"r"(b[1]));
}
__device__ __forceinline__ void split_bf16(float v, __nv_bfloat16& h, __nv_bfloat16& l){
    h = __float2bfloat16(v);
    l = __float2bfloat16(v - __bfloat162float(h));
}
__device__ __forceinline__ float gelu(float xx){
    return 0.5f*xx*(1.0f + tanhf(0.7978845608028654f*(xx + 0.044715f*xx*xx*xx)));
}
__device__ __forceinline__ uint32_t taddr(const __nv_bfloat16* S, int P, int kbase, int nbase, int lane){
    int kk = (lane & 7) + ((lane >> 4) << 3);
    int nn = ((lane >> 3) & 1) << 3;
    return s2u(S + (size_t)(kbase + kk)*P + nbase + nn);
}
#define MMA3x2(accA, accB, ah_, al_, b0h_, b0l_, b1h_, b1l_) \
    do { mma_bf16(accA, ah_, b0h_); mma_bf16(accA, ah_, b0l_); mma_bf16(accA, al_, b0h_); \
         mma_bf16(accB, ah_, b1h_); mma_bf16(accB, ah_, b1l_); mma_bf16(accB, al_, b1h_); } while(0)

#define KP 136

// ======== merged feature GEMM, K staged in two 64-chunks (73.7 KB -> 2 CTAs/SM)
// blockIdx.x==0 -> K features (dd+bmax+diag); ==1 -> Q features (exp -> qp hi/lo)
#define FP 72
__global__ __launch_bounds__(256) void k_mmaF(
    const __nv_bfloat16* __restrict__ Kh, const __nv_bfloat16* __restrict__ Kl,
    const __nv_bfloat16* __restrict__ Qh, const __nv_bfloat16* __restrict__ Ql,
    const __nv_bfloat16* __restrict__ Bh, const __nv_bfloat16* __restrict__ Bl,
    float* __restrict__ out,
    __nv_bfloat16* __restrict__ outH, __nv_bfloat16* __restrict__ outL,
    float* __restrict__ bmax)
{
    extern __shared__ __align__(16) char dsm[];
    __nv_bfloat16* sAh = (__nv_bfloat16*)dsm;          // [128][FP] (64 K-cols)
    __nv_bfloat16* sAl = sAh + 128*FP;
    __nv_bfloat16* sBh = sAl + 128*FP;
    __nv_bfloat16* sBl = sBh + 128*FP;
    __shared__ float s_rm[2][128];
    __shared__ float s_red[256];
    __shared__ float s_dg[128];

    const int MODE = (blockIdx.x == 0) ? 4 : 3;
    const __nv_bfloat16* Ah = (MODE == 4) ? Kh : Qh;
    const __nv_bfloat16* Al = (MODE == 4) ? Kl : Ql;

    const int t = threadIdx.x, w = t >> 5, lane = t & 31;
    const int wm = w & 3, wn = w >> 2;
    const int row0 = blockIdx.y*128;

    float acc[2][8][4] = {};
    float dacc = 0.f;
    const int lrow = (lane & 15), lcol8 = (lane >> 4)*8;

    #pragma unroll
    for (int kc = 0; kc < 128; kc += 64) {
        if (kc) __syncthreads();   // protect previous chunk reads
        #pragma unroll
        for (int i = 0; i < 4; i++) {
            int f = i*256 + t;
            int r = f >> 3, c8 = (f & 7) << 3;
            *(uint4*)(sAh + r*FP + c8) = *(const uint4*)(Ah + (size_t)(row0+r)*128 + kc + c8);
            *(uint4*)(sAl + r*FP + c8) = *(const uint4*)(Al + (size_t)(row0+r)*128 + kc + c8);
            *(uint4*)(sBh + r*FP + c8) = *(const uint4*)(Bh + (size_t)r*128 + kc + c8);
            *(uint4*)(sBl + r*FP + c8) = *(const uint4*)(Bl + (size_t)r*128 + kc + c8);
        }
        __syncthreads();

        if (t < 128) {
            #pragma unroll
            for (int k8 = 0; k8 < 8; k8++) {
                uint4 uh = *(uint4*)(sAh + t*FP + k8*8);
                uint4 ul = *(uint4*)(sAl + t*FP + k8*8);
                const __nv_bfloat16* ph = (const __nv_bfloat16*)&uh;
                const __nv_bfloat16* pl = (const __nv_bfloat16*)&ul;
                #pragma unroll
                for (int j = 0; j < 8; j++) {
                    float av = __bfloat162float(ph[j]) + __bfloat162float(pl[j]);
                    dacc += av*av;
                }
            }
        }

        #pragma unroll
        for (int ks = 0; ks < 4; ks++) {
            int kcol = ks*16 + lcol8;
            uint32_t ah[2][4], al[2][4];
            #pragma unroll
            for (int mt = 0; mt < 2; mt++) {
                int arow = wm*32 + mt*16 + lrow;
                ldsm4(ah[mt], s2u(sAh + arow*FP + kcol));
                ldsm4(al[mt], s2u(sAl + arow*FP + kcol));
            }
            #pragma unroll
            for (int nt2 = 0; nt2 < 4; nt2++) {
                int brow = wn*64 + nt2*16 + lrow;
                uint32_t rh[4], rl[4];
                ldsm4(rh, s2u(sBh + brow*FP + kcol));
                ldsm4(rl, s2u(sBl + brow*FP + kcol));
                uint32_t b0h[2] = {rh[0], rh[2]}, b1h[2] = {rh[1], rh[3]};
                uint32_t b0l[2] = {rl[0], rl[2]}, b1l[2] = {rl[1], rl[3]};
                #pragma unroll
                for (int mt = 0; mt < 2; mt++)
                    MMA3x2(acc[mt][nt2*2], acc[mt][nt2*2+1], ah[mt], al[mt], b0h, b0l, b1h, b1l);
            }
        }
    }
    if (t < 128) {
        if (MODE == 4) g_diagk[row0 + t] = 0.5f*dacc;
        else           s_dg[t] = 0.5f*dacc;
    }

    const int rl4 = lane >> 2, cl2 = (lane & 3)*2;

    if (MODE == 4) {
        float bm = -1e30f;
        #pragma unroll
        for (int mt = 0; mt < 2; mt++)
            #pragma unroll
            for (int h = 0; h < 2; h++) {
                int gr = row0 + wm*32 + mt*16 + rl4 + h*8;
                #pragma unroll
                for (int nt = 0; nt < 8; nt++) {
                    float2 v = {acc[mt][nt][h*2], acc[mt][nt][h*2+1]};
                    *(float2*)(out + (size_t)gr*MF + wn*64 + nt*8 + cl2) = v;
                    bm = fmaxf(bm, fmaxf(v.x, v.y));
                }
            }
        s_red[t] = bm; __syncthreads();
        #pragma unroll
        for (int o = 128; o > 0; o >>= 1) { if (t < o) s_red[t] = fmaxf(s_red[t], s_red[t+o]); __syncthreads(); }
        if (t == 0) bmax[blockIdx.y] = s_red[0];
    } else {
        float rm[2][2];
        #pragma unroll
        for (int mt = 0; mt < 2; mt++)
            #pragma unroll
            for (int h = 0; h < 2; h++) {
                float m = -1e30f;
                #pragma unroll
                for (int nt = 0; nt < 8; nt++)
                    m = fmaxf(m, fmaxf(acc[mt][nt][h*2], acc[mt][nt][h*2+1]));
                m = fmaxf(m, __shfl_xor_sync(0xffffffffu, m, 1));
                m = fmaxf(m, __shfl_xor_sync(0xffffffffu, m, 2));
                rm[mt][h] = m;
            }
        if ((lane & 3) == 0) {
            #pragma unroll
            for (int mt = 0; mt < 2; mt++)
                #pragma unroll
                for (int h = 0; h < 2; h++)
                    s_rm[wn][wm*32 + mt*16 + rl4 + h*8] = rm[mt][h];
        }
        __syncthreads();
        #pragma unroll
        for (int mt = 0; mt < 2; mt++)
            #pragma unroll
            for (int h = 0; h < 2; h++) {
                int lr = wm*32 + mt*16 + rl4 + h*8;
                int gr = row0 + lr;
                float rmax = fmaxf(s_rm[0][lr], s_rm[1][lr]);
                float dg = s_dg[lr];
                #pragma unroll
                for (int nt = 0; nt < 8; nt++) {
                    int gc = wn*64 + nt*8 + cl2;
                    float v0 = RATIOC*(expf(acc[mt][nt][h*2]  -dg-rmax) + 1e-4f);
                    float v1 = RATIOC*(expf(acc[mt][nt][h*2+1]-dg-rmax) + 1e-4f);
                    __nv_bfloat16 h0,l0,h1,l1;
                    split_bf16(v0,h0,l0); split_bf16(v1,h1,l1);
                    __nv_bfloat162 hp, lp;
                    hp.x = h0; hp.y = h1; lp.x = l0; lp.y = l1;
                    *(__nv_bfloat162*)(outH + (size_t)gr*MF + gc) = hp;
                    *(__nv_bfloat162*)(outL + (size_t)gr*MF + gc) = lp;
                }
            }
    }
}

// ======== 128x64-tile K=128 mainloop (2 CTAs/SM) — shared by QKV and FF1 ========
#define QKV_SMEM ((2*128 + 2*64)*KP*2)
#define MAINLOOP_64COL(sAh, sAl, sBh, sBl, Ah, Al, Bh, Bl, row0, col0, acc) \
    {   \
        _Pragma("unroll")                                                        \
        for (int i = 0; i < 8; i++) {                                            \
            int f = i*256 + threadIdx.x;                                         \
            int r = f >> 4, c8 = (f & 15) << 3;                                  \
            *(uint4*)(sAh + r*KP + c8) = *(const uint4*)(Ah + (size_t)(row0+r)*128 + c8); \
            *(uint4*)(sAl + r*KP + c8) = *(const uint4*)(Al + (size_t)(row0+r)*128 + c8); \
        }                                                                        \
        _Pragma("unroll")                                                        \
        for (int i = 0; i < 4; i++) {                                            \
            int f = i*256 + threadIdx.x;                                         \
            int r = f >> 4, c8 = (f & 15) << 3;                                  \
            *(uint4*)(sBh + r*KP + c8) = *(const uint4*)(Bh + (size_t)(col0+r)*128 + c8); \
            *(uint4*)(sBl + r*KP + c8) = *(const uint4*)(Bl + (size_t)(col0+r)*128 + c8); \
        }                                                                        \
        __syncthreads();                                                         \
        _Pragma("unroll")                                                        \
        for (int ks = 0; ks < 8; ks++) {                                         \
            int kcol = ks*16 + lcol8;                                            \
            uint32_t ah[2][4], al[2][4];                                         \
            _Pragma("unroll")                                                    \
            for (int mt = 0; mt < 2; mt++) {                                     \
                int arow = wm*32 + mt*16 + lrow;                                 \
                ldsm4(ah[mt], s2u(sAh + arow*KP + kcol));                        \
                ldsm4(al[mt], s2u(sAl + arow*KP + kcol));                        \
            }                                                                    \
            _Pragma("unroll")                                                    \
            for (int nt2 = 0; nt2 < 2; nt2++) {                                  \
                int brow = wn*32 + nt2*16 + lrow;                                \
                uint32_t rh[4], rl[4];                                           \
                ldsm4(rh, s2u(sBh + brow*KP + kcol));                            \
                ldsm4(rl, s2u(sBl + brow*KP + kcol));                            \
                uint32_t b0h[2] = {rh[0], rh[2]}, b1h[2] = {rh[1], rh[3]};       \
                uint32_t b0l[2] = {rl[0], rl[2]}, b1l[2] = {rl[1], rl[3]};       \
                _Pragma("unroll")                                                \
                for (int mt = 0; mt < 2; mt++)                                   \
                    MMA3x2(acc[mt][nt2*2], acc[mt][nt2*2+1], ah[mt], al[mt], b0h, b0l, b1h, b1l); \
            }                                                                    \
        }                                                                        \
    }

// QKV: grid (48, 64); epilogue scatters per part/head
__global__ __launch_bounds__(256) void k_mmaqkv64(
    const __nv_bfloat16* __restrict__ Ah, const __nv_bfloat16* __restrict__ Al,
    const __nv_bfloat16* __restrict__ Bh, const __nv_bfloat16* __restrict__ Bl)
{
    extern __shared__ __align__(16) char dsm[];
    __nv_bfloat16* sAh = (__nv_bfloat16*)dsm;
    __nv_bfloat16* sAl = sAh + 128*KP;
    __nv_bfloat16* sBh = sAl + 128*KP;
    __nv_bfloat16* sBl = sBh + 64*KP;
    const int t = threadIdx.x, w = t >> 5, lane = t & 31;
    const int wm = w & 3, wn = w >> 2;
    const int row0 = blockIdx.y*128, col0 = blockIdx.x*64;
    const int lrow = (lane & 15), lcol8 = (lane >> 4)*8;
    float acc[2][4][4] = {};

    MAINLOOP_64COL(sAh, sAl, sBh, sBl, Ah, Al, Bh, Bl, row0, col0, acc);

    const int rl4 = lane >> 2, cl2 = (lane & 3)*2;
    const int part = col0 >> 10;
    const int h = (col0 >> 7) & 7;
    const int d0 = col0 & 127;

    if (part < 2) {
        __nv_bfloat16* dH = part ? g_knh : g_qnh;
        __nv_bfloat16* dL = part ? g_knl : g_qnl;
        #pragma unroll
        for (int mt = 0; mt < 2; mt++)
            #pragma unroll
            for (int h2 = 0; h2 < 2; h2++) {
                int gr = row0 + wm*32 + mt*16 + rl4 + h2*8;
                int b = gr >> 11, s = gr & 2047;
                size_t base = ((size_t)(b*HH + h)*SS + s)*DHD + d0;
                #pragma unroll
                for (int nt = 0; nt < 4; nt++) {
                    float v0 = acc[mt][nt][h2*2]   * NORMC;
                    float v1 = acc[mt][nt][h2*2+1] * NORMC;
                    __nv_bfloat16 h0,l0,h1,l1;
                    split_bf16(v0,h0,l0); split_bf16(v1,h1,l1);
                    __nv_bfloat162 hp, lp;
                    hp.x = h0; hp.y = h1; lp.x = l0; lp.y = l1;
                    *(__nv_bfloat162*)(dH + base + wn*32 + nt*8 + cl2) = hp;
                    *(__nv_bfloat162*)(dL + base + wn*32 + nt*8 + cl2) = lp;
                }
            }
    } else {
        #pragma unroll
        for (int mt = 0; mt < 2; mt++)
            #pragma unroll
            for (int h2 = 0; h2 < 2; h2++) {
                int gr = row0 + wm*32 + mt*16 + rl4 + h2*8;
                size_t base = (size_t)gr*INNER + h*DHD + d0;
                #pragma unroll
                for (int nt = 0; nt < 4; nt++) {
                    __nv_bfloat16 h0,l0,h1,l1;
                    split_bf16(acc[mt][nt][h2*2],   h0, l0);
                    split_bf16(acc[mt][nt][h2*2+1], h1, l1);
                    __nv_bfloat162 hp, lp;
                    hp.x = h0; hp.y = h1; lp.x = l0; lp.y = l1;
                    *(__nv_bfloat162*)(g_vh + base + wn*32 + nt*8 + cl2) = hp;
                    *(__nv_bfloat162*)(g_vl + base + wn*32 + nt*8 + cl2) = lp;
                }
            }
    }
}

// FF1: grid (8, 64); gelu epilogue -> fh/fl
__global__ __launch_bounds__(256) void k_ff1(
    const __nv_bfloat16* __restrict__ Ah, const __nv_bfloat16* __restrict__ Al,
    const __nv_bfloat16* __restrict__ Bh, const __nv_bfloat16* __restrict__ Bl,
    const float* __restrict__ bias)
{
    extern __shared__ __align__(16) char dsm[];
    __nv_bfloat16* sAh = (__nv_bfloat16*)dsm;
    __nv_bfloat16* sAl = sAh + 128*KP;
    __nv_bfloat16* sBh = sAl + 128*KP;
    __nv_bfloat16* sBl = sBh + 64*KP;
    const int t = threadIdx.x, w = t >> 5, lane = t & 31;
    const int wm = w & 3, wn = w >> 2;
    const int row0 = blockIdx.y*128, col0 = blockIdx.x*64;
    const int lrow = (lane & 15), lcol8 = (lane >> 4)*8;
    float acc[2][4][4] = {};

    MAINLOOP_64COL(sAh, sAl, sBh, sBl, Ah, Al, Bh, Bl, row0, col0, acc);

    const int rl4 = lane >> 2, cl2 = (lane & 3)*2;
    #pragma unroll
    for (int mt = 0; mt < 2; mt++)
        #pragma unroll
        for (int h2 = 0; h2 < 2; h2++) {
            int gr = row0 + wm*32 + mt*16 + rl4 + h2*8;
            #pragma unroll
            for (int nt = 0; nt < 4; nt++) {
                int gc = col0 + wn*32 + nt*8 + cl2;
                float v0 = gelu(acc[mt][nt][h2*2]   + bias[gc]);
                float v1 = gelu(acc[mt][nt][h2*2+1] + bias[gc+1]);
                __nv_bfloat16 h0,l0,h1,l1;
                split_bf16(v0,h0,l0); split_bf16(v1,h1,l1);
                __nv_bfloat162 hp, lp;
                hp.x = h0; hp.y = h1; lp.x = l0; lp.y = l1;
                *(__nv_bfloat162*)(g_fh + (size_t)gr*FFD + gc) = hp;
                *(__nv_bfloat162*)(g_fl + (size_t)gr*FFD + gc) = lp;
            }
        }
}

// ============ HMMA GEMM 64x128 tile, double-buffered (WO/FF2) — round-10 proven ============
#define SROW 72
#define BUFSZ (384*SROW)
__global__ __launch_bounds__(256) void k_mma64(
    const __nv_bfloat16* __restrict__ Ah, const __nv_bfloat16* __restrict__ Al, int lda,
    const __nv_bfloat16* __restrict__ Bh, const __nv_bfloat16* __restrict__ Bl,
    int Ktot,
    const float* __restrict__ bias,
    float* __restrict__ out)
{
    extern __shared__ __align__(16) __nv_bfloat16 sb[];
    const int t = threadIdx.x, w = t >> 5, lane = t & 31;
    const int wm = w & 1, wn = w >> 1;
    const int row0 = blockIdx.y*64;
    float acc[2][4][4] = {};
    const int lrow = (lane & 15), lcol8 = (lane >> 4)*8;

    {
        #pragma unroll
        for (int i = 0; i < 2; i++) {
            int f = i*256 + t;
            int r = f >> 3, c8 = (f & 7) << 3;
            *(uint4*)(sb + r*SROW + c8)            = *(const uint4*)(Ah + (size_t)(row0+r)*lda + c8);
            *(uint4*)(sb + 64*SROW + r*SROW + c8)  = *(const uint4*)(Al + (size_t)(row0+r)*lda + c8);
        }
        #pragma unroll
        for (int i = 0; i < 4; i++) {
            int f = i*256 + t;
            int r = f >> 3, c8 = (f & 7) << 3;
            *(uint4*)(sb + 128*SROW + r*SROW + c8) = *(const uint4*)(Bh + (size_t)r*Ktot + c8);
            *(uint4*)(sb + 256*SROW + r*SROW + c8) = *(const uint4*)(Bl + (size_t)r*Ktot + c8);
        }
    }
    __syncthreads();
    int buf = 0;

    for (int kc = 64; kc <= Ktot; kc += 64) {
        uint4 ra[2][2], rb[2][4];
        if (kc < Ktot) {
            #pragma unroll
            for (int i = 0; i < 2; i++) {
                int f = i*256 + t;
                int r = f >> 3, c8 = (f & 7) << 3;
                ra[0][i] = *(const uint4*)(Ah + (size_t)(row0+r)*lda + kc + c8);
                ra[1][i] = *(const uint4*)(Al + (size_t)(row0+r)*lda + kc + c8);
            }
            #pragma unroll
            for (int i = 0; i < 4; i++) {
                int f = i*256 + t;
                int r = f >> 3, c8 = (f & 7) << 3;
                rb[0][i] = *(const uint4*)(Bh + (size_t)r*Ktot + kc + c8);
                rb[1][i] = *(const uint4*)(Bl + (size_t)r*Ktot + kc + c8);
            }
        }
        const __nv_bfloat16* cb = sb + buf*BUFSZ;
        #pragma unroll
        for (int ks = 0; ks < 4; ks++) {
            int kcol = ks*16 + lcol8;
            uint32_t ah[2][4], al[2][4];
            #pragma unroll
            for (int mt = 0; mt < 2; mt++) {
                int arow = wm*32 + mt*16 + lrow;
                ldsm4(ah[mt], s2u(cb + arow*SROW + kcol));
                ldsm4(al[mt], s2u(cb + 64*SROW + arow*SROW + kcol));
            }
            #pragma unroll
            for (int nt2 = 0; nt2 < 2; nt2++) {
                int brow = wn*32 + nt2*16 + lrow;
                uint32_t rh[4], rl[4];
                ldsm4(rh, s2u(cb + 128*SROW + brow*SROW + kcol));
                ldsm4(rl, s2u(cb + 256*SROW + brow*SROW + kcol));
                uint32_t b0h[2] = {rh[0], rh[2]}, b1h[2] = {rh[1], rh[3]};
                uint32_t b0l[2] = {rl[0], rl[2]}, b1l[2] = {rl[1], rl[3]};
                #pragma unroll
                for (int mt = 0; mt < 2; mt++)
                    MMA3x2(acc[mt][nt2*2], acc[mt][nt2*2+1], ah[mt], al[mt], b0h, b0l, b1h, b1l);
            }
        }
        if (kc < Ktot) {
            __nv_bfloat16* nb = sb + (buf^1)*BUFSZ;
            #pragma unroll
            for (int i = 0; i < 2; i++) {
                int f = i*256 + t;
                int r = f >> 3, c8 = (f & 7) << 3;
                *(uint4*)(nb + r*SROW + c8)           = ra[0][i];
                *(uint4*)(nb + 64*SROW + r*SROW + c8) = ra[1][i];
            }
            #pragma unroll
            for (int i = 0; i < 4; i++) {
                int f = i*256 + t;
                int r = f >> 3, c8 = (f & 7) << 3;
                *(uint4*)(nb + 128*SROW + r*SROW + c8) = rb[0][i];
                *(uint4*)(nb + 256*SROW + r*SROW + c8) = rb[1][i];
            }
            __syncthreads();
            buf ^= 1;
        }
    }

    const int rl4 = lane >> 2, cl2 = (lane & 3)*2;
    #pragma unroll
    for (int mt = 0; mt < 2; mt++)
        #pragma unroll
        for (int h2 = 0; h2 < 2; h2++) {
            int gr = row0 + wm*32 + mt*16 + rl4 + h2*8;
            #pragma unroll
            for (int nt = 0; nt < 4; nt++) {
                int gc = wn*32 + nt*8 + cl2;
                size_t idx = (size_t)gr*DIMC + gc;
                float2 v = *(float2*)(out + idx);
                v.x += acc[mt][nt][h2*2]   + bias[gc];
                v.y += acc[mt][nt][h2*2+1] + bias[gc+1];
                *(float2*)(out + idx) = v;
            }
        }
}

// ---------------- embed ----------------
__global__ void k_embed(const float* __restrict__ x, const float* __restrict__ lw,
                        const float* __restrict__ lb, const float* __restrict__ pe)
{
    int warp = threadIdx.x >> 5, lane = threadIdx.x & 31;
    int r = blockIdx.x*8 + warp;
    float xv = x[r];
    float4 l4 = ((const float4*)lw)[lane];
    float4 b4 = ((const float4*)lb)[lane];
    float4 p4 = ((const float4*)(pe + (size_t)(r % SS)*DIMC))[lane];
    float4 o4 = { xv*l4.x + b4.x + p4.x, xv*l4.y + b4.y + p4.y,
                  xv*l4.z + b4.z + p4.z, xv*l4.w + b4.w + p4.w };
    ((float4*)(g_h + (size_t)r*DIMC))[lane] = o4;
}

// ---------------- layernorm -> bf16 hi/lo ----------------
__global__ void k_ln(const float* __restrict__ in, const float* __restrict__ g,
                     const float* __restrict__ b,
                     __nv_bfloat16* __restrict__ outH, __nv_bfloat16* __restrict__ outL)
{
    int warp = threadIdx.x >> 5, lane = threadIdx.x & 31;
    int r = blockIdx.x*8 + warp;
    float4 v = ((const float4*)(in + (size_t)r*DIMC))[lane];
    float s = v.x + v.y + v.z + v.w;
    #pragma unroll
    for (int o = 16; o > 0; o >>= 1) s += __shfl_xor_sync(0xffffffffu, s, o);
    float mu = s * (1.0f/DIMC);
    float dx = v.x-mu, dy = v.y-mu, dz = v.z-mu, dw = v.w-mu;
    float q = dx*dx + dy*dy + dz*dz + dw*dw;
    #pragma unroll
    for (int o = 16; o > 0; o >>= 1) q += __shfl_xor_sync(0xffffffffu, q, o);
    float inv = rsqrtf(q*(1.0f/DIMC) + 1e-5f);
    float4 gv = ((const float4*)g)[lane];
    float4 bv = ((const float4*)b)[lane];
    float o4[4] = { dx*inv*gv.x + bv.x, dy*inv*gv.y + bv.y,
                    dz*inv*gv.z + bv.z, dw*inv*gv.w + bv.w };
    __nv_bfloat16 hh[4], ll[4];
    #pragma unroll
    for (int j = 0; j < 4; j++) split_bf16(o4[j], hh[j], ll[j]);
    size_t base = (size_t)r*DIMC + lane*4;
    *(uint2*)(outH+base) = *(uint2*)hh;
    *(uint2*)(outL+base) = *(uint2*)ll;
}

// -------- unified weight prep: one launch, all weights, both layers --------
__global__ __launch_bounds__(256) void k_wprep(
    const float* __restrict__ wq, const float* __restrict__ wk,
    const float* __restrict__ wv, const float* __restrict__ wo,
    const float* __restrict__ ff1_w, const float* __restrict__ ff2_w,
    const float* __restrict__ proj)
{
    __shared__ float tile[32][33];
    int bid = blockIdx.x;
    int l = (bid >= 656) ? 1 : 0;
    bid -= l*656;
    size_t wb = (size_t)l*WT_LAYER;
    __nv_bfloat16* wth = g_wth + wb;
    __nv_bfloat16* wtl = g_wtl + wb;

    const float* W; __nv_bfloat16 *oH, *oL; int K, N, tidx;
    if (bid < 384) {
        int which = bid >> 7; tidx = bid & 127;
        W = (which == 0 ? wq : which == 1 ? wk : wv) + (size_t)l*DIMC*INNER;
        oH = wth + (which == 0 ? WT_Q : which == 1 ? WT_K : WT_V);
        oL = wtl + (which == 0 ? WT_Q : which == 1 ? WT_K : WT_V);
        K = DIMC; N = INNER;
    } else if (bid < 512) {
        tidx = bid - 384;
        W = wo + (size_t)l*INNER*DIMC;
        oH = wth + WT_O; oL = wtl + WT_O;
        K = INNER; N = DIMC;
    } else if (bid < 576) {
        tidx = bid - 512;
        W = ff1_w + (size_t)l*DIMC*FFD;
        oH = wth + WT_F1; oL = wtl + WT_F1;
        K = DIMC; N = FFD;
    } else if (bid < 640) {
        tidx = bid - 576;
        W = ff2_w + (size_t)l*FFD*DIMC;
        oH = wth + WT_F2; oL = wtl + WT_F2;
        K = FFD; N = DIMC;
    } else {
        int e4 = (bid - 640)*256 + threadIdx.x;
        float4 v = ((const float4*)(proj + (size_t)l*MF*DHD))[e4];
        __nv_bfloat16 hh[4], ll[4];
        split_bf16(v.x, hh[0], ll[0]); split_bf16(v.y, hh[1], ll[1]);
        split_bf16(v.z, hh[2], ll[2]); split_bf16(v.w, hh[3], ll[3]);
        *(uint2*)(wth + WT_PJ + e4*4) = *(uint2*)hh;
        *(uint2*)(wtl + WT_PJ + e4*4) = *(uint2*)ll;
        return;
    }
    int ntiles = N >> 5;
    int n0 = (tidx % ntiles)*32, k0 = (tidx / ntiles)*32;
    int tx = threadIdx.x & 31, ty = threadIdx.x >> 5;
    #pragma unroll
    for (int i = ty; i < 32; i += 8)
        tile[i][tx] = W[(size_t)(k0+i)*N + n0 + tx];
    __syncthreads();
    #pragma unroll
    for (int i = ty; i < 32; i += 8) {
        float v = tile[tx][i];
        __nv_bfloat16 hh, ll;
        split_bf16(v, hh, ll);
        oH[(size_t)(n0+i)*K + k0 + tx] = hh;
        oL[(size_t)(n0+i)*K + k0 + tx] = ll;
    }
}

// ================= chunk-local attention via HMMA, 512 threads =================
#define CP 136
__global__ __launch_bounds__(512) void k_chunk(
    const __nv_bfloat16* __restrict__ qph, const __nv_bfloat16* __restrict__ qpl)
{
    extern __shared__ __align__(16) __nv_bfloat16 cs[];
    __nv_bfloat16* sQh = cs;
    __nv_bfloat16* sQl = sQh + 128*CP;
    __nv_bfloat16* sKh = sQl + 128*CP;
    __nv_bfloat16* sKl = sKh + 128*CP;
    __nv_bfloat16* sVh = sKl + 128*CP;
    __nv_bfloat16* sVl = sVh + 128*CP;
    __shared__ float s_den[4][128];
    __shared__ float s_dg[128];

    int blk = blockIdx.x, bh = blk >> 4, c = blk & 15;
    int b = bh >> 3, hh = bh & 7;
    int t = threadIdx.x, w = t >> 5, lane = t & 31;
    int wm = w & 3, wn = w >> 2;
    const int lrow = lane & 15, lcol8 = (lane >> 4)*8;
    const int rl4 = lane >> 2, cl2 = (lane & 3)*2;

    const size_t qbase = ((size_t)bh*SS + c*CHUNK)*MF;
    if (t < 128) {
        float st = g_bmax[bh*16];
        #pragma unroll
        for (int i = 1; i < 16; i++) st = fmaxf(st, g_bmax[bh*16 + i]);
        s_dg[t] = g_diagk[(size_t)bh*SS + c*CHUNK + t] + st;
    }
    for (int i = t; i < 2048; i += 512) {
        int r = i >> 4, c8 = (i & 15) << 3;
        *(uint4*)(sQh + r*CP + c8) = *(const uint4*)(qph + qbase + r*MF + c8);
        *(uint4*)(sQl + r*CP + c8) = *(const uint4*)(qpl + qbase + r*MF + c8);
        size_t vsrc = (size_t)(b*SS + c*CHUNK + r)*INNER + hh*DHD + c8;
        *(uint4*)(sVh + r*CP + c8) = *(const uint4*)(g_vh + vsrc);
        *(uint4*)(sVl + r*CP + c8) = *(const uint4*)(g_vl + vsrc);
    }
    __syncthreads();
    for (int f = t; f < 4096; f += 512) {
        int r = f >> 5, c4 = (f & 31) << 2;
        float4 dv = *(const float4*)(g_kp + qbase + (size_t)r*MF + c4);
        float dgv = s_dg[r];
        float o0 = RATIOC*(expf(dv.x - dgv) + 1e-4f);
        float o1 = RATIOC*(expf(dv.y - dgv) + 1e-4f);
        float o2 = RATIOC*(expf(dv.z - dgv) + 1e-4f);
        float o3 = RATIOC*(expf(dv.w - dgv) + 1e-4f);
        __nv_bfloat16 hh4[4], ll4[4];
        split_bf16(o0, hh4[0], ll4[0]); split_bf16(o1, hh4[1], ll4[1]);
        split_bf16(o2, hh4[2], ll4[2]); split_bf16(o3, hh4[3], ll4[3]);
        *(uint2*)(sKh + r*CP + c4) = *(uint2*)hh4;
        *(uint2*)(sKl + r*CP + c4) = *(uint2*)ll4;
    }
    __syncthreads();

    float acc[2][4][4] = {};
    if (wn <= wm) {
        #pragma unroll
        for (int ks = 0; ks < 8; ks++) {
            int kcol = ks*16 + lcol8;
            uint32_t ah[2][4], al[2][4];
            #pragma unroll
            for (int mt = 0; mt < 2; mt++) {
                int arow = wm*32 + mt*16 + lrow;
                ldsm4(ah[mt], s2u(sQh + arow*CP + kcol));
                ldsm4(al[mt], s2u(sQl + arow*CP + kcol));
            }
            #pragma unroll
            for (int nt2 = 0; nt2 < 2; nt2++) {
                int brow = wn*32 + nt2*16 + lrow;
                uint32_t rh[4], rl[4];
                ldsm4(rh, s2u(sKh + brow*CP + kcol));
                ldsm4(rl, s2u(sKl + brow*CP + kcol));
                uint32_t b0h[2] = {rh[0], rh[2]}, b1h[2] = {rh[1], rh[3]};
                uint32_t b0l[2] = {rl[0], rl[2]}, b1l[2] = {rl[1], rl[3]};
                #pragma unroll
                for (int mt = 0; mt < 2; mt++)
                    MMA3x2(acc[mt][nt2*2], acc[mt][nt2*2+1], ah[mt], al[mt], b0h, b0l, b1h, b1l);
            }
        }
    }
    float dp[2][2] = {};
    #pragma unroll
    for (int mt = 0; mt < 2; mt++)
        #pragma unroll
        for (int nt = 0; nt < 4; nt++)
            #pragma unroll
            for (int f = 0; f < 4; f++) {
                int i = wm*32 + mt*16 + rl4 + ((f>>1)<<3);
                int j = wn*32 + nt*8 + cl2 + (f&1);
                if (j > i) acc[mt][nt][f] = 0.f;
                dp[mt][f>>1] += acc[mt][nt][f];
            }
    #pragma unroll
    for (int o = 1; o < 4; o <<= 1)
        #pragma unroll
        for (int mt = 0; mt < 2; mt++)
            #pragma unroll
            for (int h2 = 0; h2 < 2; h2++)
                dp[mt][h2] += __shfl_xor_sync(0xffffffffu, dp[mt][h2], o);
    if ((lane & 3) == 0) {
        #pragma unroll
        for (int mt = 0; mt < 2; mt++)
            #pragma unroll
            for (int h2 = 0; h2 < 2; h2++)
                s_den[wn][wm*32 + mt*16 + rl4 + h2*8] = dp[mt][h2];
    }
    __syncthreads();

    #pragma unroll
    for (int mt = 0; mt < 2; mt++)
        #pragma unroll
        for (int nt = 0; nt < 4; nt++)
            #pragma unroll
            for (int f = 0; f < 4; f++) {
                int i = wm*32 + mt*16 + rl4 + ((f>>1)<<3);
                int j = wn*32 + nt*8 + cl2 + (f&1);
                __nv_bfloat16 hh2, ll2;
                split_bf16(acc[mt][nt][f], hh2, ll2);
                sQh[i*CP + j] = hh2;
                sQl[i*CP + j] = ll2;
            }
    if (t < 128) {
        g_den[(size_t)bh*SS + c*CHUNK + t] = s_den[0][t] + s_den[1][t] + s_den[2][t] + s_den[3][t];
        float kssum = 0.f;
        for (int j = 0; j < 128; j++)
            kssum += __bfloat162float(sKh[j*CP + t]) + __bfloat162float(sKl[j*CP + t]);
        g_ksc[((size_t)bh*NC + c)*MF + t] = kssum;
    }
    __syncthreads();

    #pragma unroll
    for (int mt = 0; mt < 2; mt++)
        #pragma unroll
        for (int nt = 0; nt < 4; nt++)
            #pragma unroll
            for (int f = 0; f < 4; f++) acc[mt][nt][f] = 0.f;
    #pragma unroll
    for (int ks = 0; ks < 8; ks++) {
        int kcol = ks*16 + lcol8;
        uint32_t ah[2][4], al[2][4];
        #pragma unroll
        for (int mt = 0; mt < 2; mt++) {
            int arow = wm*32 + mt*16 + lrow;
            ldsm4(ah[mt], s2u(sQh + arow*CP + kcol));
            ldsm4(al[mt], s2u(sQl + arow*CP + kcol));
        }
        #pragma unroll
        for (int nt2 = 0; nt2 < 2; nt2++) {
            int nbase = wn*32 + nt2*16;
            uint32_t dh[4], dl[4];
            ldsm4t(dh, taddr(sVh, CP, ks*16, nbase, lane));
            ldsm4t(dl, taddr(sVl, CP, ks*16, nbase, lane));
            uint32_t b0h[2] = {dh[0], dh[2]}, b1h[2] = {dh[1], dh[3]};
            uint32_t b0l[2] = {dl[0], dl[2]}, b1l[2] = {dl[1], dl[3]};
            #pragma unroll
            for (int mt = 0; mt < 2; mt++)
                MMA3x2(acc[mt][nt2*2], acc[mt][nt2*2+1], ah[mt], al[mt], b0h, b0l, b1h, b1l);
        }
    }
    #pragma unroll
    for (int mt = 0; mt < 2; mt++)
        #pragma unroll
        for (int h2 = 0; h2 < 2; h2++) {
            int i = wm*32 + mt*16 + rl4 + h2*8;
            size_t base = ((size_t)(b*SS + c*CHUNK + i)*HH + hh)*DHD;
            #pragma unroll
            for (int nt = 0; nt < 4; nt++) {
                float2 vv = {acc[mt][nt][h2*2], acc[mt][nt][h2*2+1]};
                *(float2*)(g_o + base + wn*32 + nt*8 + cl2) = vv;
            }
        }

    #pragma unroll
    for (int mt = 0; mt < 2; mt++)
        #pragma unroll
        for (int nt = 0; nt < 4; nt++)
            #pragma unroll
            for (int f = 0; f < 4; f++) acc[mt][nt][f] = 0.f;
    #pragma unroll
    for (int ks = 0; ks < 8; ks++) {
        uint32_t ah[2][4], al[2][4];
        #pragma unroll
        for (int mt = 0; mt < 2; mt++) {
            int mbase = wm*32 + mt*16;
            ldsm4t(ah[mt], taddr(sKh, CP, ks*16, mbase, lane));
            ldsm4t(al[mt], taddr(sKl, CP, ks*16, mbase, lane));
        }
        #pragma unroll
        for (int nt2 = 0; nt2 < 2; nt2++) {
            int nbase = wn*32 + nt2*16;
            uint32_t dh[4], dl[4];
            ldsm4t(dh, taddr(sVh, CP, ks*16, nbase, lane));
            ldsm4t(dl, taddr(sVl, CP, ks*16, nbase, lane));
            uint32_t b0h[2] = {dh[0], dh[2]}, b1h[2] = {dh[1], dh[3]};
            uint32_t b0l[2] = {dl[0], dl[2]}, b1l[2] = {dl[1], dl[3]};
            #pragma unroll
            for (int mt = 0; mt < 2; mt++)
                MMA3x2(acc[mt][nt2*2], acc[mt][nt2*2+1], ah[mt], al[mt], b0h, b0l, b1h, b1l);
        }
    }
    {
        size_t kvbase = ((size_t)bh*NC + c)*(MF*DHD);
        #pragma unroll
        for (int mt = 0; mt < 2; mt++)
            #pragma unroll
            for (int h2 = 0; h2 < 2; h2++) {
                int m = wm*32 + mt*16 + rl4 + h2*8;
                #pragma unroll
                for (int nt = 0; nt < 4; nt++) {
                    float2 vv = {acc[mt][nt][h2*2], acc[mt][nt][h2*2+1]};
                    *(float2*)(g_kvc + kvbase + (size_t)m*DHD + wn*32 + nt*8 + cl2) = vv;
                }
            }
    }
}

// ---------------- exclusive prefix over chunks (emits bf16 hi/lo) ----------------
__global__ void k_prefix()
{
    int bh = blockIdx.x, seg = blockIdx.y, t = threadIdx.x;
    for (int e = seg*2048 + t; e < (seg+1)*2048; e += 256) {
        float run = 0.f;
        #pragma unroll
        for (int c = 0; c < NC; c++) {
            size_t idx = ((size_t)bh*NC + c)*(MF*DHD) + e;
            __nv_bfloat16 hh, ll;
            split_bf16(run, hh, ll);
            g_kvph[idx] = hh; g_kvpl[idx] = ll;
            run += g_kvc[idx];
        }
    }
    if (seg == 0) {
        for (int e = t; e < MF; e += 256) {
            float run = 0.f;
            #pragma unroll
            for (int c = 0; c < NC; c++) {
                size_t idx = ((size_t)bh*NC + c)*MF + e;
                g_ksp[idx] = run; run += g_ksc[idx];
            }
        }
    }
}

// ========== cross = qp @ kvp, + num, normalize -> oh/ol (HMMA, 512 thr) ==========
__global__ __launch_bounds__(512) void k_cross(
    const __nv_bfloat16* __restrict__ qph, const __nv_bfloat16* __restrict__ qpl)
{
    extern __shared__ __align__(16) __nv_bfloat16 cs[];
    __nv_bfloat16* sQh = cs;
    __nv_bfloat16* sQl = sQh + 128*CP;
    __nv_bfloat16* sPh = sQl + 128*CP;
    __nv_bfloat16* sPl = sPh + 128*CP;
    __shared__ float s_ks[128];
    __shared__ float s_dc[128];

    int blk = blockIdx.x, bh = blk >> 4, c = blk & 15;
    int b = bh >> 3, hh = bh & 7;
    int t = threadIdx.x, w = t >> 5, lane = t & 31;
    int wm = w & 3, wn = w >> 2;
    const int lrow = lane & 15, lcol8 = (lane >> 4)*8;
    const int rl4 = lane >> 2, cl2 = (lane & 3)*2;

    const size_t qbase = ((size_t)bh*SS + c*CHUNK)*MF;
    const size_t pbase = ((size_t)bh*NC + c)*(MF*DHD);
    for (int i = t; i < 2048; i += 512) {
        int r = i >> 4, c8 = (i & 15) << 3;
        *(uint4*)(sQh + r*CP + c8) = *(const uint4*)(qph + qbase + r*MF + c8);
        *(uint4*)(sQl + r*CP + c8) = *(const uint4*)(qpl + qbase + r*MF + c8);
        *(uint4*)(sPh + r*CP + c8) = *(const uint4*)(g_kvph + pbase + r*DHD + c8);
        *(uint4*)(sPl + r*CP + c8) = *(const uint4*)(g_kvpl + pbase + r*DHD + c8);
    }
    if (t < 128) s_ks[t] = g_ksp[((size_t)bh*NC + c)*MF + t];
    __syncthreads();
    if (t < 128) {
        float dc = 0.f;
        for (int m = 0; m < 128; m++)
            dc += (__bfloat162float(sQh[t*CP + m]) + __bfloat162float(sQl[t*CP + m]))*s_ks[m];
        s_dc[t] = g_den[(size_t)bh*SS + c*CHUNK + t] + dc + 1e-6f;
    }
    __syncthreads();

    float acc[2][4][4] = {};
    #pragma unroll
    for (int ks = 0; ks < 8; ks++) {
        int kcol = ks*16 + lcol8;
        uint32_t ah[2][4], al[2][4];
        #pragma unroll
        for (int mt = 0; mt < 2; mt++) {
            int arow = wm*32 + mt*16 + lrow;
            ldsm4(ah[mt], s2u(sQh + arow*CP + kcol));
            ldsm4(al[mt], s2u(sQl + arow*CP + kcol));
        }
        #pragma unroll
        for (int nt2 = 0; nt2 < 2; nt2++) {
            int nbase = wn*32 + nt2*16;
            uint32_t dh[4], dl[4];
            ldsm4t(dh, taddr(sPh, CP, ks*16, nbase, lane));
            ldsm4t(dl, taddr(sPl, CP, ks*16, nbase, lane));
            uint32_t b0h[2] = {dh[0], dh[2]}, b1h[2] = {dh[1], dh[3]};
            uint32_t b0l[2] = {dl[0], dl[2]}, b1l[2] = {dl[1], dl[3]};
            #pragma unroll
            for (int mt = 0; mt < 2; mt++)
                MMA3x2(acc[mt][nt2*2], acc[mt][nt2*2+1], ah[mt], al[mt], b0h, b0l, b1h, b1l);
        }
    }
    #pragma unroll
    for (int mt = 0; mt < 2; mt++)
        #pragma unroll
        for (int h2 = 0; h2 < 2; h2++) {
            int i = wm*32 + mt*16 + rl4 + h2*8;
            float inv = 1.0f / s_dc[i];
            size_t base = ((size_t)(b*SS + c*CHUNK + i)*HH + hh)*DHD;
            #pragma unroll
            for (int nt = 0; nt < 4; nt++) {
                size_t idx = base + wn*32 + nt*8 + cl2;
                float2 nn = *(float2*)(g_o + idx);
                float v0 = (nn.x + acc[mt][nt][h2*2])   * inv;
                float v1 = (nn.y + acc[mt][nt][h2*2+1]) * inv;
                __nv_bfloat16 h0,l0,h1,l1;
                split_bf16(v0,h0,l0); split_bf16(v1,h1,l1);
                __nv_bfloat162 hp, lp;
                hp.x = h0; hp.y = h1; lp.x = l0; lp.y = l1;
                *(__nv_bfloat162*)(g_oh + idx) = hp;
                *(__nv_bfloat162*)(g_ol + idx) = lp;
            }
        }
}

// ---------------- pooling ----------------
__global__ void k_pool()
{
    int b = blockIdx.x, seg = blockIdx.y, t = threadIdx.x;
    float acc = 0.f;
    for (int s = seg*128; s < (seg+1)*128; s++) acc += g_h[((size_t)b*SS + s)*DIMC + t];
    g_pp[(b*16 + seg)*DIMC + t] = acc;
}

__global__ void k_final(const float* __restrict__ fw, const float* __restrict__ fb,
                        float* __restrict__ out)
{
    __shared__ float pooled[BB*DIMC];
    int t = threadIdx.x;
    for (int b = 0; b < BB; b++) {
        float a = 0.f;
        #pragma unroll
        for (int s = 0; s < 16; s++) a += g_pp[(b*16 + s)*DIMC + t];
        pooled[b*DIMC + t] = a * (1.0f/SS);
    }
    __syncthreads();
    if (t < BB*NCLS) {
        int b = t / NCLS, c = t % NCLS;
        float acc = fb[c];
        for (int d = 0; d < DIMC; d++) acc += pooled[b*DIMC + d]*fw[d*NCLS + c];
        out[t] = acc;
    }
}

// ---------------- host driver ----------------
static void* sym(const void* s) { void* p = nullptr; cudaGetSymbolAddress(&p, s); return p; }

extern "C" void kernel_launch(void* const* d_in, const int* in_sizes, int n_in,
                              void* d_out, int out_size)
{
    const float* x     = (const float*)d_in[0];
    const float* lin_w = (const float*)d_in[1];
    const float* lin_b = (const float*)d_in[2];
    const float* pe    = (const float*)d_in[3];
    const float* proj  = (const float*)d_in[4];
    const float* ln1_g = (const float*)d_in[5];
    const float* ln1_b = (const float*)d_in[6];
    const float* wq    = (const float*)d_in[7];
    const float* wk    = (const float*)d_in[8];
    const float* wv    = (const float*)d_in[9];
    const float* wo    = (const float*)d_in[10];
    const float* wo_b  = (const float*)d_in[11];
    const float* ln2_g = (const float*)d_in[12];
    const float* ln2_b = (const float*)d_in[13];
    const float* ff1_w = (const float*)d_in[14];
    const float* ff1_b = (const float*)d_in[15];
    const float* ff2_w = (const float*)d_in[16];
    const float* ff2_b = (const float*)d_in[17];
    const float* fin_w = (const float*)d_in[18];
    const float* fin_b = (const float*)d_in[19];
    float* out = (float*)d_out;

    float* ph   = (float*)sym(g_h);
    float* pkp  = (float*)sym(g_kp);
    float* pbm  = (float*)sym(g_bmax);

    __nv_bfloat16* yh  = (__nv_bfloat16*)sym(g_yh);
    __nv_bfloat16* yl  = (__nv_bfloat16*)sym(g_yl);
    __nv_bfloat16* wth = (__nv_bfloat16*)sym(g_wth);
    __nv_bfloat16* wtl = (__nv_bfloat16*)sym(g_wtl);
    __nv_bfloat16* qnh = (__nv_bfloat16*)sym(g_qnh);
    __nv_bfloat16* qnl = (__nv_bfloat16*)sym(g_qnl);
    __nv_bfloat16* knh = (__nv_bfloat16*)sym(g_knh);
    __nv_bfloat16* knl = (__nv_bfloat16*)sym(g_knl);
    __nv_bfloat16* qp_h = (__nv_bfloat16*)sym(g_qph);
    __nv_bfloat16* qp_l = (__nv_bfloat16*)sym(g_qpl);
    __nv_bfloat16* oh  = (__nv_bfloat16*)sym(g_oh);
    __nv_bfloat16* ol  = (__nv_bfloat16*)sym(g_ol);
    __nv_bfloat16* fh  = (__nv_bfloat16*)sym(g_fh);
    __nv_bfloat16* fl  = (__nv_bfloat16*)sym(g_fl);

    const int SMEM_MMA   = 4*128*FP*2;           // 73728 (features, 2 CTAs/SM)
    const int SMEM_QKVFF = QKV_SMEM;             // 104448 (2 CTAs/SM)
    const int SMEM_MMA64 = 2*BUFSZ*2;            // 110592 (round-10 proven)
    const int SMEM_CHUNK = 6*128*CP*2;           // 208896
    const int SMEM_CROSS = 4*128*CP*2;           // 139264
    cudaFuncSetAttribute(k_mmaF, cudaFuncAttributeMaxDynamicSharedMemorySize, SMEM_MMA);
    cudaFuncSetAttribute(k_mmaqkv64, cudaFuncAttributeMaxDynamicSharedMemorySize, SMEM_QKVFF);
    cudaFuncSetAttribute(k_ff1, cudaFuncAttributeMaxDynamicSharedMemorySize, SMEM_QKVFF);
    cudaFuncSetAttribute(k_mma64, cudaFuncAttributeMaxDynamicSharedMemorySize, SMEM_MMA64);
    cudaFuncSetAttribute(k_chunk, cudaFuncAttributeMaxDynamicSharedMemorySize, SMEM_CHUNK);
    cudaFuncSetAttribute(k_cross, cudaFuncAttributeMaxDynamicSharedMemorySize, SMEM_CROSS);

    k_embed<<<BSR/8, 256>>>(x, lin_w, lin_b, pe);

    k_wprep<<<2*656, 256>>>(wq, wk, wv, wo, ff1_w, ff2_w, proj);

    for (int l = 0; l < DEPTH; l++) {
        size_t wb = (size_t)l*WT_LAYER;

        k_ln<<<BSR/8, 256>>>(ph, ln1_g + l*DIMC, ln1_b + l*DIMC, yh, yl);

        k_mmaqkv64<<<dim3(48,64), 256, SMEM_QKVFF>>>(yh, yl, wth+wb+WT_Q, wtl+wb+WT_Q);

        k_mmaF<<<dim3(2,512), 256, SMEM_MMA>>>(knh, knl, qnh, qnl,
                                               wth+wb+WT_PJ, wtl+wb+WT_PJ,
                                               pkp, qp_h, qp_l, pbm);

        k_chunk<<<NBH*NC, 512, SMEM_CHUNK>>>(qp_h, qp_l);
        k_prefix<<<dim3(NBH, 8), 256>>>();
        k_cross<<<NBH*NC, 512, SMEM_CROSS>>>(qp_h, qp_l);

        k_mma64<<<dim3(1,BSR/64), 256, SMEM_MMA64>>>(oh, ol, INNER, wth+wb+WT_O, wtl+wb+WT_O, INNER,
                                                     wo_b + l*DIMC, ph);

        k_ln<<<BSR/8, 256>>>(ph, ln2_g + l*DIMC, ln2_b + l*DIMC, yh, yl);
        k_ff1<<<dim3(8,64), 256, SMEM_QKVFF>>>(yh, yl, wth+wb+WT_F1, wtl+wb+WT_F1, ff1_b + l*FFD);
        k_mma64<<<dim3(1,BSR/64), 256, SMEM_MMA64>>>(fh, fl, FFD, wth+wb+WT_F2, wtl+wb+WT_F2, FFD,
                                                     ff2_b + l*DIMC, ph);
    }

    k_pool<<<dim3(BB, 16), 128>>>();
    k_final<<<1, 128>>>(fin_w, fin_b, out);
}

// round 14
// speedup vs baseline: 1.0202x; 1.0202x over previous
#include <cuda_runtime.h>
#include <cuda_bf16.h>
#include <math.h>
#include <stdint.h>

// ---------------- problem constants ----------------
#define BB 4
#define SS 2048
#define DIMC 128
#define HH 8
#define DHD 128
#define DEPTH 2
#define NCLS 10
#define MF 128
#define CHUNK 128
#define NC 16
#define INNER 1024
#define FFD 512
#define BSR 8192
#define BHS 65536
#define NBH 32

#define NORMC 0.29730177875068026f
#define RATIOC 0.08838834764831845f

// ---------------- device scratch (fp32) ----------------
__device__ float g_h  [BSR*DIMC];
__device__ float g_kp [(size_t)NBH*SS*MF];
__device__ float g_diagk[BHS];
__device__ float g_bmax[NBH*16];
__device__ float g_o  [BSR*INNER];
__device__ float g_den[BHS];
__device__ float g_kvc[(size_t)NBH*NC*MF*DHD];
__device__ float g_ksc[NBH*NC*MF];
__device__ float g_ksp[NBH*NC*MF];
__device__ float g_pp [BB*16*DIMC];

// ---------------- device scratch (bf16 hi/lo) ----------------
__device__ __align__(256) __nv_bfloat16 g_yh [BSR*DIMC];
__device__ __align__(256) __nv_bfloat16 g_yl [BSR*DIMC];
__device__ __align__(256) __nv_bfloat16 g_wth[2*672000];
__device__ __align__(256) __nv_bfloat16 g_wtl[2*672000];
__device__ __align__(256) __nv_bfloat16 g_qnh[(size_t)BHS*DHD];
__device__ __align__(256) __nv_bfloat16 g_qnl[(size_t)BHS*DHD];
__device__ __align__(256) __nv_bfloat16 g_knh[(size_t)BHS*DHD];
__device__ __align__(256) __nv_bfloat16 g_knl[(size_t)BHS*DHD];
__device__ __align__(256) __nv_bfloat16 g_vh [(size_t)BSR*INNER];
__device__ __align__(256) __nv_bfloat16 g_vl [(size_t)BSR*INNER];
__device__ __align__(256) __nv_bfloat16 g_qph[(size_t)NBH*SS*MF];
__device__ __align__(256) __nv_bfloat16 g_qpl[(size_t)NBH*SS*MF];
__device__ __align__(256) __nv_bfloat16 g_kvph[(size_t)NBH*NC*MF*DHD];
__device__ __align__(256) __nv_bfloat16 g_kvpl[(size_t)NBH*NC*MF*DHD];
__device__ __align__(256) __nv_bfloat16 g_oh [(size_t)BSR*INNER];
__device__ __align__(256) __nv_bfloat16 g_ol [(size_t)BSR*INNER];
__device__ __align__(256) __nv_bfloat16 g_fh [(size_t)BSR*FFD];
__device__ __align__(256) __nv_bfloat16 g_fl [(size_t)BSR*FFD];

#define WT_Q  0
#define WT_K  131072
#define WT_V  262144
#define WT_O  393216
#define WT_F1 524288
#define WT_F2 589824
#define WT_PJ 655360
#define WT_LAYER 672000

// ---------------- warp MMA helpers ----------------
__device__ __forceinline__ uint32_t s2u(const void* p){
    uint32_t a;
    asm("{ .reg .u64 t; cvta.to.shared.u64 t, %1; cvt.u32.u64 %0, t; }" : "=r"(a) : "l"(p));
    return a;
}
__device__ __forceinline__ void ldsm4(uint32_t* r, uint32_t addr){
    asm volatile("ldmatrix.sync.aligned.m8n8.x4.shared.b16 {%0,%1,%2,%3}, [%4];"
                 : "=r"(r[0]),"=r"(r[1]),"=r"(r[2]),"=r"(r[3]) : "r"(addr));
}
__device__ __forceinline__ void ldsm4t(uint32_t* r, uint32_t addr){
    asm volatile("ldmatrix.sync.aligned.m8n8.x4.trans.shared.b16 {%0,%1,%2,%3}, [%4];"
                 : "=r"(r[0]),"=r"(r[1]),"=r"(r[2]),"=r"(r[3]) : "r"(addr));
}
__device__ __forceinline__ void mma_bf16(float* c, const uint32_t* a, const uint32_t* b){
    asm volatile("mma.sync.aligned.m16n8k16.row.col.f32.bf16.bf16.f32 "
                 "{%0,%1,%2,%3}, {%4,%5,%6,%7}, {%8,%9}, {%0,%1,%2,%3};"
                 : "+f"(c[0]),"+f"(c[1]),"+f"(c[2]),"+f"(c[3])
                 : "r"(a[0]),"r"(a[1]),"r"(a[2]),"r"(a[3]), "r"(b[0]),"r"(b[1]));
}
__device__ __forceinline__ void split_bf16(float v, __nv_bfloat16& h, __nv_bfloat16& l){
    h = __float2bfloat16(v);
    l = __float2bfloat16(v - __bfloat162float(h));
}
__device__ __forceinline__ float gelu(float xx){
    return 0.5f*xx*(1.0f + tanhf(0.7978845608028654f*(xx + 0.044715f*xx*xx*xx)));
}
__device__ __forceinline__ uint32_t taddr(const __nv_bfloat16* S, int P, int kbase, int nbase, int lane){
    int kk = (lane & 7) + ((lane >> 4) << 3);
    int nn = ((lane >> 3) & 1) << 3;
    return s2u(S + (size_t)(kbase + kk)*P + nbase + nn);
}
#define MMA3x2(accA, accB, ah_, al_, b0h_, b0l_, b1h_, b1l_) \
    do { mma_bf16(accA, ah_, b0h_); mma_bf16(accA, ah_, b0l_); mma_bf16(accA, al_, b0h_); \
         mma_bf16(accB, ah_, b1h_); mma_bf16(accB, ah_, b1l_); mma_bf16(accB, al_, b1h_); } while(0)

#define KP 136

// ======== merged feature GEMM (single-stage K=128, round-10 proven):
// blockIdx.x==0 -> K features (dd+bmax+diag); ==1 -> Q features (exp -> qp hi/lo)
__global__ __launch_bounds__(256) void k_mmaF(
    const __nv_bfloat16* __restrict__ Kh, const __nv_bfloat16* __restrict__ Kl,
    const __nv_bfloat16* __restrict__ Qh, const __nv_bfloat16* __restrict__ Ql,
    const __nv_bfloat16* __restrict__ Bh, const __nv_bfloat16* __restrict__ Bl,
    float* __restrict__ out,
    __nv_bfloat16* __restrict__ outH, __nv_bfloat16* __restrict__ outL,
    float* __restrict__ bmax)
{
    extern __shared__ __align__(16) char dsm[];
    __nv_bfloat16* sAh = (__nv_bfloat16*)dsm;
    __nv_bfloat16* sAl = sAh + 128*KP;
    __nv_bfloat16* sBh = sAl + 128*KP;
    __nv_bfloat16* sBl = sBh + 128*KP;
    __shared__ float s_rm[2][128];
    __shared__ float s_red[256];
    __shared__ float s_dg[128];

    const int MODE = (blockIdx.x == 0) ? 4 : 3;
    const __nv_bfloat16* Ah = (MODE == 4) ? Kh : Qh;
    const __nv_bfloat16* Al = (MODE == 4) ? Kl : Ql;

    const int t = threadIdx.x, w = t >> 5, lane = t & 31;
    const int wm = w & 3, wn = w >> 2;
    const int row0 = blockIdx.y*128;

    float acc[2][8][4] = {};
    const int lrow = (lane & 15), lcol8 = (lane >> 4)*8;

    #pragma unroll
    for (int i = 0; i < 8; i++) {
        int f = i*256 + t;
        int r = f >> 4, c8 = (f & 15) << 3;
        *(uint4*)(sAh + r*KP + c8) = *(const uint4*)(Ah + (size_t)(row0+r)*128 + c8);
        *(uint4*)(sAl + r*KP + c8) = *(const uint4*)(Al + (size_t)(row0+r)*128 + c8);
        *(uint4*)(sBh + r*KP + c8) = *(const uint4*)(Bh + (size_t)r*128 + c8);
        *(uint4*)(sBl + r*KP + c8) = *(const uint4*)(Bl + (size_t)r*128 + c8);
    }
    __syncthreads();

    if (t < 128) {
        float dacc = 0.f;
        #pragma unroll
        for (int k8 = 0; k8 < 16; k8++) {
            uint4 uh = *(uint4*)(sAh + t*KP + k8*8);
            uint4 ul = *(uint4*)(sAl + t*KP + k8*8);
            const __nv_bfloat16* ph = (const __nv_bfloat16*)&uh;
            const __nv_bfloat16* pl = (const __nv_bfloat16*)&ul;
            #pragma unroll
            for (int j = 0; j < 8; j++) {
                float av = __bfloat162float(ph[j]) + __bfloat162float(pl[j]);
                dacc += av*av;
            }
        }
        if (MODE == 4) g_diagk[row0 + t] = 0.5f*dacc;
        else           s_dg[t] = 0.5f*dacc;
    }

    #pragma unroll
    for (int ks = 0; ks < 8; ks++) {
        int kcol = ks*16 + lcol8;
        uint32_t ah[2][4], al[2][4];
        #pragma unroll
        for (int mt = 0; mt < 2; mt++) {
            int arow = wm*32 + mt*16 + lrow;
            ldsm4(ah[mt], s2u(sAh + arow*KP + kcol));
            ldsm4(al[mt], s2u(sAl + arow*KP + kcol));
        }
        #pragma unroll
        for (int nt2 = 0; nt2 < 4; nt2++) {
            int brow = wn*64 + nt2*16 + lrow;
            uint32_t rh[4], rl[4];
            ldsm4(rh, s2u(sBh + brow*KP + kcol));
            ldsm4(rl, s2u(sBl + brow*KP + kcol));
            uint32_t b0h[2] = {rh[0], rh[2]}, b1h[2] = {rh[1], rh[3]};
            uint32_t b0l[2] = {rl[0], rl[2]}, b1l[2] = {rl[1], rl[3]};
            #pragma unroll
            for (int mt = 0; mt < 2; mt++)
                MMA3x2(acc[mt][nt2*2], acc[mt][nt2*2+1], ah[mt], al[mt], b0h, b0l, b1h, b1l);
        }
    }

    const int rl4 = lane >> 2, cl2 = (lane & 3)*2;

    if (MODE == 4) {
        float bm = -1e30f;
        #pragma unroll
        for (int mt = 0; mt < 2; mt++)
            #pragma unroll
            for (int h = 0; h < 2; h++) {
                int gr = row0 + wm*32 + mt*16 + rl4 + h*8;
                #pragma unroll
                for (int nt = 0; nt < 8; nt++) {
                    float2 v = {acc[mt][nt][h*2], acc[mt][nt][h*2+1]};
                    *(float2*)(out + (size_t)gr*MF + wn*64 + nt*8 + cl2) = v;
                    bm = fmaxf(bm, fmaxf(v.x, v.y));
                }
            }
        s_red[t] = bm; __syncthreads();
        #pragma unroll
        for (int o = 128; o > 0; o >>= 1) { if (t < o) s_red[t] = fmaxf(s_red[t], s_red[t+o]); __syncthreads(); }
        if (t == 0) bmax[blockIdx.y] = s_red[0];
    } else {
        float rm[2][2];
        #pragma unroll
        for (int mt = 0; mt < 2; mt++)
            #pragma unroll
            for (int h = 0; h < 2; h++) {
                float m = -1e30f;
                #pragma unroll
                for (int nt = 0; nt < 8; nt++)
                    m = fmaxf(m, fmaxf(acc[mt][nt][h*2], acc[mt][nt][h*2+1]));
                m = fmaxf(m, __shfl_xor_sync(0xffffffffu, m, 1));
                m = fmaxf(m, __shfl_xor_sync(0xffffffffu, m, 2));
                rm[mt][h] = m;
            }
        if ((lane & 3) == 0) {
            #pragma unroll
            for (int mt = 0; mt < 2; mt++)
                #pragma unroll
                for (int h = 0; h < 2; h++)
                    s_rm[wn][wm*32 + mt*16 + rl4 + h*8] = rm[mt][h];
        }
        __syncthreads();
        #pragma unroll
        for (int mt = 0; mt < 2; mt++)
            #pragma unroll
            for (int h = 0; h < 2; h++) {
                int lr = wm*32 + mt*16 + rl4 + h*8;
                int gr = row0 + lr;
                float rmax = fmaxf(s_rm[0][lr], s_rm[1][lr]);
                float dg = s_dg[lr];
                #pragma unroll
                for (int nt = 0; nt < 8; nt++) {
                    int gc = wn*64 + nt*8 + cl2;
                    float v0 = RATIOC*(expf(acc[mt][nt][h*2]  -dg-rmax) + 1e-4f);
                    float v1 = RATIOC*(expf(acc[mt][nt][h*2+1]-dg-rmax) + 1e-4f);
                    __nv_bfloat16 h0,l0,h1,l1;
                    split_bf16(v0,h0,l0); split_bf16(v1,h1,l1);
                    __nv_bfloat162 hp, lp;
                    hp.x = h0; hp.y = h1; lp.x = l0; lp.y = l1;
                    *(__nv_bfloat162*)(outH + (size_t)gr*MF + gc) = hp;
                    *(__nv_bfloat162*)(outL + (size_t)gr*MF + gc) = lp;
                }
            }
    }
}

// ======== 128x64-tile K=128 mainloop (2 CTAs/SM) — shared by QKV and FF1 ========
#define QKV_SMEM ((2*128 + 2*64)*KP*2)
#define MAINLOOP_64COL(sAh, sAl, sBh, sBl, Ah, Al, Bh, Bl, row0, col0, acc) \
    {   \
        _Pragma("unroll")                                                        \
        for (int i = 0; i < 8; i++) {                                            \
            int f = i*256 + threadIdx.x;                                         \
            int r = f >> 4, c8 = (f & 15) << 3;                                  \
            *(uint4*)(sAh + r*KP + c8) = *(const uint4*)(Ah + (size_t)(row0+r)*128 + c8); \
            *(uint4*)(sAl + r*KP + c8) = *(const uint4*)(Al + (size_t)(row0+r)*128 + c8); \
        }                                                                        \
        _Pragma("unroll")                                                        \
        for (int i = 0; i < 4; i++) {                                            \
            int f = i*256 + threadIdx.x;                                         \
            int r = f >> 4, c8 = (f & 15) << 3;                                  \
            *(uint4*)(sBh + r*KP + c8) = *(const uint4*)(Bh + (size_t)(col0+r)*128 + c8); \
            *(uint4*)(sBl + r*KP + c8) = *(const uint4*)(Bl + (size_t)(col0+r)*128 + c8); \
        }                                                                        \
        __syncthreads();                                                         \
        _Pragma("unroll")                                                        \
        for (int ks = 0; ks < 8; ks++) {                                         \
            int kcol = ks*16 + lcol8;                                            \
            uint32_t ah[2][4], al[2][4];                                         \
            _Pragma("unroll")                                                    \
            for (int mt = 0; mt < 2; mt++) {                                     \
                int arow = wm*32 + mt*16 + lrow;                                 \
                ldsm4(ah[mt], s2u(sAh + arow*KP + kcol));                        \
                ldsm4(al[mt], s2u(sAl + arow*KP + kcol));                        \
            }                                                                    \
            _Pragma("unroll")                                                    \
            for (int nt2 = 0; nt2 < 2; nt2++) {                                  \
                int brow = wn*32 + nt2*16 + lrow;                                \
                uint32_t rh[4], rl[4];                                           \
                ldsm4(rh, s2u(sBh + brow*KP + kcol));                            \
                ldsm4(rl, s2u(sBl + brow*KP + kcol));                            \
                uint32_t b0h[2] = {rh[0], rh[2]}, b1h[2] = {rh[1], rh[3]};       \
                uint32_t b0l[2] = {rl[0], rl[2]}, b1l[2] = {rl[1], rl[3]};       \
                _Pragma("unroll")                                                \
                for (int mt = 0; mt < 2; mt++)                                   \
                    MMA3x2(acc[mt][nt2*2], acc[mt][nt2*2+1], ah[mt], al[mt], b0h, b0l, b1h, b1l); \
            }                                                                    \
        }                                                                        \
    }

// QKV: grid (48, 64); epilogue scatters per part/head
__global__ __launch_bounds__(256) void k_mmaqkv64(
    const __nv_bfloat16* __restrict__ Ah, const __nv_bfloat16* __restrict__ Al,
    const __nv_bfloat16* __restrict__ Bh, const __nv_bfloat16* __restrict__ Bl)
{
    extern __shared__ __align__(16) char dsm[];
    __nv_bfloat16* sAh = (__nv_bfloat16*)dsm;
    __nv_bfloat16* sAl = sAh + 128*KP;
    __nv_bfloat16* sBh = sAl + 128*KP;
    __nv_bfloat16* sBl = sBh + 64*KP;
    const int t = threadIdx.x, w = t >> 5, lane = t & 31;
    const int wm = w & 3, wn = w >> 2;
    const int row0 = blockIdx.y*128, col0 = blockIdx.x*64;
    const int lrow = (lane & 15), lcol8 = (lane >> 4)*8;
    float acc[2][4][4] = {};

    MAINLOOP_64COL(sAh, sAl, sBh, sBl, Ah, Al, Bh, Bl, row0, col0, acc);

    const int rl4 = lane >> 2, cl2 = (lane & 3)*2;
    const int part = col0 >> 10;
    const int h = (col0 >> 7) & 7;
    const int d0 = col0 & 127;

    if (part < 2) {
        __nv_bfloat16* dH = part ? g_knh : g_qnh;
        __nv_bfloat16* dL = part ? g_knl : g_qnl;
        #pragma unroll
        for (int mt = 0; mt < 2; mt++)
            #pragma unroll
            for (int h2 = 0; h2 < 2; h2++) {
                int gr = row0 + wm*32 + mt*16 + rl4 + h2*8;
                int b = gr >> 11, s = gr & 2047;
                size_t base = ((size_t)(b*HH + h)*SS + s)*DHD + d0;
                #pragma unroll
                for (int nt = 0; nt < 4; nt++) {
                    float v0 = acc[mt][nt][h2*2]   * NORMC;
                    float v1 = acc[mt][nt][h2*2+1] * NORMC;
                    __nv_bfloat16 h0,l0,h1,l1;
                    split_bf16(v0,h0,l0); split_bf16(v1,h1,l1);
                    __nv_bfloat162 hp, lp;
                    hp.x = h0; hp.y = h1; lp.x = l0; lp.y = l1;
                    *(__nv_bfloat162*)(dH + base + wn*32 + nt*8 + cl2) = hp;
                    *(__nv_bfloat162*)(dL + base + wn*32 + nt*8 + cl2) = lp;
                }
            }
    } else {
        #pragma unroll
        for (int mt = 0; mt < 2; mt++)
            #pragma unroll
            for (int h2 = 0; h2 < 2; h2++) {
                int gr = row0 + wm*32 + mt*16 + rl4 + h2*8;
                size_t base = (size_t)gr*INNER + h*DHD + d0;
                #pragma unroll
                for (int nt = 0; nt < 4; nt++) {
                    __nv_bfloat16 h0,l0,h1,l1;
                    split_bf16(acc[mt][nt][h2*2],   h0, l0);
                    split_bf16(acc[mt][nt][h2*2+1], h1, l1);
                    __nv_bfloat162 hp, lp;
                    hp.x = h0; hp.y = h1; lp.x = l0; lp.y = l1;
                    *(__nv_bfloat162*)(g_vh + base + wn*32 + nt*8 + cl2) = hp;
                    *(__nv_bfloat162*)(g_vl + base + wn*32 + nt*8 + cl2) = lp;
                }
            }
    }
}

// FF1: grid (8, 64); gelu epilogue -> fh/fl
__global__ __launch_bounds__(256) void k_ff1(
    const __nv_bfloat16* __restrict__ Ah, const __nv_bfloat16* __restrict__ Al,
    const __nv_bfloat16* __restrict__ Bh, const __nv_bfloat16* __restrict__ Bl,
    const float* __restrict__ bias)
{
    extern __shared__ __align__(16) char dsm[];
    __nv_bfloat16* sAh = (__nv_bfloat16*)dsm;
    __nv_bfloat16* sAl = sAh + 128*KP;
    __nv_bfloat16* sBh = sAl + 128*KP;
    __nv_bfloat16* sBl = sBh + 64*KP;
    const int t = threadIdx.x, w = t >> 5, lane = t & 31;
    const int wm = w & 3, wn = w >> 2;
    const int row0 = blockIdx.y*128, col0 = blockIdx.x*64;
    const int lrow = (lane & 15), lcol8 = (lane >> 4)*8;
    float acc[2][4][4] = {};

    MAINLOOP_64COL(sAh, sAl, sBh, sBl, Ah, Al, Bh, Bl, row0, col0, acc);

    const int rl4 = lane >> 2, cl2 = (lane & 3)*2;
    #pragma unroll
    for (int mt = 0; mt < 2; mt++)
        #pragma unroll
        for (int h2 = 0; h2 < 2; h2++) {
            int gr = row0 + wm*32 + mt*16 + rl4 + h2*8;
            #pragma unroll
            for (int nt = 0; nt < 4; nt++) {
                int gc = col0 + wn*32 + nt*8 + cl2;
                float v0 = gelu(acc[mt][nt][h2*2]   + bias[gc]);
                float v1 = gelu(acc[mt][nt][h2*2+1] + bias[gc+1]);
                __nv_bfloat16 h0,l0,h1,l1;
                split_bf16(v0,h0,l0); split_bf16(v1,h1,l1);
                __nv_bfloat162 hp, lp;
                hp.x = h0; hp.y = h1; lp.x = l0; lp.y = l1;
                *(__nv_bfloat162*)(g_fh + (size_t)gr*FFD + gc) = hp;
                *(__nv_bfloat162*)(g_fl + (size_t)gr*FFD + gc) = lp;
            }
        }
}

// ============ HMMA GEMM 64x128 tile, double-buffered (WO/FF2) — round-10 proven ============
#define SROW 72
#define BUFSZ (384*SROW)
__global__ __launch_bounds__(256) void k_mma64(
    const __nv_bfloat16* __restrict__ Ah, const __nv_bfloat16* __restrict__ Al, int lda,
    const __nv_bfloat16* __restrict__ Bh, const __nv_bfloat16* __restrict__ Bl,
    int Ktot,
    const float* __restrict__ bias,
    float* __restrict__ out)
{
    extern __shared__ __align__(16) __nv_bfloat16 sb[];
    const int t = threadIdx.x, w = t >> 5, lane = t & 31;
    const int wm = w & 1, wn = w >> 1;
    const int row0 = blockIdx.y*64;
    float acc[2][4][4] = {};
    const int lrow = (lane & 15), lcol8 = (lane >> 4)*8;

    {
        #pragma unroll
        for (int i = 0; i < 2; i++) {
            int f = i*256 + t;
            int r = f >> 3, c8 = (f & 7) << 3;
            *(uint4*)(sb + r*SROW + c8)            = *(const uint4*)(Ah + (size_t)(row0+r)*lda + c8);
            *(uint4*)(sb + 64*SROW + r*SROW + c8)  = *(const uint4*)(Al + (size_t)(row0+r)*lda + c8);
        }
        #pragma unroll
        for (int i = 0; i < 4; i++) {
            int f = i*256 + t;
            int r = f >> 3, c8 = (f & 7) << 3;
            *(uint4*)(sb + 128*SROW + r*SROW + c8) = *(const uint4*)(Bh + (size_t)r*Ktot + c8);
            *(uint4*)(sb + 256*SROW + r*SROW + c8) = *(const uint4*)(Bl + (size_t)r*Ktot + c8);
        }
    }
    __syncthreads();
    int buf = 0;

    for (int kc = 64; kc <= Ktot; kc += 64) {
        uint4 ra[2][2], rb[2][4];
        if (kc < Ktot) {
            #pragma unroll
            for (int i = 0; i < 2; i++) {
                int f = i*256 + t;
                int r = f >> 3, c8 = (f & 7) << 3;
                ra[0][i] = *(const uint4*)(Ah + (size_t)(row0+r)*lda + kc + c8);
                ra[1][i] = *(const uint4*)(Al + (size_t)(row0+r)*lda + kc + c8);
            }
            #pragma unroll
            for (int i = 0; i < 4; i++) {
                int f = i*256 + t;
                int r = f >> 3, c8 = (f & 7) << 3;
                rb[0][i] = *(const uint4*)(Bh + (size_t)r*Ktot + kc + c8);
                rb[1][i] = *(const uint4*)(Bl + (size_t)r*Ktot + kc + c8);
            }
        }
        const __nv_bfloat16* cb = sb + buf*BUFSZ;
        #pragma unroll
        for (int ks = 0; ks < 4; ks++) {
            int kcol = ks*16 + lcol8;
            uint32_t ah[2][4], al[2][4];
            #pragma unroll
            for (int mt = 0; mt < 2; mt++) {
                int arow = wm*32 + mt*16 + lrow;
                ldsm4(ah[mt], s2u(cb + arow*SROW + kcol));
                ldsm4(al[mt], s2u(cb + 64*SROW + arow*SROW + kcol));
            }
            #pragma unroll
            for (int nt2 = 0; nt2 < 2; nt2++) {
                int brow = wn*32 + nt2*16 + lrow;
                uint32_t rh[4], rl[4];
                ldsm4(rh, s2u(cb + 128*SROW + brow*SROW + kcol));
                ldsm4(rl, s2u(cb + 256*SROW + brow*SROW + kcol));
                uint32_t b0h[2] = {rh[0], rh[2]}, b1h[2] = {rh[1], rh[3]};
                uint32_t b0l[2] = {rl[0], rl[2]}, b1l[2] = {rl[1], rl[3]};
                #pragma unroll
                for (int mt = 0; mt < 2; mt++)
                    MMA3x2(acc[mt][nt2*2], acc[mt][nt2*2+1], ah[mt], al[mt], b0h, b0l, b1h, b1l);
            }
        }
        if (kc < Ktot) {
            __nv_bfloat16* nb = sb + (buf^1)*BUFSZ;
            #pragma unroll
            for (int i = 0; i < 2; i++) {
                int f = i*256 + t;
                int r = f >> 3, c8 = (f & 7) << 3;
                *(uint4*)(nb + r*SROW + c8)           = ra[0][i];
                *(uint4*)(nb + 64*SROW + r*SROW + c8) = ra[1][i];
            }
            #pragma unroll
            for (int i = 0; i < 4; i++) {
                int f = i*256 + t;
                int r = f >> 3, c8 = (f & 7) << 3;
                *(uint4*)(nb + 128*SROW + r*SROW + c8) = rb[0][i];
                *(uint4*)(nb + 256*SROW + r*SROW + c8) = rb[1][i];
            }
            __syncthreads();
            buf ^= 1;
        }
    }

    const int rl4 = lane >> 2, cl2 = (lane & 3)*2;
    #pragma unroll
    for (int mt = 0; mt < 2; mt++)
        #pragma unroll
        for (int h2 = 0; h2 < 2; h2++) {
            int gr = row0 + wm*32 + mt*16 + rl4 + h2*8;
            #pragma unroll
            for (int nt = 0; nt < 4; nt++) {
                int gc = wn*32 + nt*8 + cl2;
                size_t idx = (size_t)gr*DIMC + gc;
                float2 v = *(float2*)(out + idx);
                v.x += acc[mt][nt][h2*2]   + bias[gc];
                v.y += acc[mt][nt][h2*2+1] + bias[gc+1];
                *(float2*)(out + idx) = v;
            }
        }
}

// ---------------- embed ----------------
__global__ void k_embed(const float* __restrict__ x, const float* __restrict__ lw,
                        const float* __restrict__ lb, const float* __restrict__ pe)
{
    int warp = threadIdx.x >> 5, lane = threadIdx.x & 31;
    int r = blockIdx.x*8 + warp;
    float xv = x[r];
    float4 l4 = ((const float4*)lw)[lane];
    float4 b4 = ((const float4*)lb)[lane];
    float4 p4 = ((const float4*)(pe + (size_t)(r % SS)*DIMC))[lane];
    float4 o4 = { xv*l4.x + b4.x + p4.x, xv*l4.y + b4.y + p4.y,
                  xv*l4.z + b4.z + p4.z, xv*l4.w + b4.w + p4.w };
    ((float4*)(g_h + (size_t)r*DIMC))[lane] = o4;
}

// ---------------- layernorm -> bf16 hi/lo ----------------
__global__ void k_ln(const float* __restrict__ in, const float* __restrict__ g,
                     const float* __restrict__ b,
                     __nv_bfloat16* __restrict__ outH, __nv_bfloat16* __restrict__ outL)
{
    int warp = threadIdx.x >> 5, lane = threadIdx.x & 31;
    int r = blockIdx.x*8 + warp;
    float4 v = ((const float4*)(in + (size_t)r*DIMC))[lane];
    float s = v.x + v.y + v.z + v.w;
    #pragma unroll
    for (int o = 16; o > 0; o >>= 1) s += __shfl_xor_sync(0xffffffffu, s, o);
    float mu = s * (1.0f/DIMC);
    float dx = v.x-mu, dy = v.y-mu, dz = v.z-mu, dw = v.w-mu;
    float q = dx*dx + dy*dy + dz*dz + dw*dw;
    #pragma unroll
    for (int o = 16; o > 0; o >>= 1) q += __shfl_xor_sync(0xffffffffu, q, o);
    float inv = rsqrtf(q*(1.0f/DIMC) + 1e-5f);
    float4 gv = ((const float4*)g)[lane];
    float4 bv = ((const float4*)b)[lane];
    float o4[4] = { dx*inv*gv.x + bv.x, dy*inv*gv.y + bv.y,
                    dz*inv*gv.z + bv.z, dw*inv*gv.w + bv.w };
    __nv_bfloat16 hh[4], ll[4];
    #pragma unroll
    for (int j = 0; j < 4; j++) split_bf16(o4[j], hh[j], ll[j]);
    size_t base = (size_t)r*DIMC + lane*4;
    *(uint2*)(outH+base) = *(uint2*)hh;
    *(uint2*)(outL+base) = *(uint2*)ll;
}

// -------- unified weight prep: one launch, all weights, both layers --------
__global__ __launch_bounds__(256) void k_wprep(
    const float* __restrict__ wq, const float* __restrict__ wk,
    const float* __restrict__ wv, const float* __restrict__ wo,
    const float* __restrict__ ff1_w, const float* __restrict__ ff2_w,
    const float* __restrict__ proj)
{
    __shared__ float tile[32][33];
    int bid = blockIdx.x;
    int l = (bid >= 656) ? 1 : 0;
    bid -= l*656;
    size_t wb = (size_t)l*WT_LAYER;
    __nv_bfloat16* wth = g_wth + wb;
    __nv_bfloat16* wtl = g_wtl + wb;

    const float* W; __nv_bfloat16 *oH, *oL; int K, N, tidx;
    if (bid < 384) {
        int which = bid >> 7; tidx = bid & 127;
        W = (which == 0 ? wq : which == 1 ? wk : wv) + (size_t)l*DIMC*INNER;
        oH = wth + (which == 0 ? WT_Q : which == 1 ? WT_K : WT_V);
        oL = wtl + (which == 0 ? WT_Q : which == 1 ? WT_K : WT_V);
        K = DIMC; N = INNER;
    } else if (bid < 512) {
        tidx = bid - 384;
        W = wo + (size_t)l*INNER*DIMC;
        oH = wth + WT_O; oL = wtl + WT_O;
        K = INNER; N = DIMC;
    } else if (bid < 576) {
        tidx = bid - 512;
        W = ff1_w + (size_t)l*DIMC*FFD;
        oH = wth + WT_F1; oL = wtl + WT_F1;
        K = DIMC; N = FFD;
    } else if (bid < 640) {
        tidx = bid - 576;
        W = ff2_w + (size_t)l*FFD*DIMC;
        oH = wth + WT_F2; oL = wtl + WT_F2;
        K = FFD; N = DIMC;
    } else {
        int e4 = (bid - 640)*256 + threadIdx.x;
        float4 v = ((const float4*)(proj + (size_t)l*MF*DHD))[e4];
        __nv_bfloat16 hh[4], ll[4];
        split_bf16(v.x, hh[0], ll[0]); split_bf16(v.y, hh[1], ll[1]);
        split_bf16(v.z, hh[2], ll[2]); split_bf16(v.w, hh[3], ll[3]);
        *(uint2*)(wth + WT_PJ + e4*4) = *(uint2*)hh;
        *(uint2*)(wtl + WT_PJ + e4*4) = *(uint2*)ll;
        return;
    }
    int ntiles = N >> 5;
    int n0 = (tidx % ntiles)*32, k0 = (tidx / ntiles)*32;
    int tx = threadIdx.x & 31, ty = threadIdx.x >> 5;
    #pragma unroll
    for (int i = ty; i < 32; i += 8)
        tile[i][tx] = W[(size_t)(k0+i)*N + n0 + tx];
    __syncthreads();
    #pragma unroll
    for (int i = ty; i < 32; i += 8) {
        float v = tile[tx][i];
        __nv_bfloat16 hh, ll;
        split_bf16(v, hh, ll);
        oH[(size_t)(n0+i)*K + k0 + tx] = hh;
        oL[(size_t)(n0+i)*K + k0 + tx] = ll;
    }
}

// ================= chunk-local attention via HMMA, 512 threads =================
#define CP 136
__global__ __launch_bounds__(512) void k_chunk(
    const __nv_bfloat16* __restrict__ qph, const __nv_bfloat16* __restrict__ qpl)
{
    extern __shared__ __align__(16) __nv_bfloat16 cs[];
    __nv_bfloat16* sQh = cs;
    __nv_bfloat16* sQl = sQh + 128*CP;
    __nv_bfloat16* sKh = sQl + 128*CP;
    __nv_bfloat16* sKl = sKh + 128*CP;
    __nv_bfloat16* sVh = sKl + 128*CP;
    __nv_bfloat16* sVl = sVh + 128*CP;
    __shared__ float s_den[4][128];
    __shared__ float s_dg[128];

    int blk = blockIdx.x, bh = blk >> 4, c = blk & 15;
    int b = bh >> 3, hh = bh & 7;
    int t = threadIdx.x, w = t >> 5, lane = t & 31;
    int wm = w & 3, wn = w >> 2;
    const int lrow = lane & 15, lcol8 = (lane >> 4)*8;
    const int rl4 = lane >> 2, cl2 = (lane & 3)*2;

    const size_t qbase = ((size_t)bh*SS + c*CHUNK)*MF;
    if (t < 128) {
        float st = g_bmax[bh*16];
        #pragma unroll
        for (int i = 1; i < 16; i++) st = fmaxf(st, g_bmax[bh*16 + i]);
        s_dg[t] = g_diagk[(size_t)bh*SS + c*CHUNK + t] + st;
    }
    for (int i = t; i < 2048; i += 512) {
        int r = i >> 4, c8 = (i & 15) << 3;
        *(uint4*)(sQh + r*CP + c8) = *(const uint4*)(qph + qbase + r*MF + c8);
        *(uint4*)(sQl + r*CP + c8) = *(const uint4*)(qpl + qbase + r*MF + c8);
        size_t vsrc = (size_t)(b*SS + c*CHUNK + r)*INNER + hh*DHD + c8;
        *(uint4*)(sVh + r*CP + c8) = *(const uint4*)(g_vh + vsrc);
        *(uint4*)(sVl + r*CP + c8) = *(const uint4*)(g_vl + vsrc);
    }
    __syncthreads();
    for (int f = t; f < 4096; f += 512) {
        int r = f >> 5, c4 = (f & 31) << 2;
        float4 dv = *(const float4*)(g_kp + qbase + (size_t)r*MF + c4);
        float dgv = s_dg[r];
        float o0 = RATIOC*(expf(dv.x - dgv) + 1e-4f);
        float o1 = RATIOC*(expf(dv.y - dgv) + 1e-4f);
        float o2 = RATIOC*(expf(dv.z - dgv) + 1e-4f);
        float o3 = RATIOC*(expf(dv.w - dgv) + 1e-4f);
        __nv_bfloat16 hh4[4], ll4[4];
        split_bf16(o0, hh4[0], ll4[0]); split_bf16(o1, hh4[1], ll4[1]);
        split_bf16(o2, hh4[2], ll4[2]); split_bf16(o3, hh4[3], ll4[3]);
        *(uint2*)(sKh + r*CP + c4) = *(uint2*)hh4;
        *(uint2*)(sKl + r*CP + c4) = *(uint2*)ll4;
    }
    __syncthreads();

    float acc[2][4][4] = {};
    if (wn <= wm) {
        #pragma unroll
        for (int ks = 0; ks < 8; ks++) {
            int kcol = ks*16 + lcol8;
            uint32_t ah[2][4], al[2][4];
            #pragma unroll
            for (int mt = 0; mt < 2; mt++) {
                int arow = wm*32 + mt*16 + lrow;
                ldsm4(ah[mt], s2u(sQh + arow*CP + kcol));
                ldsm4(al[mt], s2u(sQl + arow*CP + kcol));
            }
            #pragma unroll
            for (int nt2 = 0; nt2 < 2; nt2++) {
                int brow = wn*32 + nt2*16 + lrow;
                uint32_t rh[4], rl[4];
                ldsm4(rh, s2u(sKh + brow*CP + kcol));
                ldsm4(rl, s2u(sKl + brow*CP + kcol));
                uint32_t b0h[2] = {rh[0], rh[2]}, b1h[2] = {rh[1], rh[3]};
                uint32_t b0l[2] = {rl[0], rl[2]}, b1l[2] = {rl[1], rl[3]};
                #pragma unroll
                for (int mt = 0; mt < 2; mt++)
                    MMA3x2(acc[mt][nt2*2], acc[mt][nt2*2+1], ah[mt], al[mt], b0h, b0l, b1h, b1l);
            }
        }
    }
    float dp[2][2] = {};
    #pragma unroll
    for (int mt = 0; mt < 2; mt++)
        #pragma unroll
        for (int nt = 0; nt < 4; nt++)
            #pragma unroll
            for (int f = 0; f < 4; f++) {
                int i = wm*32 + mt*16 + rl4 + ((f>>1)<<3);
                int j = wn*32 + nt*8 + cl2 + (f&1);
                if (j > i) acc[mt][nt][f] = 0.f;
                dp[mt][f>>1] += acc[mt][nt][f];
            }
    #pragma unroll
    for (int o = 1; o < 4; o <<= 1)
        #pragma unroll
        for (int mt = 0; mt < 2; mt++)
            #pragma unroll
            for (int h2 = 0; h2 < 2; h2++)
                dp[mt][h2] += __shfl_xor_sync(0xffffffffu, dp[mt][h2], o);
    if ((lane & 3) == 0) {
        #pragma unroll
        for (int mt = 0; mt < 2; mt++)
            #pragma unroll
            for (int h2 = 0; h2 < 2; h2++)
                s_den[wn][wm*32 + mt*16 + rl4 + h2*8] = dp[mt][h2];
    }
    __syncthreads();

    #pragma unroll
    for (int mt = 0; mt < 2; mt++)
        #pragma unroll
        for (int nt = 0; nt < 4; nt++)
            #pragma unroll
            for (int f = 0; f < 4; f++) {
                int i = wm*32 + mt*16 + rl4 + ((f>>1)<<3);
                int j = wn*32 + nt*8 + cl2 + (f&1);
                __nv_bfloat16 hh2, ll2;
                split_bf16(acc[mt][nt][f], hh2, ll2);
                sQh[i*CP + j] = hh2;
                sQl[i*CP + j] = ll2;
            }
    if (t < 128) {
        g_den[(size_t)bh*SS + c*CHUNK + t] = s_den[0][t] + s_den[1][t] + s_den[2][t] + s_den[3][t];
        float kssum = 0.f;
        for (int j = 0; j < 128; j++)
            kssum += __bfloat162float(sKh[j*CP + t]) + __bfloat162float(sKl[j*CP + t]);
        g_ksc[((size_t)bh*NC + c)*MF + t] = kssum;
    }
    __syncthreads();

    #pragma unroll
    for (int mt = 0; mt < 2; mt++)
        #pragma unroll
        for (int nt = 0; nt < 4; nt++)
            #pragma unroll
            for (int f = 0; f < 4; f++) acc[mt][nt][f] = 0.f;
    #pragma unroll
    for (int ks = 0; ks < 8; ks++) {
        int kcol = ks*16 + lcol8;
        uint32_t ah[2][4], al[2][4];
        #pragma unroll
        for (int mt = 0; mt < 2; mt++) {
            int arow = wm*32 + mt*16 + lrow;
            ldsm4(ah[mt], s2u(sQh + arow*CP + kcol));
            ldsm4(al[mt], s2u(sQl + arow*CP + kcol));
        }
        #pragma unroll
        for (int nt2 = 0; nt2 < 2; nt2++) {
            int nbase = wn*32 + nt2*16;
            uint32_t dh[4], dl[4];
            ldsm4t(dh, taddr(sVh, CP, ks*16, nbase, lane));
            ldsm4t(dl, taddr(sVl, CP, ks*16, nbase, lane));
            uint32_t b0h[2] = {dh[0], dh[2]}, b1h[2] = {dh[1], dh[3]};
            uint32_t b0l[2] = {dl[0], dl[2]}, b1l[2] = {dl[1], dl[3]};
            #pragma unroll
            for (int mt = 0; mt < 2; mt++)
                MMA3x2(acc[mt][nt2*2], acc[mt][nt2*2+1], ah[mt], al[mt], b0h, b0l, b1h, b1l);
        }
    }
    #pragma unroll
    for (int mt = 0; mt < 2; mt++)
        #pragma unroll
        for (int h2 = 0; h2 < 2; h2++) {
            int i = wm*32 + mt*16 + rl4 + h2*8;
            size_t base = ((size_t)(b*SS + c*CHUNK + i)*HH + hh)*DHD;
            #pragma unroll
            for (int nt = 0; nt < 4; nt++) {
                float2 vv = {acc[mt][nt][h2*2], acc[mt][nt][h2*2+1]};
                *(float2*)(g_o + base + wn*32 + nt*8 + cl2) = vv;
            }
        }

    #pragma unroll
    for (int mt = 0; mt < 2; mt++)
        #pragma unroll
        for (int nt = 0; nt < 4; nt++)
            #pragma unroll
            for (int f = 0; f < 4; f++) acc[mt][nt][f] = 0.f;
    #pragma unroll
    for (int ks = 0; ks < 8; ks++) {
        uint32_t ah[2][4], al[2][4];
        #pragma unroll
        for (int mt = 0; mt < 2; mt++) {
            int mbase = wm*32 + mt*16;
            ldsm4t(ah[mt], taddr(sKh, CP, ks*16, mbase, lane));
            ldsm4t(al[mt], taddr(sKl, CP, ks*16, mbase, lane));
        }
        #pragma unroll
        for (int nt2 = 0; nt2 < 2; nt2++) {
            int nbase = wn*32 + nt2*16;
            uint32_t dh[4], dl[4];
            ldsm4t(dh, taddr(sVh, CP, ks*16, nbase, lane));
            ldsm4t(dl, taddr(sVl, CP, ks*16, nbase, lane));
            uint32_t b0h[2] = {dh[0], dh[2]}, b1h[2] = {dh[1], dh[3]};
            uint32_t b0l[2] = {dl[0], dl[2]}, b1l[2] = {dl[1], dl[3]};
            #pragma unroll
            for (int mt = 0; mt < 2; mt++)
                MMA3x2(acc[mt][nt2*2], acc[mt][nt2*2+1], ah[mt], al[mt], b0h, b0l, b1h, b1l);
        }
    }
    {
        size_t kvbase = ((size_t)bh*NC + c)*(MF*DHD);
        #pragma unroll
        for (int mt = 0; mt < 2; mt++)
            #pragma unroll
            for (int h2 = 0; h2 < 2; h2++) {
                int m = wm*32 + mt*16 + rl4 + h2*8;
                #pragma unroll
                for (int nt = 0; nt < 4; nt++) {
                    float2 vv = {acc[mt][nt][h2*2], acc[mt][nt][h2*2+1]};
                    *(float2*)(g_kvc + kvbase + (size_t)m*DHD + wn*32 + nt*8 + cl2) = vv;
                }
            }
    }
}

// ---------------- exclusive prefix over chunks (emits bf16 hi/lo) ----------------
__global__ void k_prefix()
{
    int bh = blockIdx.x, seg = blockIdx.y, t = threadIdx.x;
    for (int e = seg*2048 + t; e < (seg+1)*2048; e += 256) {
        float run = 0.f;
        #pragma unroll
        for (int c = 0; c < NC; c++) {
            size_t idx = ((size_t)bh*NC + c)*(MF*DHD) + e;
            __nv_bfloat16 hh, ll;
            split_bf16(run, hh, ll);
            g_kvph[idx] = hh; g_kvpl[idx] = ll;
            run += g_kvc[idx];
        }
    }
    if (seg == 0) {
        for (int e = t; e < MF; e += 256) {
            float run = 0.f;
            #pragma unroll
            for (int c = 0; c < NC; c++) {
                size_t idx = ((size_t)bh*NC + c)*MF + e;
                g_ksp[idx] = run; run += g_ksc[idx];
            }
        }
    }
}

// ========== cross = qp @ kvp, + num, normalize -> oh/ol (HMMA, 512 thr) ==========
__global__ __launch_bounds__(512) void k_cross(
    const __nv_bfloat16* __restrict__ qph, const __nv_bfloat16* __restrict__ qpl)
{
    extern __shared__ __align__(16) __nv_bfloat16 cs[];
    __nv_bfloat16* sQh = cs;
    __nv_bfloat16* sQl = sQh + 128*CP;
    __nv_bfloat16* sPh = sQl + 128*CP;
    __nv_bfloat16* sPl = sPh + 128*CP;
    __shared__ float s_ks[128];
    __shared__ float s_dc[128];

    int blk = blockIdx.x, bh = blk >> 4, c = blk & 15;
    int b = bh >> 3, hh = bh & 7;
    int t = threadIdx.x, w = t >> 5, lane = t & 31;
    int wm = w & 3, wn = w >> 2;
    const int lrow = lane & 15, lcol8 = (lane >> 4)*8;
    const int rl4 = lane >> 2, cl2 = (lane & 3)*2;

    const size_t qbase = ((size_t)bh*SS + c*CHUNK)*MF;
    const size_t pbase = ((size_t)bh*NC + c)*(MF*DHD);
    for (int i = t; i < 2048; i += 512) {
        int r = i >> 4, c8 = (i & 15) << 3;
        *(uint4*)(sQh + r*CP + c8) = *(const uint4*)(qph + qbase + r*MF + c8);
        *(uint4*)(sQl + r*CP + c8) = *(const uint4*)(qpl + qbase + r*MF + c8);
        *(uint4*)(sPh + r*CP + c8) = *(const uint4*)(g_kvph + pbase + r*DHD + c8);
        *(uint4*)(sPl + r*CP + c8) = *(const uint4*)(g_kvpl + pbase + r*DHD + c8);
    }
    if (t < 128) s_ks[t] = g_ksp[((size_t)bh*NC + c)*MF + t];
    __syncthreads();
    if (t < 128) {
        float dc = 0.f;
        for (int m = 0; m < 128; m++)
            dc += (__bfloat162float(sQh[t*CP + m]) + __bfloat162float(sQl[t*CP + m]))*s_ks[m];
        s_dc[t] = g_den[(size_t)bh*SS + c*CHUNK + t] + dc + 1e-6f;
    }
    __syncthreads();

    float acc[2][4][4] = {};
    #pragma unroll
    for (int ks = 0; ks < 8; ks++) {
        int kcol = ks*16 + lcol8;
        uint32_t ah[2][4], al[2][4];
        #pragma unroll
        for (int mt = 0; mt < 2; mt++) {
            int arow = wm*32 + mt*16 + lrow;
            ldsm4(ah[mt], s2u(sQh + arow*CP + kcol));
            ldsm4(al[mt], s2u(sQl + arow*CP + kcol));
        }
        #pragma unroll
        for (int nt2 = 0; nt2 < 2; nt2++) {
            int nbase = wn*32 + nt2*16;
            uint32_t dh[4], dl[4];
            ldsm4t(dh, taddr(sPh, CP, ks*16, nbase, lane));
            ldsm4t(dl, taddr(sPl, CP, ks*16, nbase, lane));
            uint32_t b0h[2] = {dh[0], dh[2]}, b1h[2] = {dh[1], dh[3]};
            uint32_t b0l[2] = {dl[0], dl[2]}, b1l[2] = {dl[1], dl[3]};
            #pragma unroll
            for (int mt = 0; mt < 2; mt++)
                MMA3x2(acc[mt][nt2*2], acc[mt][nt2*2+1], ah[mt], al[mt], b0h, b0l, b1h, b1l);
        }
    }
    #pragma unroll
    for (int mt = 0; mt < 2; mt++)
        #pragma unroll
        for (int h2 = 0; h2 < 2; h2++) {
            int i = wm*32 + mt*16 + rl4 + h2*8;
            float inv = 1.0f / s_dc[i];
            size_t base = ((size_t)(b*SS + c*CHUNK + i)*HH + hh)*DHD;
            #pragma unroll
            for (int nt = 0; nt < 4; nt++) {
                size_t idx = base + wn*32 + nt*8 + cl2;
                float2 nn = *(float2*)(g_o + idx);
                float v0 = (nn.x + acc[mt][nt][h2*2])   * inv;
                float v1 = (nn.y + acc[mt][nt][h2*2+1]) * inv;
                __nv_bfloat16 h0,l0,h1,l1;
                split_bf16(v0,h0,l0); split_bf16(v1,h1,l1);
                __nv_bfloat162 hp, lp;
                hp.x = h0; hp.y = h1; lp.x = l0; lp.y = l1;
                *(__nv_bfloat162*)(g_oh + idx) = hp;
                *(__nv_bfloat162*)(g_ol + idx) = lp;
            }
        }
}

// ---------------- pooling ----------------
__global__ void k_pool()
{
    int b = blockIdx.x, seg = blockIdx.y, t = threadIdx.x;
    float acc = 0.f;
    for (int s = seg*128; s < (seg+1)*128; s++) acc += g_h[((size_t)b*SS + s)*DIMC + t];
    g_pp[(b*16 + seg)*DIMC + t] = acc;
}

__global__ void k_final(const float* __restrict__ fw, const float* __restrict__ fb,
                        float* __restrict__ out)
{
    __shared__ float pooled[BB*DIMC];
    int t = threadIdx.x;
    for (int b = 0; b < BB; b++) {
        float a = 0.f;
        #pragma unroll
        for (int s = 0; s < 16; s++) a += g_pp[(b*16 + s)*DIMC + t];
        pooled[b*DIMC + t] = a * (1.0f/SS);
    }
    __syncthreads();
    if (t < BB*NCLS) {
        int b = t / NCLS, c = t % NCLS;
        float acc = fb[c];
        for (int d = 0; d < DIMC; d++) acc += pooled[b*DIMC + d]*fw[d*NCLS + c];
        out[t] = acc;
    }
}

// ---------------- host driver ----------------
static void* sym(const void* s) { void* p = nullptr; cudaGetSymbolAddress(&p, s); return p; }

extern "C" void kernel_launch(void* const* d_in, const int* in_sizes, int n_in,
                              void* d_out, int out_size)
{
    const float* x     = (const float*)d_in[0];
    const float* lin_w = (const float*)d_in[1];
    const float* lin_b = (const float*)d_in[2];
    const float* pe    = (const float*)d_in[3];
    const float* proj  = (const float*)d_in[4];
    const float* ln1_g = (const float*)d_in[5];
    const float* ln1_b = (const float*)d_in[6];
    const float* wq    = (const float*)d_in[7];
    const float* wk    = (const float*)d_in[8];
    const float* wv    = (const float*)d_in[9];
    const float* wo    = (const float*)d_in[10];
    const float* wo_b  = (const float*)d_in[11];
    const float* ln2_g = (const float*)d_in[12];
    const float* ln2_b = (const float*)d_in[13];
    const float* ff1_w = (const float*)d_in[14];
    const float* ff1_b = (const float*)d_in[15];
    const float* ff2_w = (const float*)d_in[16];
    const float* ff2_b = (const float*)d_in[17];
    const float* fin_w = (const float*)d_in[18];
    const float* fin_b = (const float*)d_in[19];
    float* out = (float*)d_out;

    float* ph   = (float*)sym(g_h);
    float* pkp  = (float*)sym(g_kp);
    float* pbm  = (float*)sym(g_bmax);

    __nv_bfloat16* yh  = (__nv_bfloat16*)sym(g_yh);
    __nv_bfloat16* yl  = (__nv_bfloat16*)sym(g_yl);
    __nv_bfloat16* wth = (__nv_bfloat16*)sym(g_wth);
    __nv_bfloat16* wtl = (__nv_bfloat16*)sym(g_wtl);
    __nv_bfloat16* qnh = (__nv_bfloat16*)sym(g_qnh);
    __nv_bfloat16* qnl = (__nv_bfloat16*)sym(g_qnl);
    __nv_bfloat16* knh = (__nv_bfloat16*)sym(g_knh);
    __nv_bfloat16* knl = (__nv_bfloat16*)sym(g_knl);
    __nv_bfloat16* qp_h = (__nv_bfloat16*)sym(g_qph);
    __nv_bfloat16* qp_l = (__nv_bfloat16*)sym(g_qpl);
    __nv_bfloat16* oh  = (__nv_bfloat16*)sym(g_oh);
    __nv_bfloat16* ol  = (__nv_bfloat16*)sym(g_ol);
    __nv_bfloat16* fh  = (__nv_bfloat16*)sym(g_fh);
    __nv_bfloat16* fl  = (__nv_bfloat16*)sym(g_fl);

    const int SMEM_MMA   = 4*128*KP*2;           // 139264 (features, single-stage)
    const int SMEM_QKVFF = QKV_SMEM;             // 104448 (2 CTAs/SM)
    const int SMEM_MMA64 = 2*BUFSZ*2;            // 110592 (round-10 proven)
    const int SMEM_CHUNK = 6*128*CP*2;           // 208896
    const int SMEM_CROSS = 4*128*CP*2;           // 139264
    cudaFuncSetAttribute(k_mmaF, cudaFuncAttributeMaxDynamicSharedMemorySize, SMEM_MMA);
    cudaFuncSetAttribute(k_mmaqkv64, cudaFuncAttributeMaxDynamicSharedMemorySize, SMEM_QKVFF);
    cudaFuncSetAttribute(k_ff1, cudaFuncAttributeMaxDynamicSharedMemorySize, SMEM_QKVFF);
    cudaFuncSetAttribute(k_mma64, cudaFuncAttributeMaxDynamicSharedMemorySize, SMEM_MMA64);
    cudaFuncSetAttribute(k_chunk, cudaFuncAttributeMaxDynamicSharedMemorySize, SMEM_CHUNK);
    cudaFuncSetAttribute(k_cross, cudaFuncAttributeMaxDynamicSharedMemorySize, SMEM_CROSS);

    // bigger prep first; embed fills its tail wave
    k_wprep<<<2*656, 256>>>(wq, wk, wv, wo, ff1_w, ff2_w, proj);
    k_embed<<<BSR/8, 256>>>(x, lin_w, lin_b, pe);

    for (int l = 0; l < DEPTH; l++) {
        size_t wb = (size_t)l*WT_LAYER;

        k_ln<<<BSR/8, 256>>>(ph, ln1_g + l*DIMC, ln1_b + l*DIMC, yh, yl);

        k_mmaqkv64<<<dim3(48,64), 256, SMEM_QKVFF>>>(yh, yl, wth+wb+WT_Q, wtl+wb+WT_Q);

        k_mmaF<<<dim3(2,512), 256, SMEM_MMA>>>(knh, knl, qnh, qnl,
                                               wth+wb+WT_PJ, wtl+wb+WT_PJ,
                                               pkp, qp_h, qp_l, pbm);

        k_chunk<<<NBH*NC, 512, SMEM_CHUNK>>>(qp_h, qp_l);
        k_prefix<<<dim3(NBH, 8), 256>>>();
        k_cross<<<NBH*NC, 512, SMEM_CROSS>>>(qp_h, qp_l);

        k_mma64<<<dim3(1,BSR/64), 256, SMEM_MMA64>>>(oh, ol, INNER, wth+wb+WT_O, wtl+wb+WT_O, INNER,
                                                     wo_b + l*DIMC, ph);

        k_ln<<<BSR/8, 256>>>(ph, ln2_g + l*DIMC, ln2_b + l*DIMC, yh, yl);
        k_ff1<<<dim3(8,64), 256, SMEM_QKVFF>>>(yh, yl, wth+wb+WT_F1, wtl+wb+WT_F1, ff1_b + l*FFD);
        k_mma64<<<dim3(1,BSR/64), 256, SMEM_MMA64>>>(fh, fl, FFD, wth+wb+WT_F2, wtl+wb+WT_F2, FFD,
                                                     ff2_b + l*DIMC, ph);
    }

    k_pool<<<dim3(BB, 16), 128>>>();
    k_final<<<1, 128>>>(fin_w, fin_b, out);
}

// round 15
// speedup vs baseline: 1.1252x; 1.1029x over previous
#include <cuda_runtime.h>
#include <cuda_bf16.h>
#include <math.h>
#include <stdint.h>

// ---------------- problem constants ----------------
#define BB 4
#define SS 2048
#define DIMC 128
#define HH 8
#define DHD 128
#define DEPTH 2
#define NCLS 10
#define MF 128
#define CHUNK 128
#define NC 16
#define INNER 1024
#define FFD 512
#define BSR 8192
#define BHS 65536
#define NBH 32

#define NORMC 0.29730177875068026f
#define RATIOC 0.08838834764831845f

// ---------------- device scratch (fp32) ----------------
__device__ float g_h  [BSR*DIMC];
__device__ float g_kp [(size_t)NBH*SS*MF];
__device__ float g_diagk[BHS];
__device__ float g_bmax[NBH*16];
__device__ float g_o  [BSR*INNER];
__device__ float g_den[BHS];
__device__ float g_kvc[(size_t)NBH*NC*MF*DHD];
__device__ float g_ksc[NBH*NC*MF];
__device__ float g_ksp[NBH*NC*MF];
__device__ float g_pp [BB*16*DIMC];

// ---------------- device scratch (bf16) ----------------
__device__ __align__(256) __nv_bfloat16 g_yh [BSR*DIMC];
__device__ __align__(256) __nv_bfloat16 g_yl [BSR*DIMC];
__device__ __align__(256) __nv_bfloat16 g_wth[2*672000];
__device__ __align__(256) __nv_bfloat16 g_wtl[2*672000];
__device__ __align__(256) __nv_bfloat16 g_qnh[(size_t)BHS*DHD];
__device__ __align__(256) __nv_bfloat16 g_qnl[(size_t)BHS*DHD];
__device__ __align__(256) __nv_bfloat16 g_knh[(size_t)BHS*DHD];
__device__ __align__(256) __nv_bfloat16 g_knl[(size_t)BHS*DHD];
__device__ __align__(256) __nv_bfloat16 g_vh [(size_t)BSR*INNER];   // V: single bf16
__device__ __align__(256) __nv_bfloat16 g_qph[(size_t)NBH*SS*MF];
__device__ __align__(256) __nv_bfloat16 g_qpl[(size_t)NBH*SS*MF];
__device__ __align__(256) __nv_bfloat16 g_kvph[(size_t)NBH*NC*MF*DHD];  // kvp: single bf16
__device__ __align__(256) __nv_bfloat16 g_oh [(size_t)BSR*INNER];
__device__ __align__(256) __nv_bfloat16 g_ol [(size_t)BSR*INNER];
__device__ __align__(256) __nv_bfloat16 g_fh [(size_t)BSR*FFD];
__device__ __align__(256) __nv_bfloat16 g_fl [(size_t)BSR*FFD];

#define WT_Q  0
#define WT_K  131072
#define WT_V  262144
#define WT_O  393216
#define WT_F1 524288
#define WT_F2 589824
#define WT_PJ 655360
#define WT_LAYER 672000

// ---------------- warp MMA helpers ----------------
__device__ __forceinline__ uint32_t s2u(const void* p){
    uint32_t a;
    asm("{ .reg .u64 t; cvta.to.shared.u64 t, %1; cvt.u32.u64 %0, t; }" : "=r"(a) : "l"(p));
    return a;
}
__device__ __forceinline__ void ldsm4(uint32_t* r, uint32_t addr){
    asm volatile("ldmatrix.sync.aligned.m8n8.x4.shared.b16 {%0,%1,%2,%3}, [%4];"
                 : "=r"(r[0]),"=r"(r[1]),"=r"(r[2]),"=r"(r[3]) : "r"(addr));
}
__device__ __forceinline__ void ldsm4t(uint32_t* r, uint32_t addr){
    asm volatile("ldmatrix.sync.aligned.m8n8.x4.trans.shared.b16 {%0,%1,%2,%3}, [%4];"
                 : "=r"(r[0]),"=r"(r[1]),"=r"(r[2]),"=r"(r[3]) : "r"(addr));
}
__device__ __forceinline__ void mma_bf16(float* c, const uint32_t* a, const uint32_t* b){
    asm volatile("mma.sync.aligned.m16n8k16.row.col.f32.bf16.bf16.f32 "
                 "{%0,%1,%2,%3}, {%4,%5,%6,%7}, {%8,%9}, {%0,%1,%2,%3};"
                 : "+f"(c[0]),"+f"(c[1]),"+f"(c[2]),"+f"(c[3])
                 : "r"(a[0]),"r"(a[1]),"r"(a[2]),"r"(a[3]), "r"(b[0]),"r"(b[1]));
}
__device__ __forceinline__ void split_bf16(float v, __nv_bfloat16& h, __nv_bfloat16& l){
    h = __float2bfloat16(v);
    l = __float2bfloat16(v - __bfloat162float(h));
}
__device__ __forceinline__ float gelu(float xx){
    return 0.5f*xx*(1.0f + tanhf(0.7978845608028654f*(xx + 0.044715f*xx*xx*xx)));
}
__device__ __forceinline__ uint32_t taddr(const __nv_bfloat16* S, int P, int kbase, int nbase, int lane){
    int kk = (lane & 7) + ((lane >> 4) << 3);
    int nn = ((lane >> 3) & 1) << 3;
    return s2u(S + (size_t)(kbase + kk)*P + nbase + nn);
}
#define MMA3x2(accA, accB, ah_, al_, b0h_, b0l_, b1h_, b1l_) \
    do { mma_bf16(accA, ah_, b0h_); mma_bf16(accA, ah_, b0l_); mma_bf16(accA, al_, b0h_); \
         mma_bf16(accB, ah_, b1h_); mma_bf16(accB, ah_, b1l_); mma_bf16(accB, al_, b1h_); } while(0)
// A hi/lo vs single-precision B
#define MMA2x2(accA, accB, ah_, al_, b0_, b1_) \
    do { mma_bf16(accA, ah_, b0_); mma_bf16(accA, al_, b0_); \
         mma_bf16(accB, ah_, b1_); mma_bf16(accB, al_, b1_); } while(0)

#define KP 136

// ======== merged feature GEMM (single-stage K=128):
// blockIdx.x==0 -> K features (dd+bmax+diag); ==1 -> Q features (exp -> qp hi/lo)
__global__ __launch_bounds__(256) void k_mmaF(
    const __nv_bfloat16* __restrict__ Kh, const __nv_bfloat16* __restrict__ Kl,
    const __nv_bfloat16* __restrict__ Qh, const __nv_bfloat16* __restrict__ Ql,
    const __nv_bfloat16* __restrict__ Bh, const __nv_bfloat16* __restrict__ Bl,
    float* __restrict__ out,
    __nv_bfloat16* __restrict__ outH, __nv_bfloat16* __restrict__ outL,
    float* __restrict__ bmax)
{
    extern __shared__ __align__(16) char dsm[];
    __nv_bfloat16* sAh = (__nv_bfloat16*)dsm;
    __nv_bfloat16* sAl = sAh + 128*KP;
    __nv_bfloat16* sBh = sAl + 128*KP;
    __nv_bfloat16* sBl = sBh + 128*KP;
    __shared__ float s_rm[2][128];
    __shared__ float s_red[256];
    __shared__ float s_dg[128];

    const int MODE = (blockIdx.x == 0) ? 4 : 3;
    const __nv_bfloat16* Ah = (MODE == 4) ? Kh : Qh;
    const __nv_bfloat16* Al = (MODE == 4) ? Kl : Ql;

    const int t = threadIdx.x, w = t >> 5, lane = t & 31;
    const int wm = w & 3, wn = w >> 2;
    const int row0 = blockIdx.y*128;

    float acc[2][8][4] = {};
    const int lrow = (lane & 15), lcol8 = (lane >> 4)*8;

    #pragma unroll
    for (int i = 0; i < 8; i++) {
        int f = i*256 + t;
        int r = f >> 4, c8 = (f & 15) << 3;
        *(uint4*)(sAh + r*KP + c8) = *(const uint4*)(Ah + (size_t)(row0+r)*128 + c8);
        *(uint4*)(sAl + r*KP + c8) = *(const uint4*)(Al + (size_t)(row0+r)*128 + c8);
        *(uint4*)(sBh + r*KP + c8) = *(const uint4*)(Bh + (size_t)r*128 + c8);
        *(uint4*)(sBl + r*KP + c8) = *(const uint4*)(Bl + (size_t)r*128 + c8);
    }
    __syncthreads();

    if (t < 128) {
        float dacc = 0.f;
        #pragma unroll
        for (int k8 = 0; k8 < 16; k8++) {
            uint4 uh = *(uint4*)(sAh + t*KP + k8*8);
            uint4 ul = *(uint4*)(sAl + t*KP + k8*8);
            const __nv_bfloat16* ph = (const __nv_bfloat16*)&uh;
            const __nv_bfloat16* pl = (const __nv_bfloat16*)&ul;
            #pragma unroll
            for (int j = 0; j < 8; j++) {
                float av = __bfloat162float(ph[j]) + __bfloat162float(pl[j]);
                dacc += av*av;
            }
        }
        if (MODE == 4) g_diagk[row0 + t] = 0.5f*dacc;
        else           s_dg[t] = 0.5f*dacc;
    }

    #pragma unroll
    for (int ks = 0; ks < 8; ks++) {
        int kcol = ks*16 + lcol8;
        uint32_t ah[2][4], al[2][4];
        #pragma unroll
        for (int mt = 0; mt < 2; mt++) {
            int arow = wm*32 + mt*16 + lrow;
            ldsm4(ah[mt], s2u(sAh + arow*KP + kcol));
            ldsm4(al[mt], s2u(sAl + arow*KP + kcol));
        }
        #pragma unroll
        for (int nt2 = 0; nt2 < 4; nt2++) {
            int brow = wn*64 + nt2*16 + lrow;
            uint32_t rh[4], rl[4];
            ldsm4(rh, s2u(sBh + brow*KP + kcol));
            ldsm4(rl, s2u(sBl + brow*KP + kcol));
            uint32_t b0h[2] = {rh[0], rh[2]}, b1h[2] = {rh[1], rh[3]};
            uint32_t b0l[2] = {rl[0], rl[2]}, b1l[2] = {rl[1], rl[3]};
            #pragma unroll
            for (int mt = 0; mt < 2; mt++)
                MMA3x2(acc[mt][nt2*2], acc[mt][nt2*2+1], ah[mt], al[mt], b0h, b0l, b1h, b1l);
        }
    }

    const int rl4 = lane >> 2, cl2 = (lane & 3)*2;

    if (MODE == 4) {
        float bm = -1e30f;
        #pragma unroll
        for (int mt = 0; mt < 2; mt++)
            #pragma unroll
            for (int h = 0; h < 2; h++) {
                int gr = row0 + wm*32 + mt*16 + rl4 + h*8;
                #pragma unroll
                for (int nt = 0; nt < 8; nt++) {
                    float2 v = {acc[mt][nt][h*2], acc[mt][nt][h*2+1]};
                    *(float2*)(out + (size_t)gr*MF + wn*64 + nt*8 + cl2) = v;
                    bm = fmaxf(bm, fmaxf(v.x, v.y));
                }
            }
        s_red[t] = bm; __syncthreads();
        #pragma unroll
        for (int o = 128; o > 0; o >>= 1) { if (t < o) s_red[t] = fmaxf(s_red[t], s_red[t+o]); __syncthreads(); }
        if (t == 0) bmax[blockIdx.y] = s_red[0];
    } else {
        float rm[2][2];
        #pragma unroll
        for (int mt = 0; mt < 2; mt++)
            #pragma unroll
            for (int h = 0; h < 2; h++) {
                float m = -1e30f;
                #pragma unroll
                for (int nt = 0; nt < 8; nt++)
                    m = fmaxf(m, fmaxf(acc[mt][nt][h*2], acc[mt][nt][h*2+1]));
                m = fmaxf(m, __shfl_xor_sync(0xffffffffu, m, 1));
                m = fmaxf(m, __shfl_xor_sync(0xffffffffu, m, 2));
                rm[mt][h] = m;
            }
        if ((lane & 3) == 0) {
            #pragma unroll
            for (int mt = 0; mt < 2; mt++)
                #pragma unroll
                for (int h = 0; h < 2; h++)
                    s_rm[wn][wm*32 + mt*16 + rl4 + h*8] = rm[mt][h];
        }
        __syncthreads();
        #pragma unroll
        for (int mt = 0; mt < 2; mt++)
            #pragma unroll
            for (int h = 0; h < 2; h++) {
                int lr = wm*32 + mt*16 + rl4 + h*8;
                int gr = row0 + lr;
                float rmax = fmaxf(s_rm[0][lr], s_rm[1][lr]);
                float dg = s_dg[lr];
                #pragma unroll
                for (int nt = 0; nt < 8; nt++) {
                    int gc = wn*64 + nt*8 + cl2;
                    float v0 = RATIOC*(expf(acc[mt][nt][h*2]  -dg-rmax) + 1e-4f);
                    float v1 = RATIOC*(expf(acc[mt][nt][h*2+1]-dg-rmax) + 1e-4f);
                    __nv_bfloat16 h0,l0,h1,l1;
                    split_bf16(v0,h0,l0); split_bf16(v1,h1,l1);
                    __nv_bfloat162 hp, lp;
                    hp.x = h0; hp.y = h1; lp.x = l0; lp.y = l1;
                    *(__nv_bfloat162*)(outH + (size_t)gr*MF + gc) = hp;
                    *(__nv_bfloat162*)(outL + (size_t)gr*MF + gc) = lp;
                }
            }
    }
}

// ======== 128x64-tile K=128 mainloop (2 CTAs/SM) — shared by QKV and FF1 ========
#define QKV_SMEM ((2*128 + 2*64)*KP*2)
#define MAINLOOP_64COL(sAh, sAl, sBh, sBl, Ah, Al, Bh, Bl, row0, col0, acc) \
    {   \
        _Pragma("unroll")                                                        \
        for (int i = 0; i < 8; i++) {                                            \
            int f = i*256 + threadIdx.x;                                         \
            int r = f >> 4, c8 = (f & 15) << 3;                                  \
            *(uint4*)(sAh + r*KP + c8) = *(const uint4*)(Ah + (size_t)(row0+r)*128 + c8); \
            *(uint4*)(sAl + r*KP + c8) = *(const uint4*)(Al + (size_t)(row0+r)*128 + c8); \
        }                                                                        \
        _Pragma("unroll")                                                        \
        for (int i = 0; i < 4; i++) {                                            \
            int f = i*256 + threadIdx.x;                                         \
            int r = f >> 4, c8 = (f & 15) << 3;                                  \
            *(uint4*)(sBh + r*KP + c8) = *(const uint4*)(Bh + (size_t)(col0+r)*128 + c8); \
            *(uint4*)(sBl + r*KP + c8) = *(const uint4*)(Bl + (size_t)(col0+r)*128 + c8); \
        }                                                                        \
        __syncthreads();                                                         \
        _Pragma("unroll")                                                        \
        for (int ks = 0; ks < 8; ks++) {                                         \
            int kcol = ks*16 + lcol8;                                            \
            uint32_t ah[2][4], al[2][4];                                         \
            _Pragma("unroll")                                                    \
            for (int mt = 0; mt < 2; mt++) {                                     \
                int arow = wm*32 + mt*16 + lrow;                                 \
                ldsm4(ah[mt], s2u(sAh + arow*KP + kcol));                        \
                ldsm4(al[mt], s2u(sAl + arow*KP + kcol));                        \
            }                                                                    \
            _Pragma("unroll")                                                    \
            for (int nt2 = 0; nt2 < 2; nt2++) {                                  \
                int brow = wn*32 + nt2*16 + lrow;                                \
                uint32_t rh[4], rl[4];                                           \
                ldsm4(rh, s2u(sBh + brow*KP + kcol));                            \
                ldsm4(rl, s2u(sBl + brow*KP + kcol));                            \
                uint32_t b0h[2] = {rh[0], rh[2]}, b1h[2] = {rh[1], rh[3]};       \
                uint32_t b0l[2] = {rl[0], rl[2]}, b1l[2] = {rl[1], rl[3]};       \
                _Pragma("unroll")                                                \
                for (int mt = 0; mt < 2; mt++)                                   \
                    MMA3x2(acc[mt][nt2*2], acc[mt][nt2*2+1], ah[mt], al[mt], b0h, b0l, b1h, b1l); \
            }                                                                    \
        }                                                                        \
    }

// QKV: grid (48, 64); epilogue scatters per part/head; V single bf16
__global__ __launch_bounds__(256) void k_mmaqkv64(
    const __nv_bfloat16* __restrict__ Ah, const __nv_bfloat16* __restrict__ Al,
    const __nv_bfloat16* __restrict__ Bh, const __nv_bfloat16* __restrict__ Bl)
{
    extern __shared__ __align__(16) char dsm[];
    __nv_bfloat16* sAh = (__nv_bfloat16*)dsm;
    __nv_bfloat16* sAl = sAh + 128*KP;
    __nv_bfloat16* sBh = sAl + 128*KP;
    __nv_bfloat16* sBl = sBh + 64*KP;
    const int t = threadIdx.x, w = t >> 5, lane = t & 31;
    const int wm = w & 3, wn = w >> 2;
    const int row0 = blockIdx.y*128, col0 = blockIdx.x*64;
    const int lrow = (lane & 15), lcol8 = (lane >> 4)*8;
    float acc[2][4][4] = {};

    MAINLOOP_64COL(sAh, sAl, sBh, sBl, Ah, Al, Bh, Bl, row0, col0, acc);

    const int rl4 = lane >> 2, cl2 = (lane & 3)*2;
    const int part = col0 >> 10;
    const int h = (col0 >> 7) & 7;
    const int d0 = col0 & 127;

    if (part < 2) {
        __nv_bfloat16* dH = part ? g_knh : g_qnh;
        __nv_bfloat16* dL = part ? g_knl : g_qnl;
        #pragma unroll
        for (int mt = 0; mt < 2; mt++)
            #pragma unroll
            for (int h2 = 0; h2 < 2; h2++) {
                int gr = row0 + wm*32 + mt*16 + rl4 + h2*8;
                int b = gr >> 11, s = gr & 2047;
                size_t base = ((size_t)(b*HH + h)*SS + s)*DHD + d0;
                #pragma unroll
                for (int nt = 0; nt < 4; nt++) {
                    float v0 = acc[mt][nt][h2*2]   * NORMC;
                    float v1 = acc[mt][nt][h2*2+1] * NORMC;
                    __nv_bfloat16 h0,l0,h1,l1;
                    split_bf16(v0,h0,l0); split_bf16(v1,h1,l1);
                    __nv_bfloat162 hp, lp;
                    hp.x = h0; hp.y = h1; lp.x = l0; lp.y = l1;
                    *(__nv_bfloat162*)(dH + base + wn*32 + nt*8 + cl2) = hp;
                    *(__nv_bfloat162*)(dL + base + wn*32 + nt*8 + cl2) = lp;
                }
            }
    } else {
        #pragma unroll
        for (int mt = 0; mt < 2; mt++)
            #pragma unroll
            for (int h2 = 0; h2 < 2; h2++) {
                int gr = row0 + wm*32 + mt*16 + rl4 + h2*8;
                size_t base = (size_t)gr*INNER + h*DHD + d0;
                #pragma unroll
                for (int nt = 0; nt < 4; nt++) {
                    __nv_bfloat162 hp;
                    hp.x = __float2bfloat16(acc[mt][nt][h2*2]);
                    hp.y = __float2bfloat16(acc[mt][nt][h2*2+1]);
                    *(__nv_bfloat162*)(g_vh + base + wn*32 + nt*8 + cl2) = hp;
                }
            }
    }
}

// FF1: grid (8, 64); gelu epilogue -> fh/fl
__global__ __launch_bounds__(256) void k_ff1(
    const __nv_bfloat16* __restrict__ Ah, const __nv_bfloat16* __restrict__ Al,
    const __nv_bfloat16* __restrict__ Bh, const __nv_bfloat16* __restrict__ Bl,
    const float* __restrict__ bias)
{
    extern __shared__ __align__(16) char dsm[];
    __nv_bfloat16* sAh = (__nv_bfloat16*)dsm;
    __nv_bfloat16* sAl = sAh + 128*KP;
    __nv_bfloat16* sBh = sAl + 128*KP;
    __nv_bfloat16* sBl = sBh + 64*KP;
    const int t = threadIdx.x, w = t >> 5, lane = t & 31;
    const int wm = w & 3, wn = w >> 2;
    const int row0 = blockIdx.y*128, col0 = blockIdx.x*64;
    const int lrow = (lane & 15), lcol8 = (lane >> 4)*8;
    float acc[2][4][4] = {};

    MAINLOOP_64COL(sAh, sAl, sBh, sBl, Ah, Al, Bh, Bl, row0, col0, acc);

    const int rl4 = lane >> 2, cl2 = (lane & 3)*2;
    #pragma unroll
    for (int mt = 0; mt < 2; mt++)
        #pragma unroll
        for (int h2 = 0; h2 < 2; h2++) {
            int gr = row0 + wm*32 + mt*16 + rl4 + h2*8;
            #pragma unroll
            for (int nt = 0; nt < 4; nt++) {
                int gc = col0 + wn*32 + nt*8 + cl2;
                float v0 = gelu(acc[mt][nt][h2*2]   + bias[gc]);
                float v1 = gelu(acc[mt][nt][h2*2+1] + bias[gc+1]);
                __nv_bfloat16 h0,l0,h1,l1;
                split_bf16(v0,h0,l0); split_bf16(v1,h1,l1);
                __nv_bfloat162 hp, lp;
                hp.x = h0; hp.y = h1; lp.x = l0; lp.y = l1;
                *(__nv_bfloat162*)(g_fh + (size_t)gr*FFD + gc) = hp;
                *(__nv_bfloat162*)(g_fl + (size_t)gr*FFD + gc) = lp;
            }
        }
}

// ============ HMMA GEMM 64x128 tile, double-buffered (WO/FF2) ============
#define SROW 72
#define BUFSZ (384*SROW)
__global__ __launch_bounds__(256) void k_mma64(
    const __nv_bfloat16* __restrict__ Ah, const __nv_bfloat16* __restrict__ Al, int lda,
    const __nv_bfloat16* __restrict__ Bh, const __nv_bfloat16* __restrict__ Bl,
    int Ktot,
    const float* __restrict__ bias,
    float* __restrict__ out)
{
    extern __shared__ __align__(16) __nv_bfloat16 sb[];
    const int t = threadIdx.x, w = t >> 5, lane = t & 31;
    const int wm = w & 1, wn = w >> 1;
    const int row0 = blockIdx.y*64;
    float acc[2][4][4] = {};
    const int lrow = (lane & 15), lcol8 = (lane >> 4)*8;

    {
        #pragma unroll
        for (int i = 0; i < 2; i++) {
            int f = i*256 + t;
            int r = f >> 3, c8 = (f & 7) << 3;
            *(uint4*)(sb + r*SROW + c8)            = *(const uint4*)(Ah + (size_t)(row0+r)*lda + c8);
            *(uint4*)(sb + 64*SROW + r*SROW + c8)  = *(const uint4*)(Al + (size_t)(row0+r)*lda + c8);
        }
        #pragma unroll
        for (int i = 0; i < 4; i++) {
            int f = i*256 + t;
            int r = f >> 3, c8 = (f & 7) << 3;
            *(uint4*)(sb + 128*SROW + r*SROW + c8) = *(const uint4*)(Bh + (size_t)r*Ktot + c8);
            *(uint4*)(sb + 256*SROW + r*SROW + c8) = *(const uint4*)(Bl + (size_t)r*Ktot + c8);
        }
    }
    __syncthreads();
    int buf = 0;

    for (int kc = 64; kc <= Ktot; kc += 64) {
        uint4 ra[2][2], rb[2][4];
        if (kc < Ktot) {
            #pragma unroll
            for (int i = 0; i < 2; i++) {
                int f = i*256 + t;
                int r = f >> 3, c8 = (f & 7) << 3;
                ra[0][i] = *(const uint4*)(Ah + (size_t)(row0+r)*lda + kc + c8);
                ra[1][i] = *(const uint4*)(Al + (size_t)(row0+r)*lda + kc + c8);
            }
            #pragma unroll
            for (int i = 0; i < 4; i++) {
                int f = i*256 + t;
                int r = f >> 3, c8 = (f & 7) << 3;
                rb[0][i] = *(const uint4*)(Bh + (size_t)r*Ktot + kc + c8);
                rb[1][i] = *(const uint4*)(Bl + (size_t)r*Ktot + kc + c8);
            }
        }
        const __nv_bfloat16* cb = sb + buf*BUFSZ;
        #pragma unroll
        for (int ks = 0; ks < 4; ks++) {
            int kcol = ks*16 + lcol8;
            uint32_t ah[2][4], al[2][4];
            #pragma unroll
            for (int mt = 0; mt < 2; mt++) {
                int arow = wm*32 + mt*16 + lrow;
                ldsm4(ah[mt], s2u(cb + arow*SROW + kcol));
                ldsm4(al[mt], s2u(cb + 64*SROW + arow*SROW + kcol));
            }
            #pragma unroll
            for (int nt2 = 0; nt2 < 2; nt2++) {
                int brow = wn*32 + nt2*16 + lrow;
                uint32_t rh[4], rl[4];
                ldsm4(rh, s2u(cb + 128*SROW + brow*SROW + kcol));
                ldsm4(rl, s2u(cb + 256*SROW + brow*SROW + kcol));
                uint32_t b0h[2] = {rh[0], rh[2]}, b1h[2] = {rh[1], rh[3]};
                uint32_t b0l[2] = {rl[0], rl[2]}, b1l[2] = {rl[1], rl[3]};
                #pragma unroll
                for (int mt = 0; mt < 2; mt++)
                    MMA3x2(acc[mt][nt2*2], acc[mt][nt2*2+1], ah[mt], al[mt], b0h, b0l, b1h, b1l);
            }
        }
        if (kc < Ktot) {
            __nv_bfloat16* nb = sb + (buf^1)*BUFSZ;
            #pragma unroll
            for (int i = 0; i < 2; i++) {
                int f = i*256 + t;
                int r = f >> 3, c8 = (f & 7) << 3;
                *(uint4*)(nb + r*SROW + c8)           = ra[0][i];
                *(uint4*)(nb + 64*SROW + r*SROW + c8) = ra[1][i];
            }
            #pragma unroll
            for (int i = 0; i < 4; i++) {
                int f = i*256 + t;
                int r = f >> 3, c8 = (f & 7) << 3;
                *(uint4*)(nb + 128*SROW + r*SROW + c8) = rb[0][i];
                *(uint4*)(nb + 256*SROW + r*SROW + c8) = rb[1][i];
            }
            __syncthreads();
            buf ^= 1;
        }
    }

    const int rl4 = lane >> 2, cl2 = (lane & 3)*2;
    #pragma unroll
    for (int mt = 0; mt < 2; mt++)
        #pragma unroll
        for (int h2 = 0; h2 < 2; h2++) {
            int gr = row0 + wm*32 + mt*16 + rl4 + h2*8;
            #pragma unroll
            for (int nt = 0; nt < 4; nt++) {
                int gc = wn*32 + nt*8 + cl2;
                size_t idx = (size_t)gr*DIMC + gc;
                float2 v = *(float2*)(out + idx);
                v.x += acc[mt][nt][h2*2]   + bias[gc];
                v.y += acc[mt][nt][h2*2+1] + bias[gc+1];
                *(float2*)(out + idx) = v;
            }
        }
}

// ---------------- embed ----------------
__global__ void k_embed(const float* __restrict__ x, const float* __restrict__ lw,
                        const float* __restrict__ lb, const float* __restrict__ pe)
{
    int warp = threadIdx.x >> 5, lane = threadIdx.x & 31;
    int r = blockIdx.x*8 + warp;
    float xv = x[r];
    float4 l4 = ((const float4*)lw)[lane];
    float4 b4 = ((const float4*)lb)[lane];
    float4 p4 = ((const float4*)(pe + (size_t)(r % SS)*DIMC))[lane];
    float4 o4 = { xv*l4.x + b4.x + p4.x, xv*l4.y + b4.y + p4.y,
                  xv*l4.z + b4.z + p4.z, xv*l4.w + b4.w + p4.w };
    ((float4*)(g_h + (size_t)r*DIMC))[lane] = o4;
}

// ---------------- layernorm -> bf16 hi/lo ----------------
__global__ void k_ln(const float* __restrict__ in, const float* __restrict__ g,
                     const float* __restrict__ b,
                     __nv_bfloat16* __restrict__ outH, __nv_bfloat16* __restrict__ outL)
{
    int warp = threadIdx.x >> 5, lane = threadIdx.x & 31;
    int r = blockIdx.x*8 + warp;
    float4 v = ((const float4*)(in + (size_t)r*DIMC))[lane];
    float s = v.x + v.y + v.z + v.w;
    #pragma unroll
    for (int o = 16; o > 0; o >>= 1) s += __shfl_xor_sync(0xffffffffu, s, o);
    float mu = s * (1.0f/DIMC);
    float dx = v.x-mu, dy = v.y-mu, dz = v.z-mu, dw = v.w-mu;
    float q = dx*dx + dy*dy + dz*dz + dw*dw;
    #pragma unroll
    for (int o = 16; o > 0; o >>= 1) q += __shfl_xor_sync(0xffffffffu, q, o);
    float inv = rsqrtf(q*(1.0f/DIMC) + 1e-5f);
    float4 gv = ((const float4*)g)[lane];
    float4 bv = ((const float4*)b)[lane];
    float o4[4] = { dx*inv*gv.x + bv.x, dy*inv*gv.y + bv.y,
                    dz*inv*gv.z + bv.z, dw*inv*gv.w + bv.w };
    __nv_bfloat16 hh[4], ll[4];
    #pragma unroll
    for (int j = 0; j < 4; j++) split_bf16(o4[j], hh[j], ll[j]);
    size_t base = (size_t)r*DIMC + lane*4;
    *(uint2*)(outH+base) = *(uint2*)hh;
    *(uint2*)(outL+base) = *(uint2*)ll;
}

// -------- unified weight prep: one launch, all weights, both layers --------
__global__ __launch_bounds__(256) void k_wprep(
    const float* __restrict__ wq, const float* __restrict__ wk,
    const float* __restrict__ wv, const float* __restrict__ wo,
    const float* __restrict__ ff1_w, const float* __restrict__ ff2_w,
    const float* __restrict__ proj)
{
    __shared__ float tile[32][33];
    int bid = blockIdx.x;
    int l = (bid >= 656) ? 1 : 0;
    bid -= l*656;
    size_t wb = (size_t)l*WT_LAYER;
    __nv_bfloat16* wth = g_wth + wb;
    __nv_bfloat16* wtl = g_wtl + wb;

    const float* W; __nv_bfloat16 *oH, *oL; int K, N, tidx;
    if (bid < 384) {
        int which = bid >> 7; tidx = bid & 127;
        W = (which == 0 ? wq : which == 1 ? wk : wv) + (size_t)l*DIMC*INNER;
        oH = wth + (which == 0 ? WT_Q : which == 1 ? WT_K : WT_V);
        oL = wtl + (which == 0 ? WT_Q : which == 1 ? WT_K : WT_V);
        K = DIMC; N = INNER;
    } else if (bid < 512) {
        tidx = bid - 384;
        W = wo + (size_t)l*INNER*DIMC;
        oH = wth + WT_O; oL = wtl + WT_O;
        K = INNER; N = DIMC;
    } else if (bid < 576) {
        tidx = bid - 512;
        W = ff1_w + (size_t)l*DIMC*FFD;
        oH = wth + WT_F1; oL = wtl + WT_F1;
        K = DIMC; N = FFD;
    } else if (bid < 640) {
        tidx = bid - 576;
        W = ff2_w + (size_t)l*FFD*DIMC;
        oH = wth + WT_F2; oL = wtl + WT_F2;
        K = FFD; N = DIMC;
    } else {
        int e4 = (bid - 640)*256 + threadIdx.x;
        float4 v = ((const float4*)(proj + (size_t)l*MF*DHD))[e4];
        __nv_bfloat16 hh[4], ll[4];
        split_bf16(v.x, hh[0], ll[0]); split_bf16(v.y, hh[1], ll[1]);
        split_bf16(v.z, hh[2], ll[2]); split_bf16(v.w, hh[3], ll[3]);
        *(uint2*)(wth + WT_PJ + e4*4) = *(uint2*)hh;
        *(uint2*)(wtl + WT_PJ + e4*4) = *(uint2*)ll;
        return;
    }
    int ntiles = N >> 5;
    int n0 = (tidx % ntiles)*32, k0 = (tidx / ntiles)*32;
    int tx = threadIdx.x & 31, ty = threadIdx.x >> 5;
    #pragma unroll
    for (int i = ty; i < 32; i += 8)
        tile[i][tx] = W[(size_t)(k0+i)*N + n0 + tx];
    __syncthreads();
    #pragma unroll
    for (int i = ty; i < 32; i += 8) {
        float v = tile[tx][i];
        __nv_bfloat16 hh, ll;
        split_bf16(v, hh, ll);
        oH[(size_t)(n0+i)*K + k0 + tx] = hh;
        oL[(size_t)(n0+i)*K + k0 + tx] = ll;
    }
}

// ================= chunk-local attention via HMMA, 512 threads =================
// V single bf16 (B-side); Q/K hi/lo kept
#define CP 136
__global__ __launch_bounds__(512) void k_chunk(
    const __nv_bfloat16* __restrict__ qph, const __nv_bfloat16* __restrict__ qpl)
{
    extern __shared__ __align__(16) __nv_bfloat16 cs[];
    __nv_bfloat16* sQh = cs;
    __nv_bfloat16* sQl = sQh + 128*CP;
    __nv_bfloat16* sKh = sQl + 128*CP;
    __nv_bfloat16* sKl = sKh + 128*CP;
    __nv_bfloat16* sV  = sKl + 128*CP;    // single bf16 V tile
    __shared__ float s_den[4][128];
    __shared__ float s_dg[128];

    int blk = blockIdx.x, bh = blk >> 4, c = blk & 15;
    int b = bh >> 3, hh = bh & 7;
    int t = threadIdx.x, w = t >> 5, lane = t & 31;
    int wm = w & 3, wn = w >> 2;
    const int lrow = lane & 15, lcol8 = (lane >> 4)*8;
    const int rl4 = lane >> 2, cl2 = (lane & 3)*2;

    const size_t qbase = ((size_t)bh*SS + c*CHUNK)*MF;
    if (t < 128) {
        float st = g_bmax[bh*16];
        #pragma unroll
        for (int i = 1; i < 16; i++) st = fmaxf(st, g_bmax[bh*16 + i]);
        s_dg[t] = g_diagk[(size_t)bh*SS + c*CHUNK + t] + st;
    }
    for (int i = t; i < 2048; i += 512) {
        int r = i >> 4, c8 = (i & 15) << 3;
        *(uint4*)(sQh + r*CP + c8) = *(const uint4*)(qph + qbase + r*MF + c8);
        *(uint4*)(sQl + r*CP + c8) = *(const uint4*)(qpl + qbase + r*MF + c8);
        size_t vsrc = (size_t)(b*SS + c*CHUNK + r)*INNER + hh*DHD + c8;
        *(uint4*)(sV + r*CP + c8) = *(const uint4*)(g_vh + vsrc);
    }
    __syncthreads();
    for (int f = t; f < 4096; f += 512) {
        int r = f >> 5, c4 = (f & 31) << 2;
        float4 dv = *(const float4*)(g_kp + qbase + (size_t)r*MF + c4);
        float dgv = s_dg[r];
        float o0 = RATIOC*(expf(dv.x - dgv) + 1e-4f);
        float o1 = RATIOC*(expf(dv.y - dgv) + 1e-4f);
        float o2 = RATIOC*(expf(dv.z - dgv) + 1e-4f);
        float o3 = RATIOC*(expf(dv.w - dgv) + 1e-4f);
        __nv_bfloat16 hh4[4], ll4[4];
        split_bf16(o0, hh4[0], ll4[0]); split_bf16(o1, hh4[1], ll4[1]);
        split_bf16(o2, hh4[2], ll4[2]); split_bf16(o3, hh4[3], ll4[3]);
        *(uint2*)(sKh + r*CP + c4) = *(uint2*)hh4;
        *(uint2*)(sKl + r*CP + c4) = *(uint2*)ll4;
    }
    __syncthreads();

    // ---- phase 1: attn = Q@K^T (full hi/lo) ----
    float acc[2][4][4] = {};
    if (wn <= wm) {
        #pragma unroll
        for (int ks = 0; ks < 8; ks++) {
            int kcol = ks*16 + lcol8;
            uint32_t ah[2][4], al[2][4];
            #pragma unroll
            for (int mt = 0; mt < 2; mt++) {
                int arow = wm*32 + mt*16 + lrow;
                ldsm4(ah[mt], s2u(sQh + arow*CP + kcol));
                ldsm4(al[mt], s2u(sQl + arow*CP + kcol));
            }
            #pragma unroll
            for (int nt2 = 0; nt2 < 2; nt2++) {
                int brow = wn*32 + nt2*16 + lrow;
                uint32_t rh[4], rl[4];
                ldsm4(rh, s2u(sKh + brow*CP + kcol));
                ldsm4(rl, s2u(sKl + brow*CP + kcol));
                uint32_t b0h[2] = {rh[0], rh[2]}, b1h[2] = {rh[1], rh[3]};
                uint32_t b0l[2] = {rl[0], rl[2]}, b1l[2] = {rl[1], rl[3]};
                #pragma unroll
                for (int mt = 0; mt < 2; mt++)
                    MMA3x2(acc[mt][nt2*2], acc[mt][nt2*2+1], ah[mt], al[mt], b0h, b0l, b1h, b1l);
            }
        }
    }
    float dp[2][2] = {};
    #pragma unroll
    for (int mt = 0; mt < 2; mt++)
        #pragma unroll
        for (int nt = 0; nt < 4; nt++)
            #pragma unroll
            for (int f = 0; f < 4; f++) {
                int i = wm*32 + mt*16 + rl4 + ((f>>1)<<3);
                int j = wn*32 + nt*8 + cl2 + (f&1);
                if (j > i) acc[mt][nt][f] = 0.f;
                dp[mt][f>>1] += acc[mt][nt][f];
            }
    #pragma unroll
    for (int o = 1; o < 4; o <<= 1)
        #pragma unroll
        for (int mt = 0; mt < 2; mt++)
            #pragma unroll
            for (int h2 = 0; h2 < 2; h2++)
                dp[mt][h2] += __shfl_xor_sync(0xffffffffu, dp[mt][h2], o);
    if ((lane & 3) == 0) {
        #pragma unroll
        for (int mt = 0; mt < 2; mt++)
            #pragma unroll
            for (int h2 = 0; h2 < 2; h2++)
                s_den[wn][wm*32 + mt*16 + rl4 + h2*8] = dp[mt][h2];
    }
    __syncthreads();

    #pragma unroll
    for (int mt = 0; mt < 2; mt++)
        #pragma unroll
        for (int nt = 0; nt < 4; nt++)
            #pragma unroll
            for (int f = 0; f < 4; f++) {
                int i = wm*32 + mt*16 + rl4 + ((f>>1)<<3);
                int j = wn*32 + nt*8 + cl2 + (f&1);
                __nv_bfloat16 hh2, ll2;
                split_bf16(acc[mt][nt][f], hh2, ll2);
                sQh[i*CP + j] = hh2;
                sQl[i*CP + j] = ll2;
            }
    if (t < 128) {
        g_den[(size_t)bh*SS + c*CHUNK + t] = s_den[0][t] + s_den[1][t] + s_den[2][t] + s_den[3][t];
        float kssum = 0.f;
        for (int j = 0; j < 128; j++)
            kssum += __bfloat162float(sKh[j*CP + t]) + __bfloat162float(sKl[j*CP + t]);
        g_ksc[((size_t)bh*NC + c)*MF + t] = kssum;
    }
    __syncthreads();

    // ---- phase 2: num = attn(hi/lo) @ V(single) ----
    #pragma unroll
    for (int mt = 0; mt < 2; mt++)
        #pragma unroll
        for (int nt = 0; nt < 4; nt++)
            #pragma unroll
            for (int f = 0; f < 4; f++) acc[mt][nt][f] = 0.f;
    #pragma unroll
    for (int ks = 0; ks < 8; ks++) {
        int kcol = ks*16 + lcol8;
        uint32_t ah[2][4], al[2][4];
        #pragma unroll
        for (int mt = 0; mt < 2; mt++) {
            int arow = wm*32 + mt*16 + lrow;
            ldsm4(ah[mt], s2u(sQh + arow*CP + kcol));
            ldsm4(al[mt], s2u(sQl + arow*CP + kcol));
        }
        #pragma unroll
        for (int nt2 = 0; nt2 < 2; nt2++) {
            int nbase = wn*32 + nt2*16;
            uint32_t dh[4];
            ldsm4t(dh, taddr(sV, CP, ks*16, nbase, lane));
            uint32_t b0[2] = {dh[0], dh[2]}, b1[2] = {dh[1], dh[3]};
            #pragma unroll
            for (int mt = 0; mt < 2; mt++)
                MMA2x2(acc[mt][nt2*2], acc[mt][nt2*2+1], ah[mt], al[mt], b0, b1);
        }
    }
    #pragma unroll
    for (int mt = 0; mt < 2; mt++)
        #pragma unroll
        for (int h2 = 0; h2 < 2; h2++) {
            int i = wm*32 + mt*16 + rl4 + h2*8;
            size_t base = ((size_t)(b*SS + c*CHUNK + i)*HH + hh)*DHD;
            #pragma unroll
            for (int nt = 0; nt < 4; nt++) {
                float2 vv = {acc[mt][nt][h2*2], acc[mt][nt][h2*2+1]};
                *(float2*)(g_o + base + wn*32 + nt*8 + cl2) = vv;
            }
        }

    // ---- phase 3: kv = K^T(hi/lo) @ V(single) ----
    #pragma unroll
    for (int mt = 0; mt < 2; mt++)
        #pragma unroll
        for (int nt = 0; nt < 4; nt++)
            #pragma unroll
            for (int f = 0; f < 4; f++) acc[mt][nt][f] = 0.f;
    #pragma unroll
    for (int ks = 0; ks < 8; ks++) {
        uint32_t ah[2][4], al[2][4];
        #pragma unroll
        for (int mt = 0; mt < 2; mt++) {
            int mbase = wm*32 + mt*16;
            ldsm4t(ah[mt], taddr(sKh, CP, ks*16, mbase, lane));
            ldsm4t(al[mt], taddr(sKl, CP, ks*16, mbase, lane));
        }
        #pragma unroll
        for (int nt2 = 0; nt2 < 2; nt2++) {
            int nbase = wn*32 + nt2*16;
            uint32_t dh[4];
            ldsm4t(dh, taddr(sV, CP, ks*16, nbase, lane));
            uint32_t b0[2] = {dh[0], dh[2]}, b1[2] = {dh[1], dh[3]};
            #pragma unroll
            for (int mt = 0; mt < 2; mt++)
                MMA2x2(acc[mt][nt2*2], acc[mt][nt2*2+1], ah[mt], al[mt], b0, b1);
        }
    }
    {
        size_t kvbase = ((size_t)bh*NC + c)*(MF*DHD);
        #pragma unroll
        for (int mt = 0; mt < 2; mt++)
            #pragma unroll
            for (int h2 = 0; h2 < 2; h2++) {
                int m = wm*32 + mt*16 + rl4 + h2*8;
                #pragma unroll
                for (int nt = 0; nt < 4; nt++) {
                    float2 vv = {acc[mt][nt][h2*2], acc[mt][nt][h2*2+1]};
                    *(float2*)(g_kvc + kvbase + (size_t)m*DHD + wn*32 + nt*8 + cl2) = vv;
                }
            }
    }
}

// ---------------- exclusive prefix over chunks (emits single bf16 kvp) ----------------
__global__ void k_prefix()
{
    int bh = blockIdx.x, seg = blockIdx.y, t = threadIdx.x;
    for (int e = seg*2048 + t; e < (seg+1)*2048; e += 256) {
        float run = 0.f;
        #pragma unroll
        for (int c = 0; c < NC; c++) {
            size_t idx = ((size_t)bh*NC + c)*(MF*DHD) + e;
            g_kvph[idx] = __float2bfloat16(run);
            run += g_kvc[idx];
        }
    }
    if (seg == 0) {
        for (int e = t; e < MF; e += 256) {
            float run = 0.f;
            #pragma unroll
            for (int c = 0; c < NC; c++) {
                size_t idx = ((size_t)bh*NC + c)*MF + e;
                g_ksp[idx] = run; run += g_ksc[idx];
            }
        }
    }
}

// ========== cross = qp(hi/lo) @ kvp(single), + num, normalize -> oh/ol ==========
__global__ __launch_bounds__(512) void k_cross(
    const __nv_bfloat16* __restrict__ qph, const __nv_bfloat16* __restrict__ qpl)
{
    extern __shared__ __align__(16) __nv_bfloat16 cs[];
    __nv_bfloat16* sQh = cs;
    __nv_bfloat16* sQl = sQh + 128*CP;
    __nv_bfloat16* sP  = sQl + 128*CP;    // kvp single bf16
    __shared__ float s_ks[128];
    __shared__ float s_dc[128];

    int blk = blockIdx.x, bh = blk >> 4, c = blk & 15;
    int b = bh >> 3, hh = bh & 7;
    int t = threadIdx.x, w = t >> 5, lane = t & 31;
    int wm = w & 3, wn = w >> 2;
    const int lrow = lane & 15, lcol8 = (lane >> 4)*8;
    const int rl4 = lane >> 2, cl2 = (lane & 3)*2;

    const size_t qbase = ((size_t)bh*SS + c*CHUNK)*MF;
    const size_t pbase = ((size_t)bh*NC + c)*(MF*DHD);
    for (int i = t; i < 2048; i += 512) {
        int r = i >> 4, c8 = (i & 15) << 3;
        *(uint4*)(sQh + r*CP + c8) = *(const uint4*)(qph + qbase + r*MF + c8);
        *(uint4*)(sQl + r*CP + c8) = *(const uint4*)(qpl + qbase + r*MF + c8);
        *(uint4*)(sP  + r*CP + c8) = *(const uint4*)(g_kvph + pbase + r*DHD + c8);
    }
    if (t < 128) s_ks[t] = g_ksp[((size_t)bh*NC + c)*MF + t];
    __syncthreads();
    if (t < 128) {
        float dc = 0.f;
        for (int m = 0; m < 128; m++)
            dc += (__bfloat162float(sQh[t*CP + m]) + __bfloat162float(sQl[t*CP + m]))*s_ks[m];
        s_dc[t] = g_den[(size_t)bh*SS + c*CHUNK + t] + dc + 1e-6f;
    }
    __syncthreads();

    float acc[2][4][4] = {};
    #pragma unroll
    for (int ks = 0; ks < 8; ks++) {
        int kcol = ks*16 + lcol8;
        uint32_t ah[2][4], al[2][4];
        #pragma unroll
        for (int mt = 0; mt < 2; mt++) {
            int arow = wm*32 + mt*16 + lrow;
            ldsm4(ah[mt], s2u(sQh + arow*CP + kcol));
            ldsm4(al[mt], s2u(sQl + arow*CP + kcol));
        }
        #pragma unroll
        for (int nt2 = 0; nt2 < 2; nt2++) {
            int nbase = wn*32 + nt2*16;
            uint32_t dh[4];
            ldsm4t(dh, taddr(sP, CP, ks*16, nbase, lane));
            uint32_t b0[2] = {dh[0], dh[2]}, b1[2] = {dh[1], dh[3]};
            #pragma unroll
            for (int mt = 0; mt < 2; mt++)
                MMA2x2(acc[mt][nt2*2], acc[mt][nt2*2+1], ah[mt], al[mt], b0, b1);
        }
    }
    #pragma unroll
    for (int mt = 0; mt < 2; mt++)
        #pragma unroll
        for (int h2 = 0; h2 < 2; h2++) {
            int i = wm*32 + mt*16 + rl4 + h2*8;
            float inv = 1.0f / s_dc[i];
            size_t base = ((size_t)(b*SS + c*CHUNK + i)*HH + hh)*DHD;
            #pragma unroll
            for (int nt = 0; nt < 4; nt++) {
                size_t idx = base + wn*32 + nt*8 + cl2;
                float2 nn = *(float2*)(g_o + idx);
                float v0 = (nn.x + acc[mt][nt][h2*2])   * inv;
                float v1 = (nn.y + acc[mt][nt][h2*2+1]) * inv;
                __nv_bfloat16 h0,l0,h1,l1;
                split_bf16(v0,h0,l0); split_bf16(v1,h1,l1);
                __nv_bfloat162 hp, lp;
                hp.x = h0; hp.y = h1; lp.x = l0; lp.y = l1;
                *(__nv_bfloat162*)(g_oh + idx) = hp;
                *(__nv_bfloat162*)(g_ol + idx) = lp;
            }
        }
}

// ---------------- pooling ----------------
__global__ void k_pool()
{
    int b = blockIdx.x, seg = blockIdx.y, t = threadIdx.x;
    float acc = 0.f;
    for (int s = seg*128; s < (seg+1)*128; s++) acc += g_h[((size_t)b*SS + s)*DIMC + t];
    g_pp[(b*16 + seg)*DIMC + t] = acc;
}

__global__ void k_final(const float* __restrict__ fw, const float* __restrict__ fb,
                        float* __restrict__ out)
{
    __shared__ float pooled[BB*DIMC];
    int t = threadIdx.x;
    for (int b = 0; b < BB; b++) {
        float a = 0.f;
        #pragma unroll
        for (int s = 0; s < 16; s++) a += g_pp[(b*16 + s)*DIMC + t];
        pooled[b*DIMC + t] = a * (1.0f/SS);
    }
    __syncthreads();
    if (t < BB*NCLS) {
        int b = t / NCLS, c = t % NCLS;
        float acc = fb[c];
        for (int d = 0; d < DIMC; d++) acc += pooled[b*DIMC + d]*fw[d*NCLS + c];
        out[t] = acc;
    }
}

// ---------------- host driver ----------------
static void* sym(const void* s) { void* p = nullptr; cudaGetSymbolAddress(&p, s); return p; }

extern "C" void kernel_launch(void* const* d_in, const int* in_sizes, int n_in,
                              void* d_out, int out_size)
{
    const float* x     = (const float*)d_in[0];
    const float* lin_w = (const float*)d_in[1];
    const float* lin_b = (const float*)d_in[2];
    const float* pe    = (const float*)d_in[3];
    const float* proj  = (const float*)d_in[4];
    const float* ln1_g = (const float*)d_in[5];
    const float* ln1_b = (const float*)d_in[6];
    const float* wq    = (const float*)d_in[7];
    const float* wk    = (const float*)d_in[8];
    const float* wv    = (const float*)d_in[9];
    const float* wo    = (const float*)d_in[10];
    const float* wo_b  = (const float*)d_in[11];
    const float* ln2_g = (const float*)d_in[12];
    const float* ln2_b = (const float*)d_in[13];
    const float* ff1_w = (const float*)d_in[14];
    const float* ff1_b = (const float*)d_in[15];
    const float* ff2_w = (const float*)d_in[16];
    const float* ff2_b = (const float*)d_in[17];
    const float* fin_w = (const float*)d_in[18];
    const float* fin_b = (const float*)d_in[19];
    float* out = (float*)d_out;

    float* ph   = (float*)sym(g_h);
    float* pkp  = (float*)sym(g_kp);
    float* pbm  = (float*)sym(g_bmax);

    __nv_bfloat16* yh  = (__nv_bfloat16*)sym(g_yh);
    __nv_bfloat16* yl  = (__nv_bfloat16*)sym(g_yl);
    __nv_bfloat16* wth = (__nv_bfloat16*)sym(g_wth);
    __nv_bfloat16* wtl = (__nv_bfloat16*)sym(g_wtl);
    __nv_bfloat16* qnh = (__nv_bfloat16*)sym(g_qnh);
    __nv_bfloat16* qnl = (__nv_bfloat16*)sym(g_qnl);
    __nv_bfloat16* knh = (__nv_bfloat16*)sym(g_knh);
    __nv_bfloat16* knl = (__nv_bfloat16*)sym(g_knl);
    __nv_bfloat16* qp_h = (__nv_bfloat16*)sym(g_qph);
    __nv_bfloat16* qp_l = (__nv_bfloat16*)sym(g_qpl);
    __nv_bfloat16* oh  = (__nv_bfloat16*)sym(g_oh);
    __nv_bfloat16* ol  = (__nv_bfloat16*)sym(g_ol);
    __nv_bfloat16* fh  = (__nv_bfloat16*)sym(g_fh);
    __nv_bfloat16* fl  = (__nv_bfloat16*)sym(g_fl);

    const int SMEM_MMA   = 4*128*KP*2;           // 139264 (features)
    const int SMEM_QKVFF = QKV_SMEM;             // 104448 (2 CTAs/SM)
    const int SMEM_MMA64 = 2*BUFSZ*2;            // 110592
    const int SMEM_CHUNK = 5*128*CP*2;           // 174080
    const int SMEM_CROSS = 3*128*CP*2;           // 104448
    cudaFuncSetAttribute(k_mmaF, cudaFuncAttributeMaxDynamicSharedMemorySize, SMEM_MMA);
    cudaFuncSetAttribute(k_mmaqkv64, cudaFuncAttributeMaxDynamicSharedMemorySize, SMEM_QKVFF);
    cudaFuncSetAttribute(k_ff1, cudaFuncAttributeMaxDynamicSharedMemorySize, SMEM_QKVFF);
    cudaFuncSetAttribute(k_mma64, cudaFuncAttributeMaxDynamicSharedMemorySize, SMEM_MMA64);
    cudaFuncSetAttribute(k_chunk, cudaFuncAttributeMaxDynamicSharedMemorySize, SMEM_CHUNK);
    cudaFuncSetAttribute(k_cross, cudaFuncAttributeMaxDynamicSharedMemorySize, SMEM_CROSS);

    k_wprep<<<2*656, 256>>>(wq, wk, wv, wo, ff1_w, ff2_w, proj);
    k_embed<<<BSR/8, 256>>>(x, lin_w, lin_b, pe);

    for (int l = 0; l < DEPTH; l++) {
        size_t wb = (size_t)l*WT_LAYER;

        k_ln<<<BSR/8, 256>>>(ph, ln1_g + l*DIMC, ln1_b + l*DIMC, yh, yl);

        k_mmaqkv64<<<dim3(48,64), 256, SMEM_QKVFF>>>(yh, yl, wth+wb+WT_Q, wtl+wb+WT_Q);

        k_mmaF<<<dim3(2,512), 256, SMEM_MMA>>>(knh, knl, qnh, qnl,
                                               wth+wb+WT_PJ, wtl+wb+WT_PJ,
                                               pkp, qp_h, qp_l, pbm);

        k_chunk<<<NBH*NC, 512, SMEM_CHUNK>>>(qp_h, qp_l);
        k_prefix<<<dim3(NBH, 8), 256>>>();
        k_cross<<<NBH*NC, 512, SMEM_CROSS>>>(qp_h, qp_l);

        k_mma64<<<dim3(1,BSR/64), 256, SMEM_MMA64>>>(oh, ol, INNER, wth+wb+WT_O, wtl+wb+WT_O, INNER,
                                                     wo_b + l*DIMC, ph);

        k_ln<<<BSR/8, 256>>>(ph, ln2_g + l*DIMC, ln2_b + l*DIMC, yh, yl);
        k_ff1<<<dim3(8,64), 256, SMEM_QKVFF>>>(yh, yl, wth+wb+WT_F1, wtl+wb+WT_F1, ff1_b + l*FFD);
        k_mma64<<<dim3(1,BSR/64), 256, SMEM_MMA64>>>(fh, fl, FFD, wth+wb+WT_F2, wtl+wb+WT_F2, FFD,
                                                     ff2_b + l*DIMC, ph);
    }

    k_pool<<<dim3(BB, 16), 128>>>();
    k_final<<<1, 128>>>(fin_w, fin_b, out);
}

// round 16
// speedup vs baseline: 1.1887x; 1.0564x over previous
#include <cuda_runtime.h>
#include <cuda_bf16.h>
#include <math.h>
#include <stdint.h>

// ---------------- problem constants ----------------
#define BB 4
#define SS 2048
#define DIMC 128
#define HH 8
#define DHD 128
#define DEPTH 2
#define NCLS 10
#define MF 128
#define CHUNK 128
#define NC 16
#define INNER 1024
#define FFD 512
#define BSR 8192
#define BHS 65536
#define NBH 32

#define NORMC 0.29730177875068026f
#define RATIOC 0.08838834764831845f

// ---------------- device scratch (fp32) ----------------
__device__ float g_h  [BSR*DIMC];
__device__ float g_kp [(size_t)NBH*SS*MF];
__device__ float g_diagk[BHS];
__device__ float g_bmax[NBH*16];
__device__ float g_o  [BSR*INNER];
__device__ float g_den[BHS];
__device__ float g_kvc[(size_t)NBH*NC*MF*DHD];
__device__ float g_ksc[NBH*NC*MF];
__device__ float g_ksp[NBH*NC*MF];
__device__ float g_pp [BB*16*DIMC];

// ---------------- device scratch (bf16) ----------------
__device__ __align__(256) __nv_bfloat16 g_yh [BSR*DIMC];
__device__ __align__(256) __nv_bfloat16 g_yl [BSR*DIMC];
__device__ __align__(256) __nv_bfloat16 g_wth[2*672000];
__device__ __align__(256) __nv_bfloat16 g_wtl[2*672000];
__device__ __align__(256) __nv_bfloat16 g_qnh[(size_t)BHS*DHD];
__device__ __align__(256) __nv_bfloat16 g_qnl[(size_t)BHS*DHD];
__device__ __align__(256) __nv_bfloat16 g_knh[(size_t)BHS*DHD];
__device__ __align__(256) __nv_bfloat16 g_knl[(size_t)BHS*DHD];
__device__ __align__(256) __nv_bfloat16 g_vh [(size_t)BSR*INNER];       // V: single bf16
__device__ __align__(256) __nv_bfloat16 g_qph[(size_t)NBH*SS*MF];
__device__ __align__(256) __nv_bfloat16 g_qpl[(size_t)NBH*SS*MF];
__device__ __align__(256) __nv_bfloat16 g_kvph[(size_t)NBH*NC*MF*DHD];  // kvp: single bf16
__device__ __align__(256) __nv_bfloat16 g_oh [(size_t)BSR*INNER];       // o: single bf16
__device__ __align__(256) __nv_bfloat16 g_fh [(size_t)BSR*FFD];         // f: single bf16

#define WT_Q  0
#define WT_K  131072
#define WT_V  262144
#define WT_O  393216
#define WT_F1 524288
#define WT_F2 589824
#define WT_PJ 655360
#define WT_LAYER 672000

// ---------------- warp MMA helpers ----------------
__device__ __forceinline__ uint32_t s2u(const void* p){
    uint32_t a;
    asm("{ .reg .u64 t; cvta.to.shared.u64 t, %1; cvt.u32.u64 %0, t; }" : "=r"(a) : "l"(p));
    return a;
}
__device__ __forceinline__ void ldsm4(uint32_t* r, uint32_t addr){
    asm volatile("ldmatrix.sync.aligned.m8n8.x4.shared.b16 {%0,%1,%2,%3}, [%4];"
                 : "=r"(r[0]),"=r"(r[1]),"=r"(r[2]),"=r"(r[3]) : "r"(addr));
}
__device__ __forceinline__ void ldsm4t(uint32_t* r, uint32_t addr){
    asm volatile("ldmatrix.sync.aligned.m8n8.x4.trans.shared.b16 {%0,%1,%2,%3}, [%4];"
                 : "=r"(r[0]),"=r"(r[1]),"=r"(r[2]),"=r"(r[3]) : "r"(addr));
}
__device__ __forceinline__ void mma_bf16(float* c, const uint32_t* a, const uint32_t* b){
    asm volatile("mma.sync.aligned.m16n8k16.row.col.f32.bf16.bf16.f32 "
                 "{%0,%1,%2,%3}, {%4,%5,%6,%7}, {%8,%9}, {%0,%1,%2,%3};"
                 : "+f"(c[0]),"+f"(c[1]),"+f"(c[2]),"+f"(c[3])
                 : "r"(a[0]),"r"(a[1]),"r"(a[2]),"r"(a[3]), "r"(b[0]),"r"(b[1]));
}
__device__ __forceinline__ void split_bf16(float v, __nv_bfloat16& h, __nv_bfloat16& l){
    h = __float2bfloat16(v);
    l = __float2bfloat16(v - __bfloat162float(h));
}
__device__ __forceinline__ float gelu(float xx){
    return 0.5f*xx*(1.0f + tanhf(0.7978845608028654f*(xx + 0.044715f*xx*xx*xx)));
}
__device__ __forceinline__ uint32_t taddr(const __nv_bfloat16* S, int P, int kbase, int nbase, int lane){
    int kk = (lane & 7) + ((lane >> 4) << 3);
    int nn = ((lane >> 3) & 1) << 3;
    return s2u(S + (size_t)(kbase + kk)*P + nbase + nn);
}
#define MMA3x2(accA, accB, ah_, al_, b0h_, b0l_, b1h_, b1l_) \
    do { mma_bf16(accA, ah_, b0h_); mma_bf16(accA, ah_, b0l_); mma_bf16(accA, al_, b0h_); \
         mma_bf16(accB, ah_, b1h_); mma_bf16(accB, ah_, b1l_); mma_bf16(accB, al_, b1h_); } while(0)
// A hi/lo vs single B
#define MMA2x2(accA, accB, ah_, al_, b0_, b1_) \
    do { mma_bf16(accA, ah_, b0_); mma_bf16(accA, al_, b0_); \
         mma_bf16(accB, ah_, b1_); mma_bf16(accB, al_, b1_); } while(0)
// single A vs B hi/lo
#define MMA2x2B(accA, accB, a_, b0h_, b0l_, b1h_, b1l_) \
    do { mma_bf16(accA, a_, b0h_); mma_bf16(accA, a_, b0l_); \
         mma_bf16(accB, a_, b1h_); mma_bf16(accB, a_, b1l_); } while(0)

#define KP 136

// ======== merged feature GEMM (single-stage K=128) ========
__global__ __launch_bounds__(256) void k_mmaF(
    const __nv_bfloat16* __restrict__ Kh, const __nv_bfloat16* __restrict__ Kl,
    const __nv_bfloat16* __restrict__ Qh, const __nv_bfloat16* __restrict__ Ql,
    const __nv_bfloat16* __restrict__ Bh, const __nv_bfloat16* __restrict__ Bl,
    float* __restrict__ out,
    __nv_bfloat16* __restrict__ outH, __nv_bfloat16* __restrict__ outL,
    float* __restrict__ bmax)
{
    extern __shared__ __align__(16) char dsm[];
    __nv_bfloat16* sAh = (__nv_bfloat16*)dsm;
    __nv_bfloat16* sAl = sAh + 128*KP;
    __nv_bfloat16* sBh = sAl + 128*KP;
    __nv_bfloat16* sBl = sBh + 128*KP;
    __shared__ float s_rm[2][128];
    __shared__ float s_red[256];
    __shared__ float s_dg[128];

    const int MODE = (blockIdx.x == 0) ? 4 : 3;
    const __nv_bfloat16* Ah = (MODE == 4) ? Kh : Qh;
    const __nv_bfloat16* Al = (MODE == 4) ? Kl : Ql;

    const int t = threadIdx.x, w = t >> 5, lane = t & 31;
    const int wm = w & 3, wn = w >> 2;
    const int row0 = blockIdx.y*128;

    float acc[2][8][4] = {};
    const int lrow = (lane & 15), lcol8 = (lane >> 4)*8;

    #pragma unroll
    for (int i = 0; i < 8; i++) {
        int f = i*256 + t;
        int r = f >> 4, c8 = (f & 15) << 3;
        *(uint4*)(sAh + r*KP + c8) = *(const uint4*)(Ah + (size_t)(row0+r)*128 + c8);
        *(uint4*)(sAl + r*KP + c8) = *(const uint4*)(Al + (size_t)(row0+r)*128 + c8);
        *(uint4*)(sBh + r*KP + c8) = *(const uint4*)(Bh + (size_t)r*128 + c8);
        *(uint4*)(sBl + r*KP + c8) = *(const uint4*)(Bl + (size_t)r*128 + c8);
    }
    __syncthreads();

    if (t < 128) {
        float dacc = 0.f;
        #pragma unroll
        for (int k8 = 0; k8 < 16; k8++) {
            uint4 uh = *(uint4*)(sAh + t*KP + k8*8);
            uint4 ul = *(uint4*)(sAl + t*KP + k8*8);
            const __nv_bfloat16* ph = (const __nv_bfloat16*)&uh;
            const __nv_bfloat16* pl = (const __nv_bfloat16*)&ul;
            #pragma unroll
            for (int j = 0; j < 8; j++) {
                float av = __bfloat162float(ph[j]) + __bfloat162float(pl[j]);
                dacc += av*av;
            }
        }
        if (MODE == 4) g_diagk[row0 + t] = 0.5f*dacc;
        else           s_dg[t] = 0.5f*dacc;
    }

    #pragma unroll
    for (int ks = 0; ks < 8; ks++) {
        int kcol = ks*16 + lcol8;
        uint32_t ah[2][4], al[2][4];
        #pragma unroll
        for (int mt = 0; mt < 2; mt++) {
            int arow = wm*32 + mt*16 + lrow;
            ldsm4(ah[mt], s2u(sAh + arow*KP + kcol));
            ldsm4(al[mt], s2u(sAl + arow*KP + kcol));
        }
        #pragma unroll
        for (int nt2 = 0; nt2 < 4; nt2++) {
            int brow = wn*64 + nt2*16 + lrow;
            uint32_t rh[4], rl[4];
            ldsm4(rh, s2u(sBh + brow*KP + kcol));
            ldsm4(rl, s2u(sBl + brow*KP + kcol));
            uint32_t b0h[2] = {rh[0], rh[2]}, b1h[2] = {rh[1], rh[3]};
            uint32_t b0l[2] = {rl[0], rl[2]}, b1l[2] = {rl[1], rl[3]};
            #pragma unroll
            for (int mt = 0; mt < 2; mt++)
                MMA3x2(acc[mt][nt2*2], acc[mt][nt2*2+1], ah[mt], al[mt], b0h, b0l, b1h, b1l);
        }
    }

    const int rl4 = lane >> 2, cl2 = (lane & 3)*2;

    if (MODE == 4) {
        float bm = -1e30f;
        #pragma unroll
        for (int mt = 0; mt < 2; mt++)
            #pragma unroll
            for (int h = 0; h < 2; h++) {
                int gr = row0 + wm*32 + mt*16 + rl4 + h*8;
                #pragma unroll
                for (int nt = 0; nt < 8; nt++) {
                    float2 v = {acc[mt][nt][h*2], acc[mt][nt][h*2+1]};
                    *(float2*)(out + (size_t)gr*MF + wn*64 + nt*8 + cl2) = v;
                    bm = fmaxf(bm, fmaxf(v.x, v.y));
                }
            }
        s_red[t] = bm; __syncthreads();
        #pragma unroll
        for (int o = 128; o > 0; o >>= 1) { if (t < o) s_red[t] = fmaxf(s_red[t], s_red[t+o]); __syncthreads(); }
        if (t == 0) bmax[blockIdx.y] = s_red[0];
    } else {
        float rm[2][2];
        #pragma unroll
        for (int mt = 0; mt < 2; mt++)
            #pragma unroll
            for (int h = 0; h < 2; h++) {
                float m = -1e30f;
                #pragma unroll
                for (int nt = 0; nt < 8; nt++)
                    m = fmaxf(m, fmaxf(acc[mt][nt][h*2], acc[mt][nt][h*2+1]));
                m = fmaxf(m, __shfl_xor_sync(0xffffffffu, m, 1));
                m = fmaxf(m, __shfl_xor_sync(0xffffffffu, m, 2));
                rm[mt][h] = m;
            }
        if ((lane & 3) == 0) {
            #pragma unroll
            for (int mt = 0; mt < 2; mt++)
                #pragma unroll
                for (int h = 0; h < 2; h++)
                    s_rm[wn][wm*32 + mt*16 + rl4 + h*8] = rm[mt][h];
        }
        __syncthreads();
        #pragma unroll
        for (int mt = 0; mt < 2; mt++)
            #pragma unroll
            for (int h = 0; h < 2; h++) {
                int lr = wm*32 + mt*16 + rl4 + h*8;
                int gr = row0 + lr;
                float rmax = fmaxf(s_rm[0][lr], s_rm[1][lr]);
                float dg = s_dg[lr];
                #pragma unroll
                for (int nt = 0; nt < 8; nt++) {
                    int gc = wn*64 + nt*8 + cl2;
                    float v0 = RATIOC*(expf(acc[mt][nt][h*2]  -dg-rmax) + 1e-4f);
                    float v1 = RATIOC*(expf(acc[mt][nt][h*2+1]-dg-rmax) + 1e-4f);
                    __nv_bfloat16 h0,l0,h1,l1;
                    split_bf16(v0,h0,l0); split_bf16(v1,h1,l1);
                    __nv_bfloat162 hp, lp;
                    hp.x = h0; hp.y = h1; lp.x = l0; lp.y = l1;
                    *(__nv_bfloat162*)(outH + (size_t)gr*MF + gc) = hp;
                    *(__nv_bfloat162*)(outL + (size_t)gr*MF + gc) = lp;
                }
            }
    }
}

// ======== 128x64-tile K=128 mainloop (2 CTAs/SM) — shared by QKV and FF1 ========
#define QKV_SMEM ((2*128 + 2*64)*KP*2)
#define MAINLOOP_64COL(sAh, sAl, sBh, sBl, Ah, Al, Bh, Bl, row0, col0, acc) \
    {   \
        _Pragma("unroll")                                                        \
        for (int i = 0; i < 8; i++) {                                            \
            int f = i*256 + threadIdx.x;                                         \
            int r = f >> 4, c8 = (f & 15) << 3;                                  \
            *(uint4*)(sAh + r*KP + c8) = *(const uint4*)(Ah + (size_t)(row0+r)*128 + c8); \
            *(uint4*)(sAl + r*KP + c8) = *(const uint4*)(Al + (size_t)(row0+r)*128 + c8); \
        }                                                                        \
        _Pragma("unroll")                                                        \
        for (int i = 0; i < 4; i++) {                                            \
            int f = i*256 + threadIdx.x;                                         \
            int r = f >> 4, c8 = (f & 15) << 3;                                  \
            *(uint4*)(sBh + r*KP + c8) = *(const uint4*)(Bh + (size_t)(col0+r)*128 + c8); \
            *(uint4*)(sBl + r*KP + c8) = *(const uint4*)(Bl + (size_t)(col0+r)*128 + c8); \
        }                                                                        \
        __syncthreads();                                                         \
        _Pragma("unroll")                                                        \
        for (int ks = 0; ks < 8; ks++) {                                         \
            int kcol = ks*16 + lcol8;                                            \
            uint32_t ah[2][4], al[2][4];                                         \
            _Pragma("unroll")                                                    \
            for (int mt = 0; mt < 2; mt++) {                                     \
                int arow = wm*32 + mt*16 + lrow;                                 \
                ldsm4(ah[mt], s2u(sAh + arow*KP + kcol));                        \
                ldsm4(al[mt], s2u(sAl + arow*KP + kcol));                        \
            }                                                                    \
            _Pragma("unroll")                                                    \
            for (int nt2 = 0; nt2 < 2; nt2++) {                                  \
                int brow = wn*32 + nt2*16 + lrow;                                \
                uint32_t rh[4], rl[4];                                           \
                ldsm4(rh, s2u(sBh + brow*KP + kcol));                            \
                ldsm4(rl, s2u(sBl + brow*KP + kcol));                            \
                uint32_t b0h[2] = {rh[0], rh[2]}, b1h[2] = {rh[1], rh[3]};       \
                uint32_t b0l[2] = {rl[0], rl[2]}, b1l[2] = {rl[1], rl[3]};       \
                _Pragma("unroll")                                                \
                for (int mt = 0; mt < 2; mt++)                                   \
                    MMA3x2(acc[mt][nt2*2], acc[mt][nt2*2+1], ah[mt], al[mt], b0h, b0l, b1h, b1l); \
            }                                                                    \
        }                                                                        \
    }

// QKV: grid (48, 64); epilogue scatters per part/head; V single bf16
__global__ __launch_bounds__(256) void k_mmaqkv64(
    const __nv_bfloat16* __restrict__ Ah, const __nv_bfloat16* __restrict__ Al,
    const __nv_bfloat16* __restrict__ Bh, const __nv_bfloat16* __restrict__ Bl)
{
    extern __shared__ __align__(16) char dsm[];
    __nv_bfloat16* sAh = (__nv_bfloat16*)dsm;
    __nv_bfloat16* sAl = sAh + 128*KP;
    __nv_bfloat16* sBh = sAl + 128*KP;
    __nv_bfloat16* sBl = sBh + 64*KP;
    const int t = threadIdx.x, w = t >> 5, lane = t & 31;
    const int wm = w & 3, wn = w >> 2;
    const int row0 = blockIdx.y*128, col0 = blockIdx.x*64;
    const int lrow = (lane & 15), lcol8 = (lane >> 4)*8;
    float acc[2][4][4] = {};

    MAINLOOP_64COL(sAh, sAl, sBh, sBl, Ah, Al, Bh, Bl, row0, col0, acc);

    const int rl4 = lane >> 2, cl2 = (lane & 3)*2;
    const int part = col0 >> 10;
    const int h = (col0 >> 7) & 7;
    const int d0 = col0 & 127;

    if (part < 2) {
        __nv_bfloat16* dH = part ? g_knh : g_qnh;
        __nv_bfloat16* dL = part ? g_knl : g_qnl;
        #pragma unroll
        for (int mt = 0; mt < 2; mt++)
            #pragma unroll
            for (int h2 = 0; h2 < 2; h2++) {
                int gr = row0 + wm*32 + mt*16 + rl4 + h2*8;
                int b = gr >> 11, s = gr & 2047;
                size_t base = ((size_t)(b*HH + h)*SS + s)*DHD + d0;
                #pragma unroll
                for (int nt = 0; nt < 4; nt++) {
                    float v0 = acc[mt][nt][h2*2]   * NORMC;
                    float v1 = acc[mt][nt][h2*2+1] * NORMC;
                    __nv_bfloat16 h0,l0,h1,l1;
                    split_bf16(v0,h0,l0); split_bf16(v1,h1,l1);
                    __nv_bfloat162 hp, lp;
                    hp.x = h0; hp.y = h1; lp.x = l0; lp.y = l1;
                    *(__nv_bfloat162*)(dH + base + wn*32 + nt*8 + cl2) = hp;
                    *(__nv_bfloat162*)(dL + base + wn*32 + nt*8 + cl2) = lp;
                }
            }
    } else {
        #pragma unroll
        for (int mt = 0; mt < 2; mt++)
            #pragma unroll
            for (int h2 = 0; h2 < 2; h2++) {
                int gr = row0 + wm*32 + mt*16 + rl4 + h2*8;
                size_t base = (size_t)gr*INNER + h*DHD + d0;
                #pragma unroll
                for (int nt = 0; nt < 4; nt++) {
                    __nv_bfloat162 hp;
                    hp.x = __float2bfloat16(acc[mt][nt][h2*2]);
                    hp.y = __float2bfloat16(acc[mt][nt][h2*2+1]);
                    *(__nv_bfloat162*)(g_vh + base + wn*32 + nt*8 + cl2) = hp;
                }
            }
    }
}

// FF1: grid (8, 64); gelu epilogue -> fh (single bf16)
__global__ __launch_bounds__(256) void k_ff1(
    const __nv_bfloat16* __restrict__ Ah, const __nv_bfloat16* __restrict__ Al,
    const __nv_bfloat16* __restrict__ Bh, const __nv_bfloat16* __restrict__ Bl,
    const float* __restrict__ bias)
{
    extern __shared__ __align__(16) char dsm[];
    __nv_bfloat16* sAh = (__nv_bfloat16*)dsm;
    __nv_bfloat16* sAl = sAh + 128*KP;
    __nv_bfloat16* sBh = sAl + 128*KP;
    __nv_bfloat16* sBl = sBh + 64*KP;
    const int t = threadIdx.x, w = t >> 5, lane = t & 31;
    const int wm = w & 3, wn = w >> 2;
    const int row0 = blockIdx.y*128, col0 = blockIdx.x*64;
    const int lrow = (lane & 15), lcol8 = (lane >> 4)*8;
    float acc[2][4][4] = {};

    MAINLOOP_64COL(sAh, sAl, sBh, sBl, Ah, Al, Bh, Bl, row0, col0, acc);

    const int rl4 = lane >> 2, cl2 = (lane & 3)*2;
    #pragma unroll
    for (int mt = 0; mt < 2; mt++)
        #pragma unroll
        for (int h2 = 0; h2 < 2; h2++) {
            int gr = row0 + wm*32 + mt*16 + rl4 + h2*8;
            #pragma unroll
            for (int nt = 0; nt < 4; nt++) {
                int gc = col0 + wn*32 + nt*8 + cl2;
                __nv_bfloat162 hp;
                hp.x = __float2bfloat16(gelu(acc[mt][nt][h2*2]   + bias[gc]));
                hp.y = __float2bfloat16(gelu(acc[mt][nt][h2*2+1] + bias[gc+1]));
                *(__nv_bfloat162*)(g_fh + (size_t)gr*FFD + gc) = hp;
            }
        }
}

// ==== HMMA GEMM 64x128, A single bf16 vs W hi/lo, double-buffered (WO/FF2) ====
// per buffer: A @0 (64 rows), Bh @64*SROW (128 rows), Bl @192*SROW -> 320*SROW
#define SROW 72
#define BUFSZ (320*SROW)
__global__ __launch_bounds__(256) void k_mma64(
    const __nv_bfloat16* __restrict__ A, int lda,
    const __nv_bfloat16* __restrict__ Bh, const __nv_bfloat16* __restrict__ Bl,
    int Ktot,
    const float* __restrict__ bias,
    float* __restrict__ out)
{
    extern __shared__ __align__(16) __nv_bfloat16 sb[];
    const int t = threadIdx.x, w = t >> 5, lane = t & 31;
    const int wm = w & 1, wn = w >> 1;
    const int row0 = blockIdx.y*64;
    float acc[2][4][4] = {};
    const int lrow = (lane & 15), lcol8 = (lane >> 4)*8;

    {
        #pragma unroll
        for (int i = 0; i < 2; i++) {
            int f = i*256 + t;
            int r = f >> 3, c8 = (f & 7) << 3;
            *(uint4*)(sb + r*SROW + c8) = *(const uint4*)(A + (size_t)(row0+r)*lda + c8);
        }
        #pragma unroll
        for (int i = 0; i < 4; i++) {
            int f = i*256 + t;
            int r = f >> 3, c8 = (f & 7) << 3;
            *(uint4*)(sb + 64*SROW + r*SROW + c8)  = *(const uint4*)(Bh + (size_t)r*Ktot + c8);
            *(uint4*)(sb + 192*SROW + r*SROW + c8) = *(const uint4*)(Bl + (size_t)r*Ktot + c8);
        }
    }
    __syncthreads();
    int buf = 0;

    for (int kc = 64; kc <= Ktot; kc += 64) {
        uint4 ra[2], rb[2][4];
        if (kc < Ktot) {
            #pragma unroll
            for (int i = 0; i < 2; i++) {
                int f = i*256 + t;
                int r = f >> 3, c8 = (f & 7) << 3;
                ra[i] = *(const uint4*)(A + (size_t)(row0+r)*lda + kc + c8);
            }
            #pragma unroll
            for (int i = 0; i < 4; i++) {
                int f = i*256 + t;
                int r = f >> 3, c8 = (f & 7) << 3;
                rb[0][i] = *(const uint4*)(Bh + (size_t)r*Ktot + kc + c8);
                rb[1][i] = *(const uint4*)(Bl + (size_t)r*Ktot + kc + c8);
            }
        }
        const __nv_bfloat16* cb = sb + buf*BUFSZ;
        #pragma unroll
        for (int ks = 0; ks < 4; ks++) {
            int kcol = ks*16 + lcol8;
            uint32_t a[2][4];
            #pragma unroll
            for (int mt = 0; mt < 2; mt++) {
                int arow = wm*32 + mt*16 + lrow;
                ldsm4(a[mt], s2u(cb + arow*SROW + kcol));
            }
            #pragma unroll
            for (int nt2 = 0; nt2 < 2; nt2++) {
                int brow = wn*32 + nt2*16 + lrow;
                uint32_t rh[4], rl[4];
                ldsm4(rh, s2u(cb + 64*SROW + brow*SROW + kcol));
                ldsm4(rl, s2u(cb + 192*SROW + brow*SROW + kcol));
                uint32_t b0h[2] = {rh[0], rh[2]}, b1h[2] = {rh[1], rh[3]};
                uint32_t b0l[2] = {rl[0], rl[2]}, b1l[2] = {rl[1], rl[3]};
                #pragma unroll
                for (int mt = 0; mt < 2; mt++)
                    MMA2x2B(acc[mt][nt2*2], acc[mt][nt2*2+1], a[mt], b0h, b0l, b1h, b1l);
            }
        }
        if (kc < Ktot) {
            __nv_bfloat16* nb = sb + (buf^1)*BUFSZ;
            #pragma unroll
            for (int i = 0; i < 2; i++) {
                int f = i*256 + t;
                int r = f >> 3, c8 = (f & 7) << 3;
                *(uint4*)(nb + r*SROW + c8) = ra[i];
            }
            #pragma unroll
            for (int i = 0; i < 4; i++) {
                int f = i*256 + t;
                int r = f >> 3, c8 = (f & 7) << 3;
                *(uint4*)(nb + 64*SROW + r*SROW + c8)  = rb[0][i];
                *(uint4*)(nb + 192*SROW + r*SROW + c8) = rb[1][i];
            }
            __syncthreads();
            buf ^= 1;
        }
    }

    const int rl4 = lane >> 2, cl2 = (lane & 3)*2;
    #pragma unroll
    for (int mt = 0; mt < 2; mt++)
        #pragma unroll
        for (int h2 = 0; h2 < 2; h2++) {
            int gr = row0 + wm*32 + mt*16 + rl4 + h2*8;
            #pragma unroll
            for (int nt = 0; nt < 4; nt++) {
                int gc = wn*32 + nt*8 + cl2;
                size_t idx = (size_t)gr*DIMC + gc;
                float2 v = *(float2*)(out + idx);
                v.x += acc[mt][nt][h2*2]   + bias[gc];
                v.y += acc[mt][nt][h2*2+1] + bias[gc+1];
                *(float2*)(out + idx) = v;
            }
        }
}

// ---------------- embed ----------------
__global__ void k_embed(const float* __restrict__ x, const float* __restrict__ lw,
                        const float* __restrict__ lb, const float* __restrict__ pe)
{
    int warp = threadIdx.x >> 5, lane = threadIdx.x & 31;
    int r = blockIdx.x*8 + warp;
    float xv = x[r];
    float4 l4 = ((const float4*)lw)[lane];
    float4 b4 = ((const float4*)lb)[lane];
    float4 p4 = ((const float4*)(pe + (size_t)(r % SS)*DIMC))[lane];
    float4 o4 = { xv*l4.x + b4.x + p4.x, xv*l4.y + b4.y + p4.y,
                  xv*l4.z + b4.z + p4.z, xv*l4.w + b4.w + p4.w };
    ((float4*)(g_h + (size_t)r*DIMC))[lane] = o4;
}

// ---------------- layernorm -> bf16 hi/lo ----------------
__global__ void k_ln(const float* __restrict__ in, const float* __restrict__ g,
                     const float* __restrict__ b,
                     __nv_bfloat16* __restrict__ outH, __nv_bfloat16* __restrict__ outL)
{
    int warp = threadIdx.x >> 5, lane = threadIdx.x & 31;
    int r = blockIdx.x*8 + warp;
    float4 v = ((const float4*)(in + (size_t)r*DIMC))[lane];
    float s = v.x + v.y + v.z + v.w;
    #pragma unroll
    for (int o = 16; o > 0; o >>= 1) s += __shfl_xor_sync(0xffffffffu, s, o);
    float mu = s * (1.0f/DIMC);
    float dx = v.x-mu, dy = v.y-mu, dz = v.z-mu, dw = v.w-mu;
    float q = dx*dx + dy*dy + dz*dz + dw*dw;
    #pragma unroll
    for (int o = 16; o > 0; o >>= 1) q += __shfl_xor_sync(0xffffffffu, q, o);
    float inv = rsqrtf(q*(1.0f/DIMC) + 1e-5f);
    float4 gv = ((const float4*)g)[lane];
    float4 bv = ((const float4*)b)[lane];
    float o4[4] = { dx*inv*gv.x + bv.x, dy*inv*gv.y + bv.y,
                    dz*inv*gv.z + bv.z, dw*inv*gv.w + bv.w };
    __nv_bfloat16 hh[4], ll[4];
    #pragma unroll
    for (int j = 0; j < 4; j++) split_bf16(o4[j], hh[j], ll[j]);
    size_t base = (size_t)r*DIMC + lane*4;
    *(uint2*)(outH+base) = *(uint2*)hh;
    *(uint2*)(outL+base) = *(uint2*)ll;
}

// -------- unified weight prep --------
__global__ __launch_bounds__(256) void k_wprep(
    const float* __restrict__ wq, const float* __restrict__ wk,
    const float* __restrict__ wv, const float* __restrict__ wo,
    const float* __restrict__ ff1_w, const float* __restrict__ ff2_w,
    const float* __restrict__ proj)
{
    __shared__ float tile[32][33];
    int bid = blockIdx.x;
    int l = (bid >= 656) ? 1 : 0;
    bid -= l*656;
    size_t wb = (size_t)l*WT_LAYER;
    __nv_bfloat16* wth = g_wth + wb;
    __nv_bfloat16* wtl = g_wtl + wb;

    const float* W; __nv_bfloat16 *oH, *oL; int K, N, tidx;
    if (bid < 384) {
        int which = bid >> 7; tidx = bid & 127;
        W = (which == 0 ? wq : which == 1 ? wk : wv) + (size_t)l*DIMC*INNER;
        oH = wth + (which == 0 ? WT_Q : which == 1 ? WT_K : WT_V);
        oL = wtl + (which == 0 ? WT_Q : which == 1 ? WT_K : WT_V);
        K = DIMC; N = INNER;
    } else if (bid < 512) {
        tidx = bid - 384;
        W = wo + (size_t)l*INNER*DIMC;
        oH = wth + WT_O; oL = wtl + WT_O;
        K = INNER; N = DIMC;
    } else if (bid < 576) {
        tidx = bid - 512;
        W = ff1_w + (size_t)l*DIMC*FFD;
        oH = wth + WT_F1; oL = wtl + WT_F1;
        K = DIMC; N = FFD;
    } else if (bid < 640) {
        tidx = bid - 576;
        W = ff2_w + (size_t)l*FFD*DIMC;
        oH = wth + WT_F2; oL = wtl + WT_F2;
        K = FFD; N = DIMC;
    } else {
        int e4 = (bid - 640)*256 + threadIdx.x;
        float4 v = ((const float4*)(proj + (size_t)l*MF*DHD))[e4];
        __nv_bfloat16 hh[4], ll[4];
        split_bf16(v.x, hh[0], ll[0]); split_bf16(v.y, hh[1], ll[1]);
        split_bf16(v.z, hh[2], ll[2]); split_bf16(v.w, hh[3], ll[3]);
        *(uint2*)(wth + WT_PJ + e4*4) = *(uint2*)hh;
        *(uint2*)(wtl + WT_PJ + e4*4) = *(uint2*)ll;
        return;
    }
    int ntiles = N >> 5;
    int n0 = (tidx % ntiles)*32, k0 = (tidx / ntiles)*32;
    int tx = threadIdx.x & 31, ty = threadIdx.x >> 5;
    #pragma unroll
    for (int i = ty; i < 32; i += 8)
        tile[i][tx] = W[(size_t)(k0+i)*N + n0 + tx];
    __syncthreads();
    #pragma unroll
    for (int i = ty; i < 32; i += 8) {
        float v = tile[tx][i];
        __nv_bfloat16 hh, ll;
        split_bf16(v, hh, ll);
        oH[(size_t)(n0+i)*K + k0 + tx] = hh;
        oL[(size_t)(n0+i)*K + k0 + tx] = ll;
    }
}

// ================= chunk-local attention via HMMA, 512 threads =================
#define CP 136
__global__ __launch_bounds__(512) void k_chunk(
    const __nv_bfloat16* __restrict__ qph, const __nv_bfloat16* __restrict__ qpl)
{
    extern __shared__ __align__(16) __nv_bfloat16 cs[];
    __nv_bfloat16* sQh = cs;
    __nv_bfloat16* sQl = sQh + 128*CP;
    __nv_bfloat16* sKh = sQl + 128*CP;
    __nv_bfloat16* sKl = sKh + 128*CP;
    __nv_bfloat16* sV  = sKl + 128*CP;
    __shared__ float s_den[4][128];
    __shared__ float s_dg[128];

    int blk = blockIdx.x, bh = blk >> 4, c = blk & 15;
    int b = bh >> 3, hh = bh & 7;
    int t = threadIdx.x, w = t >> 5, lane = t & 31;
    int wm = w & 3, wn = w >> 2;
    const int lrow = lane & 15, lcol8 = (lane >> 4)*8;
    const int rl4 = lane >> 2, cl2 = (lane & 3)*2;

    const size_t qbase = ((size_t)bh*SS + c*CHUNK)*MF;
    if (t < 128) {
        float st = g_bmax[bh*16];
        #pragma unroll
        for (int i = 1; i < 16; i++) st = fmaxf(st, g_bmax[bh*16 + i]);
        s_dg[t] = g_diagk[(size_t)bh*SS + c*CHUNK + t] + st;
    }
    for (int i = t; i < 2048; i += 512) {
        int r = i >> 4, c8 = (i & 15) << 3;
        *(uint4*)(sQh + r*CP + c8) = *(const uint4*)(qph + qbase + r*MF + c8);
        *(uint4*)(sQl + r*CP + c8) = *(const uint4*)(qpl + qbase + r*MF + c8);
        size_t vsrc = (size_t)(b*SS + c*CHUNK + r)*INNER + hh*DHD + c8;
        *(uint4*)(sV + r*CP + c8) = *(const uint4*)(g_vh + vsrc);
    }
    __syncthreads();
    for (int f = t; f < 4096; f += 512) {
        int r = f >> 5, c4 = (f & 31) << 2;
        float4 dv = *(const float4*)(g_kp + qbase + (size_t)r*MF + c4);
        float dgv = s_dg[r];
        float o0 = RATIOC*(expf(dv.x - dgv) + 1e-4f);
        float o1 = RATIOC*(expf(dv.y - dgv) + 1e-4f);
        float o2 = RATIOC*(expf(dv.z - dgv) + 1e-4f);
        float o3 = RATIOC*(expf(dv.w - dgv) + 1e-4f);
        __nv_bfloat16 hh4[4], ll4[4];
        split_bf16(o0, hh4[0], ll4[0]); split_bf16(o1, hh4[1], ll4[1]);
        split_bf16(o2, hh4[2], ll4[2]); split_bf16(o3, hh4[3], ll4[3]);
        *(uint2*)(sKh + r*CP + c4) = *(uint2*)hh4;
        *(uint2*)(sKl + r*CP + c4) = *(uint2*)ll4;
    }
    __syncthreads();

    // ---- phase 1: attn = Q@K^T (full hi/lo) ----
    float acc[2][4][4] = {};
    if (wn <= wm) {
        #pragma unroll
        for (int ks = 0; ks < 8; ks++) {
            int kcol = ks*16 + lcol8;
            uint32_t ah[2][4], al[2][4];
            #pragma unroll
            for (int mt = 0; mt < 2; mt++) {
                int arow = wm*32 + mt*16 + lrow;
                ldsm4(ah[mt], s2u(sQh + arow*CP + kcol));
                ldsm4(al[mt], s2u(sQl + arow*CP + kcol));
            }
            #pragma unroll
            for (int nt2 = 0; nt2 < 2; nt2++) {
                int brow = wn*32 + nt2*16 + lrow;
                uint32_t rh[4], rl[4];
                ldsm4(rh, s2u(sKh + brow*CP + kcol));
                ldsm4(rl, s2u(sKl + brow*CP + kcol));
                uint32_t b0h[2] = {rh[0], rh[2]}, b1h[2] = {rh[1], rh[3]};
                uint32_t b0l[2] = {rl[0], rl[2]}, b1l[2] = {rl[1], rl[3]};
                #pragma unroll
                for (int mt = 0; mt < 2; mt++)
                    MMA3x2(acc[mt][nt2*2], acc[mt][nt2*2+1], ah[mt], al[mt], b0h, b0l, b1h, b1l);
            }
        }
    }
    float dp[2][2] = {};
    #pragma unroll
    for (int mt = 0; mt < 2; mt++)
        #pragma unroll
        for (int nt = 0; nt < 4; nt++)
            #pragma unroll
            for (int f = 0; f < 4; f++) {
                int i = wm*32 + mt*16 + rl4 + ((f>>1)<<3);
                int j = wn*32 + nt*8 + cl2 + (f&1);
                if (j > i) acc[mt][nt][f] = 0.f;
                dp[mt][f>>1] += acc[mt][nt][f];
            }
    #pragma unroll
    for (int o = 1; o < 4; o <<= 1)
        #pragma unroll
        for (int mt = 0; mt < 2; mt++)
            #pragma unroll
            for (int h2 = 0; h2 < 2; h2++)
                dp[mt][h2] += __shfl_xor_sync(0xffffffffu, dp[mt][h2], o);
    if ((lane & 3) == 0) {
        #pragma unroll
        for (int mt = 0; mt < 2; mt++)
            #pragma unroll
            for (int h2 = 0; h2 < 2; h2++)
                s_den[wn][wm*32 + mt*16 + rl4 + h2*8] = dp[mt][h2];
    }
    __syncthreads();

    #pragma unroll
    for (int mt = 0; mt < 2; mt++)
        #pragma unroll
        for (int nt = 0; nt < 4; nt++)
            #pragma unroll
            for (int f = 0; f < 4; f++) {
                int i = wm*32 + mt*16 + rl4 + ((f>>1)<<3);
                int j = wn*32 + nt*8 + cl2 + (f&1);
                __nv_bfloat16 hh2, ll2;
                split_bf16(acc[mt][nt][f], hh2, ll2);
                sQh[i*CP + j] = hh2;
                sQl[i*CP + j] = ll2;
            }
    if (t < 128) {
        g_den[(size_t)bh*SS + c*CHUNK + t] = s_den[0][t] + s_den[1][t] + s_den[2][t] + s_den[3][t];
        float kssum = 0.f;
        for (int j = 0; j < 128; j++)
            kssum += __bfloat162float(sKh[j*CP + t]) + __bfloat162float(sKl[j*CP + t]);
        g_ksc[((size_t)bh*NC + c)*MF + t] = kssum;
    }
    __syncthreads();

    // ---- phase 2: num = attn(hi/lo) @ V(single) ----
    #pragma unroll
    for (int mt = 0; mt < 2; mt++)
        #pragma unroll
        for (int nt = 0; nt < 4; nt++)
            #pragma unroll
            for (int f = 0; f < 4; f++) acc[mt][nt][f] = 0.f;
    #pragma unroll
    for (int ks = 0; ks < 8; ks++) {
        int kcol = ks*16 + lcol8;
        uint32_t ah[2][4], al[2][4];
        #pragma unroll
        for (int mt = 0; mt < 2; mt++) {
            int arow = wm*32 + mt*16 + lrow;
            ldsm4(ah[mt], s2u(sQh + arow*CP + kcol));
            ldsm4(al[mt], s2u(sQl + arow*CP + kcol));
        }
        #pragma unroll
        for (int nt2 = 0; nt2 < 2; nt2++) {
            int nbase = wn*32 + nt2*16;
            uint32_t dh[4];
            ldsm4t(dh, taddr(sV, CP, ks*16, nbase, lane));
            uint32_t b0[2] = {dh[0], dh[2]}, b1[2] = {dh[1], dh[3]};
            #pragma unroll
            for (int mt = 0; mt < 2; mt++)
                MMA2x2(acc[mt][nt2*2], acc[mt][nt2*2+1], ah[mt], al[mt], b0, b1);
        }
    }
    #pragma unroll
    for (int mt = 0; mt < 2; mt++)
        #pragma unroll
        for (int h2 = 0; h2 < 2; h2++) {
            int i = wm*32 + mt*16 + rl4 + h2*8;
            size_t base = ((size_t)(b*SS + c*CHUNK + i)*HH + hh)*DHD;
            #pragma unroll
            for (int nt = 0; nt < 4; nt++) {
                float2 vv = {acc[mt][nt][h2*2], acc[mt][nt][h2*2+1]};
                *(float2*)(g_o + base + wn*32 + nt*8 + cl2) = vv;
            }
        }

    // ---- phase 3: kv = K^T(hi/lo) @ V(single) ----
    #pragma unroll
    for (int mt = 0; mt < 2; mt++)
        #pragma unroll
        for (int nt = 0; nt < 4; nt++)
            #pragma unroll
            for (int f = 0; f < 4; f++) acc[mt][nt][f] = 0.f;
    #pragma unroll
    for (int ks = 0; ks < 8; ks++) {
        uint32_t ah[2][4], al[2][4];
        #pragma unroll
        for (int mt = 0; mt < 2; mt++) {
            int mbase = wm*32 + mt*16;
            ldsm4t(ah[mt], taddr(sKh, CP, ks*16, mbase, lane));
            ldsm4t(al[mt], taddr(sKl, CP, ks*16, mbase, lane));
        }
        #pragma unroll
        for (int nt2 = 0; nt2 < 2; nt2++) {
            int nbase = wn*32 + nt2*16;
            uint32_t dh[4];
            ldsm4t(dh, taddr(sV, CP, ks*16, nbase, lane));
            uint32_t b0[2] = {dh[0], dh[2]}, b1[2] = {dh[1], dh[3]};
            #pragma unroll
            for (int mt = 0; mt < 2; mt++)
                MMA2x2(acc[mt][nt2*2], acc[mt][nt2*2+1], ah[mt], al[mt], b0, b1);
        }
    }
    {
        size_t kvbase = ((size_t)bh*NC + c)*(MF*DHD);
        #pragma unroll
        for (int mt = 0; mt < 2; mt++)
            #pragma unroll
            for (int h2 = 0; h2 < 2; h2++) {
                int m = wm*32 + mt*16 + rl4 + h2*8;
                #pragma unroll
                for (int nt = 0; nt < 4; nt++) {
                    float2 vv = {acc[mt][nt][h2*2], acc[mt][nt][h2*2+1]};
                    *(float2*)(g_kvc + kvbase + (size_t)m*DHD + wn*32 + nt*8 + cl2) = vv;
                }
            }
    }
}

// ---------------- exclusive prefix over chunks (single bf16 kvp) ----------------
__global__ void k_prefix()
{
    int bh = blockIdx.x, seg = blockIdx.y, t = threadIdx.x;
    for (int e = seg*2048 + t; e < (seg+1)*2048; e += 256) {
        float run = 0.f;
        #pragma unroll
        for (int c = 0; c < NC; c++) {
            size_t idx = ((size_t)bh*NC + c)*(MF*DHD) + e;
            g_kvph[idx] = __float2bfloat16(run);
            run += g_kvc[idx];
        }
    }
    if (seg == 0) {
        for (int e = t; e < MF; e += 256) {
            float run = 0.f;
            #pragma unroll
            for (int c = 0; c < NC; c++) {
                size_t idx = ((size_t)bh*NC + c)*MF + e;
                g_ksp[idx] = run; run += g_ksc[idx];
            }
        }
    }
}

// ========== cross = qp(hi/lo) @ kvp(single), + num, normalize -> oh (single) ==========
__global__ __launch_bounds__(512) void k_cross(
    const __nv_bfloat16* __restrict__ qph, const __nv_bfloat16* __restrict__ qpl)
{
    extern __shared__ __align__(16) __nv_bfloat16 cs[];
    __nv_bfloat16* sQh = cs;
    __nv_bfloat16* sQl = sQh + 128*CP;
    __nv_bfloat16* sP  = sQl + 128*CP;
    __shared__ float s_ks[128];
    __shared__ float s_dc[128];

    int blk = blockIdx.x, bh = blk >> 4, c = blk & 15;
    int b = bh >> 3, hh = bh & 7;
    int t = threadIdx.x, w = t >> 5, lane = t & 31;
    int wm = w & 3, wn = w >> 2;
    const int lrow = lane & 15, lcol8 = (lane >> 4)*8;
    const int rl4 = lane >> 2, cl2 = (lane & 3)*2;

    const size_t qbase = ((size_t)bh*SS + c*CHUNK)*MF;
    const size_t pbase = ((size_t)bh*NC + c)*(MF*DHD);
    for (int i = t; i < 2048; i += 512) {
        int r = i >> 4, c8 = (i & 15) << 3;
        *(uint4*)(sQh + r*CP + c8) = *(const uint4*)(qph + qbase + r*MF + c8);
        *(uint4*)(sQl + r*CP + c8) = *(const uint4*)(qpl + qbase + r*MF + c8);
        *(uint4*)(sP  + r*CP + c8) = *(const uint4*)(g_kvph + pbase + r*DHD + c8);
    }
    if (t < 128) s_ks[t] = g_ksp[((size_t)bh*NC + c)*MF + t];
    __syncthreads();
    if (t < 128) {
        float dc = 0.f;
        for (int m = 0; m < 128; m++)
            dc += (__bfloat162float(sQh[t*CP + m]) + __bfloat162float(sQl[t*CP + m]))*s_ks[m];
        s_dc[t] = g_den[(size_t)bh*SS + c*CHUNK + t] + dc + 1e-6f;
    }
    __syncthreads();

    float acc[2][4][4] = {};
    #pragma unroll
    for (int ks = 0; ks < 8; ks++) {
        int kcol = ks*16 + lcol8;
        uint32_t ah[2][4], al[2][4];
        #pragma unroll
        for (int mt = 0; mt < 2; mt++) {
            int arow = wm*32 + mt*16 + lrow;
            ldsm4(ah[mt], s2u(sQh + arow*CP + kcol));
            ldsm4(al[mt], s2u(sQl + arow*CP + kcol));
        }
        #pragma unroll
        for (int nt2 = 0; nt2 < 2; nt2++) {
            int nbase = wn*32 + nt2*16;
            uint32_t dh[4];
            ldsm4t(dh, taddr(sP, CP, ks*16, nbase, lane));
            uint32_t b0[2] = {dh[0], dh[2]}, b1[2] = {dh[1], dh[3]};
            #pragma unroll
            for (int mt = 0; mt < 2; mt++)
                MMA2x2(acc[mt][nt2*2], acc[mt][nt2*2+1], ah[mt], al[mt], b0, b1);
        }
    }
    #pragma unroll
    for (int mt = 0; mt < 2; mt++)
        #pragma unroll
        for (int h2 = 0; h2 < 2; h2++) {
            int i = wm*32 + mt*16 + rl4 + h2*8;
            float inv = 1.0f / s_dc[i];
            size_t base = ((size_t)(b*SS + c*CHUNK + i)*HH + hh)*DHD;
            #pragma unroll
            for (int nt = 0; nt < 4; nt++) {
                size_t idx = base + wn*32 + nt*8 + cl2;
                float2 nn = *(float2*)(g_o + idx);
                __nv_bfloat162 hp;
                hp.x = __float2bfloat16((nn.x + acc[mt][nt][h2*2])   * inv);
                hp.y = __float2bfloat16((nn.y + acc[mt][nt][h2*2+1]) * inv);
                *(__nv_bfloat162*)(g_oh + idx) = hp;
            }
        }
}

// ---------------- pooling ----------------
__global__ void k_pool()
{
    int b = blockIdx.x, seg = blockIdx.y, t = threadIdx.x;
    float acc = 0.f;
    for (int s = seg*128; s < (seg+1)*128; s++) acc += g_h[((size_t)b*SS + s)*DIMC + t];
    g_pp[(b*16 + seg)*DIMC + t] = acc;
}

__global__ void k_final(const float* __restrict__ fw, const float* __restrict__ fb,
                        float* __restrict__ out)
{
    __shared__ float pooled[BB*DIMC];
    int t = threadIdx.x;
    for (int b = 0; b < BB; b++) {
        float a = 0.f;
        #pragma unroll
        for (int s = 0; s < 16; s++) a += g_pp[(b*16 + s)*DIMC + t];
        pooled[b*DIMC + t] = a * (1.0f/SS);
    }
    __syncthreads();
    if (t < BB*NCLS) {
        int b = t / NCLS, c = t % NCLS;
        float acc = fb[c];
        for (int d = 0; d < DIMC; d++) acc += pooled[b*DIMC + d]*fw[d*NCLS + c];
        out[t] = acc;
    }
}

// ---------------- host driver ----------------
static void* sym(const void* s) { void* p = nullptr; cudaGetSymbolAddress(&p, s); return p; }

extern "C" void kernel_launch(void* const* d_in, const int* in_sizes, int n_in,
                              void* d_out, int out_size)
{
    const float* x     = (const float*)d_in[0];
    const float* lin_w = (const float*)d_in[1];
    const float* lin_b = (const float*)d_in[2];
    const float* pe    = (const float*)d_in[3];
    const float* proj  = (const float*)d_in[4];
    const float* ln1_g = (const float*)d_in[5];
    const float* ln1_b = (const float*)d_in[6];
    const float* wq    = (const float*)d_in[7];
    const float* wk    = (const float*)d_in[8];
    const float* wv    = (const float*)d_in[9];
    const float* wo    = (const float*)d_in[10];
    const float* wo_b  = (const float*)d_in[11];
    const float* ln2_g = (const float*)d_in[12];
    const float* ln2_b = (const float*)d_in[13];
    const float* ff1_w = (const float*)d_in[14];
    const float* ff1_b = (const float*)d_in[15];
    const float* ff2_w = (const float*)d_in[16];
    const float* ff2_b = (const float*)d_in[17];
    const float* fin_w = (const float*)d_in[18];
    const float* fin_b = (const float*)d_in[19];
    float* out = (float*)d_out;

    float* ph   = (float*)sym(g_h);
    float* pkp  = (float*)sym(g_kp);
    float* pbm  = (float*)sym(g_bmax);

    __nv_bfloat16* yh  = (__nv_bfloat16*)sym(g_yh);
    __nv_bfloat16* yl  = (__nv_bfloat16*)sym(g_yl);
    __nv_bfloat16* wth = (__nv_bfloat16*)sym(g_wth);
    __nv_bfloat16* wtl = (__nv_bfloat16*)sym(g_wtl);
    __nv_bfloat16* qnh = (__nv_bfloat16*)sym(g_qnh);
    __nv_bfloat16* qnl = (__nv_bfloat16*)sym(g_qnl);
    __nv_bfloat16* knh = (__nv_bfloat16*)sym(g_knh);
    __nv_bfloat16* knl = (__nv_bfloat16*)sym(g_knl);
    __nv_bfloat16* qp_h = (__nv_bfloat16*)sym(g_qph);
    __nv_bfloat16* qp_l = (__nv_bfloat16*)sym(g_qpl);
    __nv_bfloat16* oh  = (__nv_bfloat16*)sym(g_oh);
    __nv_bfloat16* fh  = (__nv_bfloat16*)sym(g_fh);

    const int SMEM_MMA   = 4*128*KP*2;           // 139264 (features)
    const int SMEM_QKVFF = QKV_SMEM;             // 104448 (2 CTAs/SM)
    const int SMEM_MMA64 = 2*BUFSZ*2;            // 92160 (2 CTAs/SM)
    const int SMEM_CHUNK = 5*128*CP*2;           // 174080
    const int SMEM_CROSS = 3*128*CP*2;           // 104448
    cudaFuncSetAttribute(k_mmaF, cudaFuncAttributeMaxDynamicSharedMemorySize, SMEM_MMA);
    cudaFuncSetAttribute(k_mmaqkv64, cudaFuncAttributeMaxDynamicSharedMemorySize, SMEM_QKVFF);
    cudaFuncSetAttribute(k_ff1, cudaFuncAttributeMaxDynamicSharedMemorySize, SMEM_QKVFF);
    cudaFuncSetAttribute(k_mma64, cudaFuncAttributeMaxDynamicSharedMemorySize, SMEM_MMA64);
    cudaFuncSetAttribute(k_chunk, cudaFuncAttributeMaxDynamicSharedMemorySize, SMEM_CHUNK);
    cudaFuncSetAttribute(k_cross, cudaFuncAttributeMaxDynamicSharedMemorySize, SMEM_CROSS);

    k_wprep<<<2*656, 256>>>(wq, wk, wv, wo, ff1_w, ff2_w, proj);
    k_embed<<<BSR/8, 256>>>(x, lin_w, lin_b, pe);

    for (int l = 0; l < DEPTH; l++) {
        size_t wb = (size_t)l*WT_LAYER;

        k_ln<<<BSR/8, 256>>>(ph, ln1_g + l*DIMC, ln1_b + l*DIMC, yh, yl);

        k_mmaqkv64<<<dim3(48,64), 256, SMEM_QKVFF>>>(yh, yl, wth+wb+WT_Q, wtl+wb+WT_Q);

        k_mmaF<<<dim3(2,512), 256, SMEM_MMA>>>(knh, knl, qnh, qnl,
                                               wth+wb+WT_PJ, wtl+wb+WT_PJ,
                                               pkp, qp_h, qp_l, pbm);

        k_chunk<<<NBH*NC, 512, SMEM_CHUNK>>>(qp_h, qp_l);
        k_prefix<<<dim3(NBH, 8), 256>>>();
        k_cross<<<NBH*NC, 512, SMEM_CROSS>>>(qp_h, qp_l);

        k_mma64<<<dim3(1,BSR/64), 256, SMEM_MMA64>>>(oh, INNER, wth+wb+WT_O, wtl+wb+WT_O, INNER,
                                                     wo_b + l*DIMC, ph);

        k_ln<<<BSR/8, 256>>>(ph, ln2_g + l*DIMC, ln2_b + l*DIMC, yh, yl);
        k_ff1<<<dim3(8,64), 256, SMEM_QKVFF>>>(yh, yl, wth+wb+WT_F1, wtl+wb+WT_F1, ff1_b + l*FFD);
        k_mma64<<<dim3(1,BSR/64), 256, SMEM_MMA64>>>(fh, FFD, wth+wb+WT_F2, wtl+wb+WT_F2, FFD,
                                                     ff2_b + l*DIMC, ph);
    }

    k_pool<<<dim3(BB, 16), 128>>>();
    k_final<<<1, 128>>>(fin_w, fin_b, out);
}

// round 17
// speedup vs baseline: 1.2438x; 1.0464x over previous
#include <cuda_runtime.h>
#include <cuda_bf16.h>
#include <math.h>
#include <stdint.h>

// ---------------- problem constants ----------------
#define BB 4
#define SS 2048
#define DIMC 128
#define HH 8
#define DHD 128
#define DEPTH 2
#define NCLS 10
#define MF 128
#define CHUNK 128
#define NC 16
#define INNER 1024
#define FFD 512
#define BSR 8192
#define BHS 65536
#define NBH 32

#define NORMC 0.29730177875068026f
#define RATIOC 0.08838834764831845f

// ---------------- device scratch (fp32) ----------------
__device__ float g_h  [BSR*DIMC];
__device__ float g_kp [(size_t)NBH*SS*MF];
__device__ float g_diagk[BHS];
__device__ float g_bmax[NBH*16];
__device__ float g_o  [BSR*INNER];
__device__ float g_den[BHS];
__device__ float g_kvc[(size_t)NBH*NC*MF*DHD];
__device__ float g_ksc[NBH*NC*MF];
__device__ float g_ksp[NBH*NC*MF];
__device__ float g_pp [BB*16*DIMC];

// ---------------- device scratch (bf16) ----------------
__device__ __align__(256) __nv_bfloat16 g_yh [BSR*DIMC];
__device__ __align__(256) __nv_bfloat16 g_yl [BSR*DIMC];
__device__ __align__(256) __nv_bfloat16 g_wth[2*672000];
__device__ __align__(256) __nv_bfloat16 g_wtl[2*672000];
__device__ __align__(256) __nv_bfloat16 g_qnh[(size_t)BHS*DHD];
__device__ __align__(256) __nv_bfloat16 g_qnl[(size_t)BHS*DHD];
__device__ __align__(256) __nv_bfloat16 g_knh[(size_t)BHS*DHD];
__device__ __align__(256) __nv_bfloat16 g_knl[(size_t)BHS*DHD];
__device__ __align__(256) __nv_bfloat16 g_vh [(size_t)BSR*INNER];       // V: single bf16
__device__ __align__(256) __nv_bfloat16 g_qph[(size_t)NBH*SS*MF];
__device__ __align__(256) __nv_bfloat16 g_qpl[(size_t)NBH*SS*MF];
__device__ __align__(256) __nv_bfloat16 g_kvph[(size_t)NBH*NC*MF*DHD];  // kvp: single bf16
__device__ __align__(256) __nv_bfloat16 g_oh [(size_t)BSR*INNER];       // o: single bf16
__device__ __align__(256) __nv_bfloat16 g_fh [(size_t)BSR*FFD];         // f: single bf16

#define WT_Q  0
#define WT_K  131072
#define WT_V  262144
#define WT_O  393216
#define WT_F1 524288
#define WT_F2 589824
#define WT_PJ 655360
#define WT_LAYER 672000

// ---------------- warp MMA helpers ----------------
__device__ __forceinline__ uint32_t s2u(const void* p){
    uint32_t a;
    asm("{ .reg .u64 t; cvta.to.shared.u64 t, %1; cvt.u32.u64 %0, t; }" : "=r"(a) : "l"(p));
    return a;
}
__device__ __forceinline__ void ldsm4(uint32_t* r, uint32_t addr){
    asm volatile("ldmatrix.sync.aligned.m8n8.x4.shared.b16 {%0,%1,%2,%3}, [%4];"
                 : "=r"(r[0]),"=r"(r[1]),"=r"(r[2]),"=r"(r[3]) : "r"(addr));
}
__device__ __forceinline__ void ldsm4t(uint32_t* r, uint32_t addr){
    asm volatile("ldmatrix.sync.aligned.m8n8.x4.trans.shared.b16 {%0,%1,%2,%3}, [%4];"
                 : "=r"(r[0]),"=r"(r[1]),"=r"(r[2]),"=r"(r[3]) : "r"(addr));
}
__device__ __forceinline__ void mma_bf16(float* c, const uint32_t* a, const uint32_t* b){
    asm volatile("mma.sync.aligned.m16n8k16.row.col.f32.bf16.bf16.f32 "
                 "{%0,%1,%2,%3}, {%4,%5,%6,%7}, {%8,%9}, {%0,%1,%2,%3};"
                 : "+f"(c[0]),"+f"(c[1]),"+f"(c[2]),"+f"(c[3])
                 : "r"(a[0]),"r"(a[1]),"r"(a[2]),"r"(a[3]), "r"(b[0]),"r"(b[1]));
}
__device__ __forceinline__ void split_bf16(float v, __nv_bfloat16& h, __nv_bfloat16& l){
    h = __float2bfloat16(v);
    l = __float2bfloat16(v - __bfloat162float(h));
}
__device__ __forceinline__ float gelu(float xx){
    return 0.5f*xx*(1.0f + tanhf(0.7978845608028654f*(xx + 0.044715f*xx*xx*xx)));
}
__device__ __forceinline__ uint32_t taddr(const __nv_bfloat16* S, int P, int kbase, int nbase, int lane){
    int kk = (lane & 7) + ((lane >> 4) << 3);
    int nn = ((lane >> 3) & 1) << 3;
    return s2u(S + (size_t)(kbase + kk)*P + nbase + nn);
}
#define MMA3x2(accA, accB, ah_, al_, b0h_, b0l_, b1h_, b1l_) \
    do { mma_bf16(accA, ah_, b0h_); mma_bf16(accA, ah_, b0l_); mma_bf16(accA, al_, b0h_); \
         mma_bf16(accB, ah_, b1h_); mma_bf16(accB, ah_, b1l_); mma_bf16(accB, al_, b1h_); } while(0)
// A hi/lo vs single B
#define MMA2x2(accA, accB, ah_, al_, b0_, b1_) \
    do { mma_bf16(accA, ah_, b0_); mma_bf16(accA, al_, b0_); \
         mma_bf16(accB, ah_, b1_); mma_bf16(accB, al_, b1_); } while(0)
// single A vs B hi/lo
#define MMA2x2B(accA, accB, a_, b0h_, b0l_, b1h_, b1l_) \
    do { mma_bf16(accA, a_, b0h_); mma_bf16(accA, a_, b0l_); \
         mma_bf16(accB, a_, b1h_); mma_bf16(accB, a_, b1l_); } while(0)
// single A vs single B
#define MMA1x2(accA, accB, a_, b0_, b1_) \
    do { mma_bf16(accA, a_, b0_); mma_bf16(accB, a_, b1_); } while(0)

#define KP 136

// ======== merged feature GEMM (single-stage K=128) ========
__global__ __launch_bounds__(256) void k_mmaF(
    const __nv_bfloat16* __restrict__ Kh, const __nv_bfloat16* __restrict__ Kl,
    const __nv_bfloat16* __restrict__ Qh, const __nv_bfloat16* __restrict__ Ql,
    const __nv_bfloat16* __restrict__ Bh, const __nv_bfloat16* __restrict__ Bl,
    float* __restrict__ out,
    __nv_bfloat16* __restrict__ outH, __nv_bfloat16* __restrict__ outL,
    float* __restrict__ bmax)
{
    extern __shared__ __align__(16) char dsm[];
    __nv_bfloat16* sAh = (__nv_bfloat16*)dsm;
    __nv_bfloat16* sAl = sAh + 128*KP;
    __nv_bfloat16* sBh = sAl + 128*KP;
    __nv_bfloat16* sBl = sBh + 128*KP;
    __shared__ float s_rm[2][128];
    __shared__ float s_red[256];
    __shared__ float s_dg[128];

    const int MODE = (blockIdx.x == 0) ? 4 : 3;
    const __nv_bfloat16* Ah = (MODE == 4) ? Kh : Qh;
    const __nv_bfloat16* Al = (MODE == 4) ? Kl : Ql;

    const int t = threadIdx.x, w = t >> 5, lane = t & 31;
    const int wm = w & 3, wn = w >> 2;
    const int row0 = blockIdx.y*128;

    float acc[2][8][4] = {};
    const int lrow = (lane & 15), lcol8 = (lane >> 4)*8;

    #pragma unroll
    for (int i = 0; i < 8; i++) {
        int f = i*256 + t;
        int r = f >> 4, c8 = (f & 15) << 3;
        *(uint4*)(sAh + r*KP + c8) = *(const uint4*)(Ah + (size_t)(row0+r)*128 + c8);
        *(uint4*)(sAl + r*KP + c8) = *(const uint4*)(Al + (size_t)(row0+r)*128 + c8);
        *(uint4*)(sBh + r*KP + c8) = *(const uint4*)(Bh + (size_t)r*128 + c8);
        *(uint4*)(sBl + r*KP + c8) = *(const uint4*)(Bl + (size_t)r*128 + c8);
    }
    __syncthreads();

    if (t < 128) {
        float dacc = 0.f;
        #pragma unroll
        for (int k8 = 0; k8 < 16; k8++) {
            uint4 uh = *(uint4*)(sAh + t*KP + k8*8);
            uint4 ul = *(uint4*)(sAl + t*KP + k8*8);
            const __nv_bfloat16* ph = (const __nv_bfloat16*)&uh;
            const __nv_bfloat16* pl = (const __nv_bfloat16*)&ul;
            #pragma unroll
            for (int j = 0; j < 8; j++) {
                float av = __bfloat162float(ph[j]) + __bfloat162float(pl[j]);
                dacc += av*av;
            }
        }
        if (MODE == 4) g_diagk[row0 + t] = 0.5f*dacc;
        else           s_dg[t] = 0.5f*dacc;
    }

    #pragma unroll
    for (int ks = 0; ks < 8; ks++) {
        int kcol = ks*16 + lcol8;
        uint32_t ah[2][4], al[2][4];
        #pragma unroll
        for (int mt = 0; mt < 2; mt++) {
            int arow = wm*32 + mt*16 + lrow;
            ldsm4(ah[mt], s2u(sAh + arow*KP + kcol));
            ldsm4(al[mt], s2u(sAl + arow*KP + kcol));
        }
        #pragma unroll
        for (int nt2 = 0; nt2 < 4; nt2++) {
            int brow = wn*64 + nt2*16 + lrow;
            uint32_t rh[4], rl[4];
            ldsm4(rh, s2u(sBh + brow*KP + kcol));
            ldsm4(rl, s2u(sBl + brow*KP + kcol));
            uint32_t b0h[2] = {rh[0], rh[2]}, b1h[2] = {rh[1], rh[3]};
            uint32_t b0l[2] = {rl[0], rl[2]}, b1l[2] = {rl[1], rl[3]};
            #pragma unroll
            for (int mt = 0; mt < 2; mt++)
                MMA3x2(acc[mt][nt2*2], acc[mt][nt2*2+1], ah[mt], al[mt], b0h, b0l, b1h, b1l);
        }
    }

    const int rl4 = lane >> 2, cl2 = (lane & 3)*2;

    if (MODE == 4) {
        float bm = -1e30f;
        #pragma unroll
        for (int mt = 0; mt < 2; mt++)
            #pragma unroll
            for (int h = 0; h < 2; h++) {
                int gr = row0 + wm*32 + mt*16 + rl4 + h*8;
                #pragma unroll
                for (int nt = 0; nt < 8; nt++) {
                    float2 v = {acc[mt][nt][h*2], acc[mt][nt][h*2+1]};
                    *(float2*)(out + (size_t)gr*MF + wn*64 + nt*8 + cl2) = v;
                    bm = fmaxf(bm, fmaxf(v.x, v.y));
                }
            }
        s_red[t] = bm; __syncthreads();
        #pragma unroll
        for (int o = 128; o > 0; o >>= 1) { if (t < o) s_red[t] = fmaxf(s_red[t], s_red[t+o]); __syncthreads(); }
        if (t == 0) bmax[blockIdx.y] = s_red[0];
    } else {
        float rm[2][2];
        #pragma unroll
        for (int mt = 0; mt < 2; mt++)
            #pragma unroll
            for (int h = 0; h < 2; h++) {
                float m = -1e30f;
                #pragma unroll
                for (int nt = 0; nt < 8; nt++)
                    m = fmaxf(m, fmaxf(acc[mt][nt][h*2], acc[mt][nt][h*2+1]));
                m = fmaxf(m, __shfl_xor_sync(0xffffffffu, m, 1));
                m = fmaxf(m, __shfl_xor_sync(0xffffffffu, m, 2));
                rm[mt][h] = m;
            }
        if ((lane & 3) == 0) {
            #pragma unroll
            for (int mt = 0; mt < 2; mt++)
                #pragma unroll
                for (int h = 0; h < 2; h++)
                    s_rm[wn][wm*32 + mt*16 + rl4 + h*8] = rm[mt][h];
        }
        __syncthreads();
        #pragma unroll
        for (int mt = 0; mt < 2; mt++)
            #pragma unroll
            for (int h = 0; h < 2; h++) {
                int lr = wm*32 + mt*16 + rl4 + h*8;
                int gr = row0 + lr;
                float rmax = fmaxf(s_rm[0][lr], s_rm[1][lr]);
                float dg = s_dg[lr];
                #pragma unroll
                for (int nt = 0; nt < 8; nt++) {
                    int gc = wn*64 + nt*8 + cl2;
                    float v0 = RATIOC*(expf(acc[mt][nt][h*2]  -dg-rmax) + 1e-4f);
                    float v1 = RATIOC*(expf(acc[mt][nt][h*2+1]-dg-rmax) + 1e-4f);
                    __nv_bfloat16 h0,l0,h1,l1;
                    split_bf16(v0,h0,l0); split_bf16(v1,h1,l1);
                    __nv_bfloat162 hp, lp;
                    hp.x = h0; hp.y = h1; lp.x = l0; lp.y = l1;
                    *(__nv_bfloat162*)(outH + (size_t)gr*MF + gc) = hp;
                    *(__nv_bfloat162*)(outL + (size_t)gr*MF + gc) = lp;
                }
            }
    }
}

// ======== 128x64-tile K=128 mainloop (2 CTAs/SM) — shared by QKV and FF1 ========
#define QKV_SMEM ((2*128 + 2*64)*KP*2)
#define MAINLOOP_64COL(sAh, sAl, sBh, sBl, Ah, Al, Bh, Bl, row0, col0, acc) \
    {   \
        _Pragma("unroll")                                                        \
        for (int i = 0; i < 8; i++) {                                            \
            int f = i*256 + threadIdx.x;                                         \
            int r = f >> 4, c8 = (f & 15) << 3;                                  \
            *(uint4*)(sAh + r*KP + c8) = *(const uint4*)(Ah + (size_t)(row0+r)*128 + c8); \
            *(uint4*)(sAl + r*KP + c8) = *(const uint4*)(Al + (size_t)(row0+r)*128 + c8); \
        }                                                                        \
        _Pragma("unroll")                                                        \
        for (int i = 0; i < 4; i++) {                                            \
            int f = i*256 + threadIdx.x;                                         \
            int r = f >> 4, c8 = (f & 15) << 3;                                  \
            *(uint4*)(sBh + r*KP + c8) = *(const uint4*)(Bh + (size_t)(col0+r)*128 + c8); \
            *(uint4*)(sBl + r*KP + c8) = *(const uint4*)(Bl + (size_t)(col0+r)*128 + c8); \
        }                                                                        \
        __syncthreads();                                                         \
        _Pragma("unroll")                                                        \
        for (int ks = 0; ks < 8; ks++) {                                         \
            int kcol = ks*16 + lcol8;                                            \
            uint32_t ah[2][4], al[2][4];                                         \
            _Pragma("unroll")                                                    \
            for (int mt = 0; mt < 2; mt++) {                                     \
                int arow = wm*32 + mt*16 + lrow;                                 \
                ldsm4(ah[mt], s2u(sAh + arow*KP + kcol));                        \
                ldsm4(al[mt], s2u(sAl + arow*KP + kcol));                        \
            }                                                                    \
            _Pragma("unroll")                                                    \
            for (int nt2 = 0; nt2 < 2; nt2++) {                                  \
                int brow = wn*32 + nt2*16 + lrow;                                \
                uint32_t rh[4], rl[4];                                           \
                ldsm4(rh, s2u(sBh + brow*KP + kcol));                            \
                ldsm4(rl, s2u(sBl + brow*KP + kcol));                            \
                uint32_t b0h[2] = {rh[0], rh[2]}, b1h[2] = {rh[1], rh[3]};       \
                uint32_t b0l[2] = {rl[0], rl[2]}, b1l[2] = {rl[1], rl[3]};       \
                _Pragma("unroll")                                                \
                for (int mt = 0; mt < 2; mt++)                                   \
                    MMA3x2(acc[mt][nt2*2], acc[mt][nt2*2+1], ah[mt], al[mt], b0h, b0l, b1h, b1l); \
            }                                                                    \
        }                                                                        \
    }

// QKV: grid (48, 64); epilogue scatters per part/head; V single bf16
__global__ __launch_bounds__(256) void k_mmaqkv64(
    const __nv_bfloat16* __restrict__ Ah, const __nv_bfloat16* __restrict__ Al,
    const __nv_bfloat16* __restrict__ Bh, const __nv_bfloat16* __restrict__ Bl)
{
    extern __shared__ __align__(16) char dsm[];
    __nv_bfloat16* sAh = (__nv_bfloat16*)dsm;
    __nv_bfloat16* sAl = sAh + 128*KP;
    __nv_bfloat16* sBh = sAl + 128*KP;
    __nv_bfloat16* sBl = sBh + 64*KP;
    const int t = threadIdx.x, w = t >> 5, lane = t & 31;
    const int wm = w & 3, wn = w >> 2;
    const int row0 = blockIdx.y*128, col0 = blockIdx.x*64;
    const int lrow = (lane & 15), lcol8 = (lane >> 4)*8;
    float acc[2][4][4] = {};

    MAINLOOP_64COL(sAh, sAl, sBh, sBl, Ah, Al, Bh, Bl, row0, col0, acc);

    const int rl4 = lane >> 2, cl2 = (lane & 3)*2;
    const int part = col0 >> 10;
    const int h = (col0 >> 7) & 7;
    const int d0 = col0 & 127;

    if (part < 2) {
        __nv_bfloat16* dH = part ? g_knh : g_qnh;
        __nv_bfloat16* dL = part ? g_knl : g_qnl;
        #pragma unroll
        for (int mt = 0; mt < 2; mt++)
            #pragma unroll
            for (int h2 = 0; h2 < 2; h2++) {
                int gr = row0 + wm*32 + mt*16 + rl4 + h2*8;
                int b = gr >> 11, s = gr & 2047;
                size_t base = ((size_t)(b*HH + h)*SS + s)*DHD + d0;
                #pragma unroll
                for (int nt = 0; nt < 4; nt++) {
                    float v0 = acc[mt][nt][h2*2]   * NORMC;
                    float v1 = acc[mt][nt][h2*2+1] * NORMC;
                    __nv_bfloat16 h0,l0,h1,l1;
                    split_bf16(v0,h0,l0); split_bf16(v1,h1,l1);
                    __nv_bfloat162 hp, lp;
                    hp.x = h0; hp.y = h1; lp.x = l0; lp.y = l1;
                    *(__nv_bfloat162*)(dH + base + wn*32 + nt*8 + cl2) = hp;
                    *(__nv_bfloat162*)(dL + base + wn*32 + nt*8 + cl2) = lp;
                }
            }
    } else {
        #pragma unroll
        for (int mt = 0; mt < 2; mt++)
            #pragma unroll
            for (int h2 = 0; h2 < 2; h2++) {
                int gr = row0 + wm*32 + mt*16 + rl4 + h2*8;
                size_t base = (size_t)gr*INNER + h*DHD + d0;
                #pragma unroll
                for (int nt = 0; nt < 4; nt++) {
                    __nv_bfloat162 hp;
                    hp.x = __float2bfloat16(acc[mt][nt][h2*2]);
                    hp.y = __float2bfloat16(acc[mt][nt][h2*2+1]);
                    *(__nv_bfloat162*)(g_vh + base + wn*32 + nt*8 + cl2) = hp;
                }
            }
    }
}

// FF1: grid (8, 64); gelu epilogue -> fh (single bf16)
__global__ __launch_bounds__(256) void k_ff1(
    const __nv_bfloat16* __restrict__ Ah, const __nv_bfloat16* __restrict__ Al,
    const __nv_bfloat16* __restrict__ Bh, const __nv_bfloat16* __restrict__ Bl,
    const float* __restrict__ bias)
{
    extern __shared__ __align__(16) char dsm[];
    __nv_bfloat16* sAh = (__nv_bfloat16*)dsm;
    __nv_bfloat16* sAl = sAh + 128*KP;
    __nv_bfloat16* sBh = sAl + 128*KP;
    __nv_bfloat16* sBl = sBh + 64*KP;
    const int t = threadIdx.x, w = t >> 5, lane = t & 31;
    const int wm = w & 3, wn = w >> 2;
    const int row0 = blockIdx.y*128, col0 = blockIdx.x*64;
    const int lrow = (lane & 15), lcol8 = (lane >> 4)*8;
    float acc[2][4][4] = {};

    MAINLOOP_64COL(sAh, sAl, sBh, sBl, Ah, Al, Bh, Bl, row0, col0, acc);

    const int rl4 = lane >> 2, cl2 = (lane & 3)*2;
    #pragma unroll
    for (int mt = 0; mt < 2; mt++)
        #pragma unroll
        for (int h2 = 0; h2 < 2; h2++) {
            int gr = row0 + wm*32 + mt*16 + rl4 + h2*8;
            #pragma unroll
            for (int nt = 0; nt < 4; nt++) {
                int gc = col0 + wn*32 + nt*8 + cl2;
                __nv_bfloat162 hp;
                hp.x = __float2bfloat16(gelu(acc[mt][nt][h2*2]   + bias[gc]));
                hp.y = __float2bfloat16(gelu(acc[mt][nt][h2*2+1] + bias[gc+1]));
                *(__nv_bfloat162*)(g_fh + (size_t)gr*FFD + gc) = hp;
            }
        }
}

// ==== HMMA GEMM 64x128, A single bf16 vs W hi/lo, double-buffered (WO/FF2) ====
#define SROW 72
#define BUFSZ (320*SROW)
__global__ __launch_bounds__(256) void k_mma64(
    const __nv_bfloat16* __restrict__ A, int lda,
    const __nv_bfloat16* __restrict__ Bh, const __nv_bfloat16* __restrict__ Bl,
    int Ktot,
    const float* __restrict__ bias,
    float* __restrict__ out)
{
    extern __shared__ __align__(16) __nv_bfloat16 sb[];
    const int t = threadIdx.x, w = t >> 5, lane = t & 31;
    const int wm = w & 1, wn = w >> 1;
    const int row0 = blockIdx.y*64;
    float acc[2][4][4] = {};
    const int lrow = (lane & 15), lcol8 = (lane >> 4)*8;

    {
        #pragma unroll
        for (int i = 0; i < 2; i++) {
            int f = i*256 + t;
            int r = f >> 3, c8 = (f & 7) << 3;
            *(uint4*)(sb + r*SROW + c8) = *(const uint4*)(A + (size_t)(row0+r)*lda + c8);
        }
        #pragma unroll
        for (int i = 0; i < 4; i++) {
            int f = i*256 + t;
            int r = f >> 3, c8 = (f & 7) << 3;
            *(uint4*)(sb + 64*SROW + r*SROW + c8)  = *(const uint4*)(Bh + (size_t)r*Ktot + c8);
            *(uint4*)(sb + 192*SROW + r*SROW + c8) = *(const uint4*)(Bl + (size_t)r*Ktot + c8);
        }
    }
    __syncthreads();
    int buf = 0;

    for (int kc = 64; kc <= Ktot; kc += 64) {
        uint4 ra[2], rb[2][4];
        if (kc < Ktot) {
            #pragma unroll
            for (int i = 0; i < 2; i++) {
                int f = i*256 + t;
                int r = f >> 3, c8 = (f & 7) << 3;
                ra[i] = *(const uint4*)(A + (size_t)(row0+r)*lda + kc + c8);
            }
            #pragma unroll
            for (int i = 0; i < 4; i++) {
                int f = i*256 + t;
                int r = f >> 3, c8 = (f & 7) << 3;
                rb[0][i] = *(const uint4*)(Bh + (size_t)r*Ktot + kc + c8);
                rb[1][i] = *(const uint4*)(Bl + (size_t)r*Ktot + kc + c8);
            }
        }
        const __nv_bfloat16* cb = sb + buf*BUFSZ;
        #pragma unroll
        for (int ks = 0; ks < 4; ks++) {
            int kcol = ks*16 + lcol8;
            uint32_t a[2][4];
            #pragma unroll
            for (int mt = 0; mt < 2; mt++) {
                int arow = wm*32 + mt*16 + lrow;
                ldsm4(a[mt], s2u(cb + arow*SROW + kcol));
            }
            #pragma unroll
            for (int nt2 = 0; nt2 < 2; nt2++) {
                int brow = wn*32 + nt2*16 + lrow;
                uint32_t rh[4], rl[4];
                ldsm4(rh, s2u(cb + 64*SROW + brow*SROW + kcol));
                ldsm4(rl, s2u(cb + 192*SROW + brow*SROW + kcol));
                uint32_t b0h[2] = {rh[0], rh[2]}, b1h[2] = {rh[1], rh[3]};
                uint32_t b0l[2] = {rl[0], rl[2]}, b1l[2] = {rl[1], rl[3]};
                #pragma unroll
                for (int mt = 0; mt < 2; mt++)
                    MMA2x2B(acc[mt][nt2*2], acc[mt][nt2*2+1], a[mt], b0h, b0l, b1h, b1l);
            }
        }
        if (kc < Ktot) {
            __nv_bfloat16* nb = sb + (buf^1)*BUFSZ;
            #pragma unroll
            for (int i = 0; i < 2; i++) {
                int f = i*256 + t;
                int r = f >> 3, c8 = (f & 7) << 3;
                *(uint4*)(nb + r*SROW + c8) = ra[i];
            }
            #pragma unroll
            for (int i = 0; i < 4; i++) {
                int f = i*256 + t;
                int r = f >> 3, c8 = (f & 7) << 3;
                *(uint4*)(nb + 64*SROW + r*SROW + c8)  = rb[0][i];
                *(uint4*)(nb + 192*SROW + r*SROW + c8) = rb[1][i];
            }
            __syncthreads();
            buf ^= 1;
        }
    }

    const int rl4 = lane >> 2, cl2 = (lane & 3)*2;
    #pragma unroll
    for (int mt = 0; mt < 2; mt++)
        #pragma unroll
        for (int h2 = 0; h2 < 2; h2++) {
            int gr = row0 + wm*32 + mt*16 + rl4 + h2*8;
            #pragma unroll
            for (int nt = 0; nt < 4; nt++) {
                int gc = wn*32 + nt*8 + cl2;
                size_t idx = (size_t)gr*DIMC + gc;
                float2 v = *(float2*)(out + idx);
                v.x += acc[mt][nt][h2*2]   + bias[gc];
                v.y += acc[mt][nt][h2*2+1] + bias[gc+1];
                *(float2*)(out + idx) = v;
            }
        }
}

// ---------------- embed ----------------
__global__ void k_embed(const float* __restrict__ x, const float* __restrict__ lw,
                        const float* __restrict__ lb, const float* __restrict__ pe)
{
    int warp = threadIdx.x >> 5, lane = threadIdx.x & 31;
    int r = blockIdx.x*8 + warp;
    float xv = x[r];
    float4 l4 = ((const float4*)lw)[lane];
    float4 b4 = ((const float4*)lb)[lane];
    float4 p4 = ((const float4*)(pe + (size_t)(r % SS)*DIMC))[lane];
    float4 o4 = { xv*l4.x + b4.x + p4.x, xv*l4.y + b4.y + p4.y,
                  xv*l4.z + b4.z + p4.z, xv*l4.w + b4.w + p4.w };
    ((float4*)(g_h + (size_t)r*DIMC))[lane] = o4;
}

// ---------------- layernorm -> bf16 hi/lo ----------------
__global__ void k_ln(const float* __restrict__ in, const float* __restrict__ g,
                     const float* __restrict__ b,
                     __nv_bfloat16* __restrict__ outH, __nv_bfloat16* __restrict__ outL)
{
    int warp = threadIdx.x >> 5, lane = threadIdx.x & 31;
    int r = blockIdx.x*8 + warp;
    float4 v = ((const float4*)(in + (size_t)r*DIMC))[lane];
    float s = v.x + v.y + v.z + v.w;
    #pragma unroll
    for (int o = 16; o > 0; o >>= 1) s += __shfl_xor_sync(0xffffffffu, s, o);
    float mu = s * (1.0f/DIMC);
    float dx = v.x-mu, dy = v.y-mu, dz = v.z-mu, dw = v.w-mu;
    float q = dx*dx + dy*dy + dz*dz + dw*dw;
    #pragma unroll
    for (int o = 16; o > 0; o >>= 1) q += __shfl_xor_sync(0xffffffffu, q, o);
    float inv = rsqrtf(q*(1.0f/DIMC) + 1e-5f);
    float4 gv = ((const float4*)g)[lane];
    float4 bv = ((const float4*)b)[lane];
    float o4[4] = { dx*inv*gv.x + bv.x, dy*inv*gv.y + bv.y,
                    dz*inv*gv.z + bv.z, dw*inv*gv.w + bv.w };
    __nv_bfloat16 hh[4], ll[4];
    #pragma unroll
    for (int j = 0; j < 4; j++) split_bf16(o4[j], hh[j], ll[j]);
    size_t base = (size_t)r*DIMC + lane*4;
    *(uint2*)(outH+base) = *(uint2*)hh;
    *(uint2*)(outL+base) = *(uint2*)ll;
}

// -------- unified weight prep --------
__global__ __launch_bounds__(256) void k_wprep(
    const float* __restrict__ wq, const float* __restrict__ wk,
    const float* __restrict__ wv, const float* __restrict__ wo,
    const float* __restrict__ ff1_w, const float* __restrict__ ff2_w,
    const float* __restrict__ proj)
{
    __shared__ float tile[32][33];
    int bid = blockIdx.x;
    int l = (bid >= 656) ? 1 : 0;
    bid -= l*656;
    size_t wb = (size_t)l*WT_LAYER;
    __nv_bfloat16* wth = g_wth + wb;
    __nv_bfloat16* wtl = g_wtl + wb;

    const float* W; __nv_bfloat16 *oH, *oL; int K, N, tidx;
    if (bid < 384) {
        int which = bid >> 7; tidx = bid & 127;
        W = (which == 0 ? wq : which == 1 ? wk : wv) + (size_t)l*DIMC*INNER;
        oH = wth + (which == 0 ? WT_Q : which == 1 ? WT_K : WT_V);
        oL = wtl + (which == 0 ? WT_Q : which == 1 ? WT_K : WT_V);
        K = DIMC; N = INNER;
    } else if (bid < 512) {
        tidx = bid - 384;
        W = wo + (size_t)l*INNER*DIMC;
        oH = wth + WT_O; oL = wtl + WT_O;
        K = INNER; N = DIMC;
    } else if (bid < 576) {
        tidx = bid - 512;
        W = ff1_w + (size_t)l*DIMC*FFD;
        oH = wth + WT_F1; oL = wtl + WT_F1;
        K = DIMC; N = FFD;
    } else if (bid < 640) {
        tidx = bid - 576;
        W = ff2_w + (size_t)l*FFD*DIMC;
        oH = wth + WT_F2; oL = wtl + WT_F2;
        K = FFD; N = DIMC;
    } else {
        int e4 = (bid - 640)*256 + threadIdx.x;
        float4 v = ((const float4*)(proj + (size_t)l*MF*DHD))[e4];
        __nv_bfloat16 hh[4], ll[4];
        split_bf16(v.x, hh[0], ll[0]); split_bf16(v.y, hh[1], ll[1]);
        split_bf16(v.z, hh[2], ll[2]); split_bf16(v.w, hh[3], ll[3]);
        *(uint2*)(wth + WT_PJ + e4*4) = *(uint2*)hh;
        *(uint2*)(wtl + WT_PJ + e4*4) = *(uint2*)ll;
        return;
    }
    int ntiles = N >> 5;
    int n0 = (tidx % ntiles)*32, k0 = (tidx / ntiles)*32;
    int tx = threadIdx.x & 31, ty = threadIdx.x >> 5;
    #pragma unroll
    for (int i = ty; i < 32; i += 8)
        tile[i][tx] = W[(size_t)(k0+i)*N + n0 + tx];
    __syncthreads();
    #pragma unroll
    for (int i = ty; i < 32; i += 8) {
        float v = tile[tx][i];
        __nv_bfloat16 hh, ll;
        split_bf16(v, hh, ll);
        oH[(size_t)(n0+i)*K + k0 + tx] = hh;
        oL[(size_t)(n0+i)*K + k0 + tx] = ll;
    }
}

// ================= chunk-local attention via HMMA, 512 threads =================
// phase 1 hi/lo; attn stored single bf16; phases 2/3 value-side single
#define CP 136
__global__ __launch_bounds__(512) void k_chunk(
    const __nv_bfloat16* __restrict__ qph, const __nv_bfloat16* __restrict__ qpl)
{
    extern __shared__ __align__(16) __nv_bfloat16 cs[];
    __nv_bfloat16* sQh = cs;                  // Q hi; later masked attn (single)
    __nv_bfloat16* sQl = sQh + 128*CP;        // Q lo (free after phase 1)
    __nv_bfloat16* sKh = sQl + 128*CP;
    __nv_bfloat16* sKl = sKh + 128*CP;
    __nv_bfloat16* sV  = sKl + 128*CP;
    __shared__ float s_den[4][128];
    __shared__ float s_dg[128];

    int blk = blockIdx.x, bh = blk >> 4, c = blk & 15;
    int b = bh >> 3, hh = bh & 7;
    int t = threadIdx.x, w = t >> 5, lane = t & 31;
    int wm = w & 3, wn = w >> 2;
    const int lrow = lane & 15, lcol8 = (lane >> 4)*8;
    const int rl4 = lane >> 2, cl2 = (lane & 3)*2;

    const size_t qbase = ((size_t)bh*SS + c*CHUNK)*MF;
    if (t < 128) {
        float st = g_bmax[bh*16];
        #pragma unroll
        for (int i = 1; i < 16; i++) st = fmaxf(st, g_bmax[bh*16 + i]);
        s_dg[t] = g_diagk[(size_t)bh*SS + c*CHUNK + t] + st;
    }
    for (int i = t; i < 2048; i += 512) {
        int r = i >> 4, c8 = (i & 15) << 3;
        *(uint4*)(sQh + r*CP + c8) = *(const uint4*)(qph + qbase + r*MF + c8);
        *(uint4*)(sQl + r*CP + c8) = *(const uint4*)(qpl + qbase + r*MF + c8);
        size_t vsrc = (size_t)(b*SS + c*CHUNK + r)*INNER + hh*DHD + c8;
        *(uint4*)(sV + r*CP + c8) = *(const uint4*)(g_vh + vsrc);
    }
    __syncthreads();
    for (int f = t; f < 4096; f += 512) {
        int r = f >> 5, c4 = (f & 31) << 2;
        float4 dv = *(const float4*)(g_kp + qbase + (size_t)r*MF + c4);
        float dgv = s_dg[r];
        float o0 = RATIOC*(expf(dv.x - dgv) + 1e-4f);
        float o1 = RATIOC*(expf(dv.y - dgv) + 1e-4f);
        float o2 = RATIOC*(expf(dv.z - dgv) + 1e-4f);
        float o3 = RATIOC*(expf(dv.w - dgv) + 1e-4f);
        __nv_bfloat16 hh4[4], ll4[4];
        split_bf16(o0, hh4[0], ll4[0]); split_bf16(o1, hh4[1], ll4[1]);
        split_bf16(o2, hh4[2], ll4[2]); split_bf16(o3, hh4[3], ll4[3]);
        *(uint2*)(sKh + r*CP + c4) = *(uint2*)hh4;
        *(uint2*)(sKl + r*CP + c4) = *(uint2*)ll4;
    }
    __syncthreads();

    // ---- phase 1: attn = Q@K^T (full hi/lo) ----
    float acc[2][4][4] = {};
    if (wn <= wm) {
        #pragma unroll
        for (int ks = 0; ks < 8; ks++) {
            int kcol = ks*16 + lcol8;
            uint32_t ah[2][4], al[2][4];
            #pragma unroll
            for (int mt = 0; mt < 2; mt++) {
                int arow = wm*32 + mt*16 + lrow;
                ldsm4(ah[mt], s2u(sQh + arow*CP + kcol));
                ldsm4(al[mt], s2u(sQl + arow*CP + kcol));
            }
            #pragma unroll
            for (int nt2 = 0; nt2 < 2; nt2++) {
                int brow = wn*32 + nt2*16 + lrow;
                uint32_t rh[4], rl[4];
                ldsm4(rh, s2u(sKh + brow*CP + kcol));
                ldsm4(rl, s2u(sKl + brow*CP + kcol));
                uint32_t b0h[2] = {rh[0], rh[2]}, b1h[2] = {rh[1], rh[3]};
                uint32_t b0l[2] = {rl[0], rl[2]}, b1l[2] = {rl[1], rl[3]};
                #pragma unroll
                for (int mt = 0; mt < 2; mt++)
                    MMA3x2(acc[mt][nt2*2], acc[mt][nt2*2+1], ah[mt], al[mt], b0h, b0l, b1h, b1l);
            }
        }
    }
    float dp[2][2] = {};
    #pragma unroll
    for (int mt = 0; mt < 2; mt++)
        #pragma unroll
        for (int nt = 0; nt < 4; nt++)
            #pragma unroll
            for (int f = 0; f < 4; f++) {
                int i = wm*32 + mt*16 + rl4 + ((f>>1)<<3);
                int j = wn*32 + nt*8 + cl2 + (f&1);
                if (j > i) acc[mt][nt][f] = 0.f;
                dp[mt][f>>1] += acc[mt][nt][f];
            }
    #pragma unroll
    for (int o = 1; o < 4; o <<= 1)
        #pragma unroll
        for (int mt = 0; mt < 2; mt++)
            #pragma unroll
            for (int h2 = 0; h2 < 2; h2++)
                dp[mt][h2] += __shfl_xor_sync(0xffffffffu, dp[mt][h2], o);
    if ((lane & 3) == 0) {
        #pragma unroll
        for (int mt = 0; mt < 2; mt++)
            #pragma unroll
            for (int h2 = 0; h2 < 2; h2++)
                s_den[wn][wm*32 + mt*16 + rl4 + h2*8] = dp[mt][h2];
    }
    __syncthreads();

    // masked attn -> single bf16 in sQh
    #pragma unroll
    for (int mt = 0; mt < 2; mt++)
        #pragma unroll
        for (int nt = 0; nt < 4; nt++)
            #pragma unroll
            for (int f = 0; f < 4; f++) {
                int i = wm*32 + mt*16 + rl4 + ((f>>1)<<3);
                int j = wn*32 + nt*8 + cl2 + (f&1);
                sQh[i*CP + j] = __float2bfloat16(acc[mt][nt][f]);
            }
    if (t < 128) {
        g_den[(size_t)bh*SS + c*CHUNK + t] = s_den[0][t] + s_den[1][t] + s_den[2][t] + s_den[3][t];
        float kssum = 0.f;
        for (int j = 0; j < 128; j++)
            kssum += __bfloat162float(sKh[j*CP + t]) + __bfloat162float(sKl[j*CP + t]);
        g_ksc[((size_t)bh*NC + c)*MF + t] = kssum;
    }
    __syncthreads();

    // ---- phase 2: num = attn(single) @ V(single) ----
    #pragma unroll
    for (int mt = 0; mt < 2; mt++)
        #pragma unroll
        for (int nt = 0; nt < 4; nt++)
            #pragma unroll
            for (int f = 0; f < 4; f++) acc[mt][nt][f] = 0.f;
    #pragma unroll
    for (int ks = 0; ks < 8; ks++) {
        int kcol = ks*16 + lcol8;
        uint32_t a[2][4];
        #pragma unroll
        for (int mt = 0; mt < 2; mt++) {
            int arow = wm*32 + mt*16 + lrow;
            ldsm4(a[mt], s2u(sQh + arow*CP + kcol));
        }
        #pragma unroll
        for (int nt2 = 0; nt2 < 2; nt2++) {
            int nbase = wn*32 + nt2*16;
            uint32_t dh[4];
            ldsm4t(dh, taddr(sV, CP, ks*16, nbase, lane));
            uint32_t b0[2] = {dh[0], dh[2]}, b1[2] = {dh[1], dh[3]};
            #pragma unroll
            for (int mt = 0; mt < 2; mt++)
                MMA1x2(acc[mt][nt2*2], acc[mt][nt2*2+1], a[mt], b0, b1);
        }
    }
    #pragma unroll
    for (int mt = 0; mt < 2; mt++)
        #pragma unroll
        for (int h2 = 0; h2 < 2; h2++) {
            int i = wm*32 + mt*16 + rl4 + h2*8;
            size_t base = ((size_t)(b*SS + c*CHUNK + i)*HH + hh)*DHD;
            #pragma unroll
            for (int nt = 0; nt < 4; nt++) {
                float2 vv = {acc[mt][nt][h2*2], acc[mt][nt][h2*2+1]};
                *(float2*)(g_o + base + wn*32 + nt*8 + cl2) = vv;
            }
        }

    // ---- phase 3: kv = K^T(hi/lo) @ V(single) ----
    #pragma unroll
    for (int mt = 0; mt < 2; mt++)
        #pragma unroll
        for (int nt = 0; nt < 4; nt++)
            #pragma unroll
            for (int f = 0; f < 4; f++) acc[mt][nt][f] = 0.f;
    #pragma unroll
    for (int ks = 0; ks < 8; ks++) {
        uint32_t ah[2][4], al[2][4];
        #pragma unroll
        for (int mt = 0; mt < 2; mt++) {
            int mbase = wm*32 + mt*16;
            ldsm4t(ah[mt], taddr(sKh, CP, ks*16, mbase, lane));
            ldsm4t(al[mt], taddr(sKl, CP, ks*16, mbase, lane));
        }
        #pragma unroll
        for (int nt2 = 0; nt2 < 2; nt2++) {
            int nbase = wn*32 + nt2*16;
            uint32_t dh[4];
            ldsm4t(dh, taddr(sV, CP, ks*16, nbase, lane));
            uint32_t b0[2] = {dh[0], dh[2]}, b1[2] = {dh[1], dh[3]};
            #pragma unroll
            for (int mt = 0; mt < 2; mt++)
                MMA2x2(acc[mt][nt2*2], acc[mt][nt2*2+1], ah[mt], al[mt], b0, b1);
        }
    }
    {
        size_t kvbase = ((size_t)bh*NC + c)*(MF*DHD);
        #pragma unroll
        for (int mt = 0; mt < 2; mt++)
            #pragma unroll
            for (int h2 = 0; h2 < 2; h2++) {
                int m = wm*32 + mt*16 + rl4 + h2*8;
                #pragma unroll
                for (int nt = 0; nt < 4; nt++) {
                    float2 vv = {acc[mt][nt][h2*2], acc[mt][nt][h2*2+1]};
                    *(float2*)(g_kvc + kvbase + (size_t)m*DHD + wn*32 + nt*8 + cl2) = vv;
                }
            }
    }
}

// ---------------- exclusive prefix over chunks (single bf16 kvp) ----------------
__global__ void k_prefix()
{
    int bh = blockIdx.x, seg = blockIdx.y, t = threadIdx.x;
    for (int e = seg*2048 + t; e < (seg+1)*2048; e += 256) {
        float run = 0.f;
        #pragma unroll
        for (int c = 0; c < NC; c++) {
            size_t idx = ((size_t)bh*NC + c)*(MF*DHD) + e;
            g_kvph[idx] = __float2bfloat16(run);
            run += g_kvc[idx];
        }
    }
    if (seg == 0) {
        for (int e = t; e < MF; e += 256) {
            float run = 0.f;
            #pragma unroll
            for (int c = 0; c < NC; c++) {
                size_t idx = ((size_t)bh*NC + c)*MF + e;
                g_ksp[idx] = run; run += g_ksc[idx];
            }
        }
    }
}

// ========== cross = qp(single) @ kvp(single), + num, normalize -> oh (single) ==========
__global__ __launch_bounds__(512) void k_cross(
    const __nv_bfloat16* __restrict__ qph)
{
    extern __shared__ __align__(16) __nv_bfloat16 cs[];
    __nv_bfloat16* sQ = cs;                   // qp hi only (single)
    __nv_bfloat16* sP = sQ + 128*CP;          // kvp single
    __shared__ float s_ks[128];
    __shared__ float s_dc[128];

    int blk = blockIdx.x, bh = blk >> 4, c = blk & 15;
    int b = bh >> 3, hh = bh & 7;
    int t = threadIdx.x, w = t >> 5, lane = t & 31;
    int wm = w & 3, wn = w >> 2;
    const int lrow = lane & 15, lcol8 = (lane >> 4)*8;
    const int rl4 = lane >> 2, cl2 = (lane & 3)*2;

    const size_t qbase = ((size_t)bh*SS + c*CHUNK)*MF;
    const size_t pbase = ((size_t)bh*NC + c)*(MF*DHD);
    for (int i = t; i < 2048; i += 512) {
        int r = i >> 4, c8 = (i & 15) << 3;
        *(uint4*)(sQ + r*CP + c8) = *(const uint4*)(qph + qbase + r*MF + c8);
        *(uint4*)(sP + r*CP + c8) = *(const uint4*)(g_kvph + pbase + r*DHD + c8);
    }
    if (t < 128) s_ks[t] = g_ksp[((size_t)bh*NC + c)*MF + t];
    __syncthreads();
    if (t < 128) {
        float dc = 0.f;
        for (int m = 0; m < 128; m++)
            dc += __bfloat162float(sQ[t*CP + m])*s_ks[m];
        s_dc[t] = g_den[(size_t)bh*SS + c*CHUNK + t] + dc + 1e-6f;
    }
    __syncthreads();

    float acc[2][4][4] = {};
    #pragma unroll
    for (int ks = 0; ks < 8; ks++) {
        int kcol = ks*16 + lcol8;
        uint32_t a[2][4];
        #pragma unroll
        for (int mt = 0; mt < 2; mt++) {
            int arow = wm*32 + mt*16 + lrow;
            ldsm4(a[mt], s2u(sQ + arow*CP + kcol));
        }
        #pragma unroll
        for (int nt2 = 0; nt2 < 2; nt2++) {
            int nbase = wn*32 + nt2*16;
            uint32_t dh[4];
            ldsm4t(dh, taddr(sP, CP, ks*16, nbase, lane));
            uint32_t b0[2] = {dh[0], dh[2]}, b1[2] = {dh[1], dh[3]};
            #pragma unroll
            for (int mt = 0; mt < 2; mt++)
                MMA1x2(acc[mt][nt2*2], acc[mt][nt2*2+1], a[mt], b0, b1);
        }
    }
    #pragma unroll
    for (int mt = 0; mt < 2; mt++)
        #pragma unroll
        for (int h2 = 0; h2 < 2; h2++) {
            int i = wm*32 + mt*16 + rl4 + h2*8;
            float inv = 1.0f / s_dc[i];
            size_t base = ((size_t)(b*SS + c*CHUNK + i)*HH + hh)*DHD;
            #pragma unroll
            for (int nt = 0; nt < 4; nt++) {
                size_t idx = base + wn*32 + nt*8 + cl2;
                float2 nn = *(float2*)(g_o + idx);
                __nv_bfloat162 hp;
                hp.x = __float2bfloat16((nn.x + acc[mt][nt][h2*2])   * inv);
                hp.y = __float2bfloat16((nn.y + acc[mt][nt][h2*2+1]) * inv);
                *(__nv_bfloat162*)(g_oh + idx) = hp;
            }
        }
}

// ---------------- pooling ----------------
__global__ void k_pool()
{
    int b = blockIdx.x, seg = blockIdx.y, t = threadIdx.x;
    float acc = 0.f;
    for (int s = seg*128; s < (seg+1)*128; s++) acc += g_h[((size_t)b*SS + s)*DIMC + t];
    g_pp[(b*16 + seg)*DIMC + t] = acc;
}

__global__ void k_final(const float* __restrict__ fw, const float* __restrict__ fb,
                        float* __restrict__ out)
{
    __shared__ float pooled[BB*DIMC];
    int t = threadIdx.x;
    for (int b = 0; b < BB; b++) {
        float a = 0.f;
        #pragma unroll
        for (int s = 0; s < 16; s++) a += g_pp[(b*16 + s)*DIMC + t];
        pooled[b*DIMC + t] = a * (1.0f/SS);
    }
    __syncthreads();
    if (t < BB*NCLS) {
        int b = t / NCLS, c = t % NCLS;
        float acc = fb[c];
        for (int d = 0; d < DIMC; d++) acc += pooled[b*DIMC + d]*fw[d*NCLS + c];
        out[t] = acc;
    }
}

// ---------------- host driver ----------------
static void* sym(const void* s) { void* p = nullptr; cudaGetSymbolAddress(&p, s); return p; }

extern "C" void kernel_launch(void* const* d_in, const int* in_sizes, int n_in,
                              void* d_out, int out_size)
{
    const float* x     = (const float*)d_in[0];
    const float* lin_w = (const float*)d_in[1];
    const float* lin_b = (const float*)d_in[2];
    const float* pe    = (const float*)d_in[3];
    const float* proj  = (const float*)d_in[4];
    const float* ln1_g = (const float*)d_in[5];
    const float* ln1_b = (const float*)d_in[6];
    const float* wq    = (const float*)d_in[7];
    const float* wk    = (const float*)d_in[8];
    const float* wv    = (const float*)d_in[9];
    const float* wo    = (const float*)d_in[10];
    const float* wo_b  = (const float*)d_in[11];
    const float* ln2_g = (const float*)d_in[12];
    const float* ln2_b = (const float*)d_in[13];
    const float* ff1_w = (const float*)d_in[14];
    const float* ff1_b = (const float*)d_in[15];
    const float* ff2_w = (const float*)d_in[16];
    const float* ff2_b = (const float*)d_in[17];
    const float* fin_w = (const float*)d_in[18];
    const float* fin_b = (const float*)d_in[19];
    float* out = (float*)d_out;

    float* ph   = (float*)sym(g_h);
    float* pkp  = (float*)sym(g_kp);
    float* pbm  = (float*)sym(g_bmax);

    __nv_bfloat16* yh  = (__nv_bfloat16*)sym(g_yh);
    __nv_bfloat16* yl  = (__nv_bfloat16*)sym(g_yl);
    __nv_bfloat16* wth = (__nv_bfloat16*)sym(g_wth);
    __nv_bfloat16* wtl = (__nv_bfloat16*)sym(g_wtl);
    __nv_bfloat16* qnh = (__nv_bfloat16*)sym(g_qnh);
    __nv_bfloat16* qnl = (__nv_bfloat16*)sym(g_qnl);
    __nv_bfloat16* knh = (__nv_bfloat16*)sym(g_knh);
    __nv_bfloat16* knl = (__nv_bfloat16*)sym(g_knl);
    __nv_bfloat16* qp_h = (__nv_bfloat16*)sym(g_qph);
    __nv_bfloat16* qp_l = (__nv_bfloat16*)sym(g_qpl);
    __nv_bfloat16* oh  = (__nv_bfloat16*)sym(g_oh);
    __nv_bfloat16* fh  = (__nv_bfloat16*)sym(g_fh);

    const int SMEM_MMA   = 4*128*KP*2;           // 139264 (features)
    const int SMEM_QKVFF = QKV_SMEM;             // 104448 (2 CTAs/SM)
    const int SMEM_MMA64 = 2*BUFSZ*2;            // 92160 (2 CTAs/SM)
    const int SMEM_CHUNK = 5*128*CP*2;           // 174080
    const int SMEM_CROSS = 2*128*CP*2;           // 69632 (3 CTAs/SM)
    cudaFuncSetAttribute(k_mmaF, cudaFuncAttributeMaxDynamicSharedMemorySize, SMEM_MMA);
    cudaFuncSetAttribute(k_mmaqkv64, cudaFuncAttributeMaxDynamicSharedMemorySize, SMEM_QKVFF);
    cudaFuncSetAttribute(k_ff1, cudaFuncAttributeMaxDynamicSharedMemorySize, SMEM_QKVFF);
    cudaFuncSetAttribute(k_mma64, cudaFuncAttributeMaxDynamicSharedMemorySize, SMEM_MMA64);
    cudaFuncSetAttribute(k_chunk, cudaFuncAttributeMaxDynamicSharedMemorySize, SMEM_CHUNK);
    cudaFuncSetAttribute(k_cross, cudaFuncAttributeMaxDynamicSharedMemorySize, SMEM_CROSS);

    k_wprep<<<2*656, 256>>>(wq, wk, wv, wo, ff1_w, ff2_w, proj);
    k_embed<<<BSR/8, 256>>>(x, lin_w, lin_b, pe);

    for (int l = 0; l < DEPTH; l++) {
        size_t wb = (size_t)l*WT_LAYER;

        k_ln<<<BSR/8, 256>>>(ph, ln1_g + l*DIMC, ln1_b + l*DIMC, yh, yl);

        k_mmaqkv64<<<dim3(48,64), 256, SMEM_QKVFF>>>(yh, yl, wth+wb+WT_Q, wtl+wb+WT_Q);

        k_mmaF<<<dim3(2,512), 256, SMEM_MMA>>>(knh, knl, qnh, qnl,
                                               wth+wb+WT_PJ, wtl+wb+WT_PJ,
                                               pkp, qp_h, qp_l, pbm);

        k_chunk<<<NBH*NC, 512, SMEM_CHUNK>>>(qp_h, qp_l);
        k_prefix<<<dim3(NBH, 8), 256>>>();
        k_cross<<<NBH*NC, 512, SMEM_CROSS>>>(qp_h);

        k_mma64<<<dim3(1,BSR/64), 256, SMEM_MMA64>>>(oh, INNER, wth+wb+WT_O, wtl+wb+WT_O, INNER,
                                                     wo_b + l*DIMC, ph);

        k_ln<<<BSR/8, 256>>>(ph, ln2_g + l*DIMC, ln2_b + l*DIMC, yh, yl);
        k_ff1<<<dim3(8,64), 256, SMEM_QKVFF>>>(yh, yl, wth+wb+WT_F1, wtl+wb+WT_F1, ff1_b + l*FFD);
        k_mma64<<<dim3(1,BSR/64), 256, SMEM_MMA64>>>(fh, FFD, wth+wb+WT_F2, wtl+wb+WT_F2, FFD,
                                                     ff2_b + l*DIMC, ph);
    }

    k_pool<<<dim3(BB, 16), 128>>>();
    k_final<<<1, 128>>>(fin_w, fin_b, out);
}